// round 12
// baseline (speedup 1.0000x reference)
#include <cuda_runtime.h>
#include <cuda_fp16.h>
#include <math.h>
#include <stdint.h>

// ---------------- constants ----------------
#define B_   8
#define C_   768
#define T_   1024
#define L_   2
#define FF_  3072
#define NPTS 2048
#define TOPK_ 5
#define NCAND 16
#define AROUND_ 5
#define NHEAD_ 8
#define HD_  96

// ---------------- scratch ----------------
__device__ float g_pf    [(size_t)B_*NPTS*C_];
__device__ float g_hid   [(size_t)B_*NPTS*C_];
__device__ float g_mainxT[(size_t)B_*T_*C_];
__device__ float g_coords[2*(size_t)B_*NPTS*2];
__device__ float g_score [2*(size_t)B_*NPTS];
__device__ int   g_top16 [2*B_*NCAND];
__device__ float g_exsc  [2*B_*NCAND];
__device__ int   g_topidx[2*B_*TOPK_];
__device__ float g_tgt   [(size_t)B_*T_*C_];
__device__ float g_tmp   [(size_t)B_*T_*C_];
__device__ float g_qkv   [(size_t)B_*T_*3*C_];
__device__ float g_ffh   [(size_t)B_*T_*FF_];      // phase-A scratch: pf1 + xT1
__device__ float g_memkv [(size_t)B_*10*2*C_];
__device__ float g_q     [(size_t)B_*T_*C_];
// fp16 mirrors / weights
__device__ __align__(256) __half g_pf16  [2*(size_t)B_*NPTS*C_];
__device__ __align__(256) __half g_tgt16 [(size_t)B_*T_*C_];
__device__ __align__(256) __half g_attn16[(size_t)B_*T_*C_];
__device__ __align__(256) __half g_memb16[(size_t)B_*10*C_];
__device__ __align__(256) __half g_ffh16 [(size_t)B_*T_*FF_];
__device__ __align__(256) __half g_wt    [19464192];

// ---------------- fp16 mma (m16n8k16) ----------------
__device__ __forceinline__ void mma16(float* d, const uint32_t* a, const uint32_t* b){
    asm volatile("mma.sync.aligned.m16n8k16.row.col.f32.f16.f16.f32 "
        "{%0,%1,%2,%3},{%4,%5,%6,%7},{%8,%9},{%0,%1,%2,%3};\n"
        : "+f"(d[0]), "+f"(d[1]), "+f"(d[2]), "+f"(d[3])
        : "r"(a[0]), "r"(a[1]), "r"(a[2]), "r"(a[3]), "r"(b[0]), "r"(b[1]));
}

// ---------------- fp16 GEMM (ldmatrix fragments) ----------------
// MODE 0: fp32 C out. MODE 1: relu, half C16 out. MODE 2: score (relu+dot w2, atomicAdd).
#define H_STAGE_B  20480
#define H_SMEM_B   (4*H_STAGE_B)

template<int MODE>
__global__ __launch_bounds__(256, 2)
void h_gemm_kernel(const __half* __restrict__ A, const __half* __restrict__ WT,
                   const float* __restrict__ bias, float* __restrict__ C,
                   __half* __restrict__ C16, const float* __restrict__ w2,
                   float* __restrict__ score,
                   int M, int N, int K, int lda, int ldb, int ldc)
{
    extern __shared__ char smraw[];

    int tid = threadIdx.x, lane = tid & 31, warp = tid >> 5;
    int gid = lane >> 2, tig = lane & 3;
    int wm = warp >> 2, wn = warp & 3;
    int row0 = blockIdx.y * 128, col0 = blockIdx.x * 128;

    float acc[4][4][4];
    #pragma unroll
    for (int i = 0; i < 4; i++)
        #pragma unroll
        for (int j = 0; j < 4; j++)
            #pragma unroll
            for (int r = 0; r < 4; r++) acc[i][j][r] = 0.f;

    int r0l = tid >> 2,         seg0 = tid & 3;
    int r1l = (tid + 256) >> 2, seg1 = tid & 3;
    int ss0 = (row0 + r0l < M) ? 16 : 0;
    int ss1 = (row0 + r1l < M) ? 16 : 0;
    int car0 = ss0 ? row0 + r0l : 0;
    int car1 = ss1 ? row0 + r1l : 0;

    // ldmatrix lane geometry (same for A and B: [row][k] layout, 80B row stride)
    int lm_row = (lane & 7) + ((lane >> 3) & 1)*8;
    int lm_kh  = (lane >> 4)*8;                    // half offset within k16

    auto issue_stage = [&](int stage, int k0){
        char* Ab = smraw + stage*H_STAGE_B;
        char* Bb = Ab + 10240;
        {
            uint32_t d = (uint32_t)__cvta_generic_to_shared(Ab + r0l*80 + seg0*16);
            const __half* s = A + (size_t)car0*lda + k0 + seg0*8;
            asm volatile("cp.async.cg.shared.global [%0], [%1], 16, %2;\n" :: "r"(d), "l"(s), "r"(ss0));
        }
        {
            uint32_t d = (uint32_t)__cvta_generic_to_shared(Ab + r1l*80 + seg1*16);
            const __half* s = A + (size_t)car1*lda + k0 + seg1*8;
            asm volatile("cp.async.cg.shared.global [%0], [%1], 16, %2;\n" :: "r"(d), "l"(s), "r"(ss1));
        }
        {
            uint32_t d = (uint32_t)__cvta_generic_to_shared(Bb + r0l*80 + seg0*16);
            const __half* s = WT + (size_t)(col0 + r0l)*ldb + k0 + seg0*8;
            asm volatile("cp.async.cg.shared.global [%0], [%1], 16;\n" :: "r"(d), "l"(s));
        }
        {
            uint32_t d = (uint32_t)__cvta_generic_to_shared(Bb + r1l*80 + seg1*16);
            const __half* s = WT + (size_t)(col0 + r1l)*ldb + k0 + seg1*8;
            asm volatile("cp.async.cg.shared.global [%0], [%1], 16;\n" :: "r"(d), "l"(s));
        }
        asm volatile("cp.async.commit_group;\n" ::: "memory");
    };

    auto compute = [&](int stage){
        uint32_t baseA = (uint32_t)__cvta_generic_to_shared(smraw + stage*H_STAGE_B);
        uint32_t baseB = baseA + 10240;
        #pragma unroll
        for (int kk = 0; kk < 2; kk++){
            int kh = kk*16 + lm_kh;
            uint32_t af[4][4], bf[4][2];
            #pragma unroll
            for (int ma = 0; ma < 4; ma++){
                uint32_t addr = baseA + (uint32_t)(wm*64 + ma*16 + lm_row)*80 + kh*2;
                asm volatile("ldmatrix.sync.aligned.m8n8.x4.shared.b16 {%0,%1,%2,%3}, [%4];"
                    : "=r"(af[ma][0]), "=r"(af[ma][1]), "=r"(af[ma][2]), "=r"(af[ma][3])
                    : "r"(addr));
            }
            #pragma unroll
            for (int np = 0; np < 2; np++){
                uint32_t addr = baseB + (uint32_t)(wn*32 + np*16 + lm_row)*80 + kh*2;
                uint32_t q0, q1, q2, q3;
                asm volatile("ldmatrix.sync.aligned.m8n8.x4.shared.b16 {%0,%1,%2,%3}, [%4];"
                    : "=r"(q0), "=r"(q1), "=r"(q2), "=r"(q3) : "r"(addr));
                bf[np*2+0][0] = q0; bf[np*2+1][0] = q1;
                bf[np*2+0][1] = q2; bf[np*2+1][1] = q3;
            }
            #pragma unroll
            for (int ma = 0; ma < 4; ma++)
                #pragma unroll
                for (int na = 0; na < 4; na++)
                    mma16(acc[ma][na], af[ma], bf[na]);
        }
    };

    int nc = K / 32;
    #pragma unroll
    for (int s = 0; s < 3; s++) issue_stage(s, s*32);
    for (int it = 0; it < nc; it++){
        asm volatile("cp.async.wait_group 2;\n" ::: "memory");
        __syncthreads();
        int nxt = it + 3;
        if (nxt < nc) issue_stage(nxt & 3, nxt*32);
        else asm volatile("cp.async.commit_group;\n" ::: "memory");
        compute(it & 3);
    }

    #pragma unroll
    for (int ma = 0; ma < 4; ma++){
        int r0 = row0 + wm*64 + ma*16 + gid;
        float s0 = 0.f, s1 = 0.f;
        #pragma unroll
        for (int na = 0; na < 4; na++){
            int c = col0 + wn*32 + na*8 + 2*tig;
            float b0 = bias ? bias[c] : 0.f;
            float b1 = bias ? bias[c+1] : 0.f;
            float x0 = acc[ma][na][0] + b0;
            float x1 = acc[ma][na][1] + b1;
            float x2 = acc[ma][na][2] + b0;
            float x3 = acc[ma][na][3] + b1;
            if (MODE >= 1){
                x0 = fmaxf(x0, 0.f); x1 = fmaxf(x1, 0.f);
                x2 = fmaxf(x2, 0.f); x3 = fmaxf(x3, 0.f);
            }
            if (MODE == 2){
                float w0 = w2[c], w1 = w2[c+1];
                s0 += x0*w0 + x1*w1;
                s1 += x2*w0 + x3*w1;
            } else if (MODE == 1){
                if (r0 < M)     *(__half2*)&C16[(size_t)r0*ldc + c]     = __floats2half2_rn(x0, x1);
                if (r0 + 8 < M) *(__half2*)&C16[(size_t)(r0+8)*ldc + c] = __floats2half2_rn(x2, x3);
            } else {
                if (r0 < M){ float2 o = make_float2(x0, x1); *(float2*)&C[(size_t)r0*ldc + c] = o; }
                if (r0 + 8 < M){ float2 o = make_float2(x2, x3); *(float2*)&C[(size_t)(r0+8)*ldc + c] = o; }
            }
        }
        if (MODE == 2){
            s0 += __shfl_xor_sync(0xffffffffu, s0, 1);
            s0 += __shfl_xor_sync(0xffffffffu, s0, 2);
            s1 += __shfl_xor_sync(0xffffffffu, s1, 1);
            s1 += __shfl_xor_sync(0xffffffffu, s1, 2);
            if (tig == 0){
                if (r0 < M)     atomicAdd(&score[r0], s0);
                if (r0 + 8 < M) atomicAdd(&score[r0 + 8], s1);
            }
        }
    }
}

template<int MODE>
static void h_gemm(const __half* A, const __half* WT, const float* bias, float* C,
                   __half* C16, const float* w2, float* score,
                   int M, int N, int K, int lda, int ldb, int ldc, cudaStream_t st){
    cudaFuncSetAttribute(h_gemm_kernel<MODE>, cudaFuncAttributeMaxDynamicSharedMemorySize, H_SMEM_B);
    dim3 grid(N/128, (M + 127)/128);
    h_gemm_kernel<MODE><<<grid, 256, H_SMEM_B, st>>>(A, WT, bias, C, C16, w2, score, M, N, K, lda, ldb, ldc);
}

// ---------------- weight transpose+convert ----------------
__global__ void transpose_w_kernel(const float* __restrict__ W, __half* __restrict__ WT,
                                   int K, int N){
    __shared__ float tile[32][33];
    int n0 = blockIdx.x*32, k0 = blockIdx.y*32;
    for (int i = threadIdx.y; i < 32; i += 8)
        tile[i][threadIdx.x] = W[(size_t)(k0 + i)*N + n0 + threadIdx.x];
    __syncthreads();
    for (int i = threadIdx.y; i < 32; i += 8)
        WT[(size_t)(n0 + i)*K + k0 + threadIdx.x] = __float2half_rn(tile[threadIdx.x][i]);
}
static void transpose_w(const float* W, __half* WT, int K, int N, cudaStream_t st){
    dim3 g(N/32, K/32); dim3 bl(32, 8);
    transpose_w_kernel<<<g, bl, 0, st>>>(W, WT, K, N);
}

// ---------------- tf32 mma kept for flash attention ----------------
__device__ __forceinline__ void mma8(float* d, const float* a, const float* b){
    asm volatile("mma.sync.aligned.m16n8k8.row.col.f32.tf32.tf32.f32 "
        "{%0,%1,%2,%3},{%4,%5,%6,%7},{%8,%9},{%0,%1,%2,%3};\n"
        : "+f"(d[0]), "+f"(d[1]), "+f"(d[2]), "+f"(d[3])
        : "r"(__float_as_uint(a[0])), "r"(__float_as_uint(a[1])),
          "r"(__float_as_uint(a[2])), "r"(__float_as_uint(a[3])),
          "r"(__float_as_uint(b[0])), "r"(__float_as_uint(b[1])));
}

// ---------------- flash attention (unchanged; half out) ----------------
#define FA_PADK 136
#define FA_PADV 104
#define FA_LOG2E 1.4426950408889634f

__global__ __launch_bounds__(256, 1)
void flash_attn_kernel(const float* __restrict__ qkv, __half* __restrict__ out16){
    extern __shared__ float sm[];
    float* Ks = sm;
    float* Vs = Ks + 96*FA_PADK;
    float* Ps = Vs + 128*FA_PADV;

    int qt = blockIdx.x, bh = blockIdx.y, b = bh >> 3, h = bh & 7;
    int tid = threadIdx.x, lane = tid & 31, warp = tid >> 5;
    int gid = lane >> 2, tig = lane & 3;
    int m0 = warp * 16;
    int q0 = qt * 128;
    const float iscale = 0.10206207261596577f;

    float qf[12][4];
    {
        const float* Qa = qkv + (size_t)(b*T_ + q0 + m0 + gid)*(3*C_) + h*HD_;
        const float* Qb = Qa + 8*(3*C_);
        #pragma unroll
        for (int kk = 0; kk < 12; kk++){
            qf[kk][0] = Qa[kk*8 + tig]     * iscale;
            qf[kk][1] = Qb[kk*8 + tig]     * iscale;
            qf[kk][2] = Qa[kk*8 + tig + 4] * iscale;
            qf[kk][3] = Qb[kk*8 + tig + 4] * iscale;
        }
    }

    float oacc[12][4];
    #pragma unroll
    for (int i = 0; i < 12; i++)
        #pragma unroll
        for (int j = 0; j < 4; j++) oacc[i][j] = 0.f;
    float mrow0 = -1e30f, mrow1 = -1e30f, lrow0 = 0.f, lrow1 = 0.f;

    for (int kt = 0; kt < 8; kt++){
        __syncthreads();
        {
            const float* Kb = qkv + (size_t)(b*T_ + kt*128)*(3*C_) + C_ + h*HD_;
            const float* Vb = Kb + C_;
            for (int idx = tid; idx < 128*24; idx += 256){
                int r = idx / 24, c4 = idx % 24;
                float4 kv4 = *(const float4*)(Kb + (size_t)r*(3*C_) + c4*4);
                Ks[(c4*4+0)*FA_PADK + r] = kv4.x;
                Ks[(c4*4+1)*FA_PADK + r] = kv4.y;
                Ks[(c4*4+2)*FA_PADK + r] = kv4.z;
                Ks[(c4*4+3)*FA_PADK + r] = kv4.w;
                float4 vv4 = *(const float4*)(Vb + (size_t)r*(3*C_) + c4*4);
                *(float4*)&Vs[r*FA_PADV + c4*4] = vv4;
            }
        }
        __syncthreads();

        float sacc[16][4];
        #pragma unroll
        for (int nf = 0; nf < 16; nf++)
            #pragma unroll
            for (int j = 0; j < 4; j++) sacc[nf][j] = 0.f;
        #pragma unroll
        for (int kk = 0; kk < 12; kk++){
            int k1 = (kk*8 + tig)*FA_PADK, k2 = (kk*8 + tig + 4)*FA_PADK;
            #pragma unroll
            for (int nf = 0; nf < 16; nf++){
                float bfr[2] = { Ks[k1 + nf*8 + gid], Ks[k2 + nf*8 + gid] };
                mma8(sacc[nf], qf[kk], bfr);
            }
        }

        float rm0 = -1e30f, rm1 = -1e30f;
        #pragma unroll
        for (int nf = 0; nf < 16; nf++){
            rm0 = fmaxf(rm0, fmaxf(sacc[nf][0], sacc[nf][1]));
            rm1 = fmaxf(rm1, fmaxf(sacc[nf][2], sacc[nf][3]));
        }
        rm0 = fmaxf(rm0, __shfl_xor_sync(0xffffffffu, rm0, 1));
        rm0 = fmaxf(rm0, __shfl_xor_sync(0xffffffffu, rm0, 2));
        rm1 = fmaxf(rm1, __shfl_xor_sync(0xffffffffu, rm1, 1));
        rm1 = fmaxf(rm1, __shfl_xor_sync(0xffffffffu, rm1, 2));
        float mn0 = fmaxf(mrow0, rm0), mn1 = fmaxf(mrow1, rm1);
        float al0 = exp2f((mrow0 - mn0)*FA_LOG2E);
        float al1 = exp2f((mrow1 - mn1)*FA_LOG2E);
        mrow0 = mn0; mrow1 = mn1;
        float rs0 = 0.f, rs1 = 0.f;
        #pragma unroll
        for (int nf = 0; nf < 16; nf++){
            float p0 = exp2f((sacc[nf][0] - mn0)*FA_LOG2E);
            float p1 = exp2f((sacc[nf][1] - mn0)*FA_LOG2E);
            float p2 = exp2f((sacc[nf][2] - mn1)*FA_LOG2E);
            float p3 = exp2f((sacc[nf][3] - mn1)*FA_LOG2E);
            sacc[nf][0] = p0; sacc[nf][1] = p1; sacc[nf][2] = p2; sacc[nf][3] = p3;
            rs0 += p0 + p1; rs1 += p2 + p3;
        }
        rs0 += __shfl_xor_sync(0xffffffffu, rs0, 1);
        rs0 += __shfl_xor_sync(0xffffffffu, rs0, 2);
        rs1 += __shfl_xor_sync(0xffffffffu, rs1, 1);
        rs1 += __shfl_xor_sync(0xffffffffu, rs1, 2);
        lrow0 = lrow0*al0 + rs0;
        lrow1 = lrow1*al1 + rs1;
        #pragma unroll
        for (int nf = 0; nf < 12; nf++){
            oacc[nf][0] *= al0; oacc[nf][1] *= al0;
            oacc[nf][2] *= al1; oacc[nf][3] *= al1;
        }

        #pragma unroll
        for (int nf = 0; nf < 16; nf++){
            int c = nf*8 + 2*tig;
            Ps[(size_t)c*FA_PADK     + m0 + gid]     = sacc[nf][0];
            Ps[(size_t)(c+1)*FA_PADK + m0 + gid]     = sacc[nf][1];
            Ps[(size_t)c*FA_PADK     + m0 + gid + 8] = sacc[nf][2];
            Ps[(size_t)(c+1)*FA_PADK + m0 + gid + 8] = sacc[nf][3];
        }
        __syncwarp();

        #pragma unroll
        for (int kk = 0; kk < 16; kk++){
            int k1 = (kk*8 + tig)*FA_PADK, k2 = (kk*8 + tig + 4)*FA_PADK;
            float pa[4] = { Ps[k1 + m0 + gid], Ps[k1 + m0 + gid + 8],
                            Ps[k2 + m0 + gid], Ps[k2 + m0 + gid + 8] };
            int v1 = (kk*8 + tig)*FA_PADV, v2 = (kk*8 + tig + 4)*FA_PADV;
            #pragma unroll
            for (int nf = 0; nf < 12; nf++){
                float vb2[2] = { Vs[v1 + nf*8 + gid], Vs[v2 + nf*8 + gid] };
                mma8(oacc[nf], pa, vb2);
            }
        }
    }

    float inv0 = 1.f / lrow0, inv1 = 1.f / lrow1;
    size_t r0 = (size_t)(b*T_ + q0 + m0 + gid);
    #pragma unroll
    for (int nf = 0; nf < 12; nf++){
        int col = h*HD_ + nf*8 + 2*tig;
        *(__half2*)&out16[r0*C_ + col]       = __floats2half2_rn(oacc[nf][0]*inv0, oacc[nf][1]*inv0);
        *(__half2*)&out16[(r0 + 8)*C_ + col] = __floats2half2_rn(oacc[nf][2]*inv1, oacc[nf][3]*inv1);
    }
}

// ---------------- transpose x [B,C,T] -> xT [B,T,C] ----------------
__global__ void transpose_in_kernel(const float* __restrict__ x, float* __restrict__ xT){
    __shared__ float tile[32][33];
    int c0 = blockIdx.x*32, t0 = blockIdx.y*32, b = blockIdx.z;
    for (int i = threadIdx.y; i < 32; i += 8)
        tile[i][threadIdx.x] = x[((size_t)b*C_ + c0 + i)*T_ + t0 + threadIdx.x];
    __syncthreads();
    for (int i = threadIdx.y; i < 32; i += 8)
        xT[((size_t)b*T_ + t0 + i)*C_ + c0 + threadIdx.x] = tile[threadIdx.x][i];
}

// ---------------- blockwise sampling (fp32 + fp16 out) ----------------
__global__ void sample_kernel(const float* __restrict__ xT, const float* __restrict__ brand,
                              float* __restrict__ pf, __half* __restrict__ pf16,
                              float* __restrict__ coords){
    int p0 = blockIdx.x * 16;
    __shared__ int   sidx[16][4];
    __shared__ float swt [16][4];
    int tid = threadIdx.x;
    if (tid < 16){
        int bn = p0 + tid;
        int b  = bn >> 11;
        int n  = bn & 2047;
        int k  = n & 1;
        int pw = (n >> 1) & 31;
        int ph = n >> 6;
        const float bs = 0.0625f;
        const float* br = brand + ((((size_t)b*32 + ph)*32 + pw)*2 + k)*2;
        float gx = br[0]*bs + (-1.0f + ph*bs);
        float gy = br[1]*bs + (-1.0f + pw*bs);
        coords[(size_t)bn*2]     = gx;
        coords[(size_t)bn*2 + 1] = gy;
        float ix = ((gx + 1.0f)*32.0f - 1.0f)*0.5f;
        float iy = ((gy + 1.0f)*32.0f - 1.0f)*0.5f;
        float x0f = floorf(ix), y0f = floorf(iy);
        int x0 = (int)x0f, y0 = (int)y0f;
        float wx1 = ix - x0f, wy1 = iy - y0f;
        float wxs[2] = {1.f - wx1, wx1};
        float wys[2] = {1.f - wy1, wy1};
        #pragma unroll
        for (int j = 0; j < 4; j++){
            int xi = x0 + (j & 1), yi = y0 + (j >> 1);
            bool v = (xi >= 0) & (xi < 32) & (yi >= 0) & (yi < 32);
            sidx[tid][j] = v ? (yi*32 + xi) : 0;
            swt [tid][j] = v ? (wxs[j & 1]*wys[j >> 1]) : 0.f;
        }
    }
    __syncthreads();
    int b = (p0 >> 11);
    const float* base = xT + (size_t)b*T_*C_;
    for (int pt = 0; pt < 16; pt++){
        const float* r0 = base + (size_t)sidx[pt][0]*C_;
        const float* r1 = base + (size_t)sidx[pt][1]*C_;
        const float* r2 = base + (size_t)sidx[pt][2]*C_;
        const float* r3 = base + (size_t)sidx[pt][3]*C_;
        float w0 = swt[pt][0], w1 = swt[pt][1], w2 = swt[pt][2], w3 = swt[pt][3];
        float* dst = pf + (size_t)(p0 + pt)*C_;
        __half* dst16 = pf16 + (size_t)(p0 + pt)*C_;
        for (int c = tid; c < C_; c += 256){
            float v = r0[c]*w0 + r1[c]*w1 + r2[c]*w2 + r3[c]*w3;
            dst[c] = v;
            dst16[c] = __float2half_rn(v);
        }
    }
}

// ---------------- zero score ----------------
__global__ void zero_score_kernel(float* __restrict__ score){
    int i = blockIdx.x*256 + threadIdx.x;
    if (i < B_*NPTS) score[i] = 0.f;
}

// ---------------- top-K ----------------
__global__ void topk_kernel(const float* __restrict__ score, int* __restrict__ topidx, int K){
    int b = blockIdx.x;
    __shared__ float sv[2048];
    __shared__ float rv[256];
    __shared__ int   ri[256];
    for (int j = threadIdx.x; j < 2048; j += 256) sv[j] = score[(size_t)b*2048 + j];
    __syncthreads();
    for (int t = 0; t < K; t++){
        float bv = -1e30f; int bi = 0x7fffffff;
        for (int j = threadIdx.x; j < 2048; j += 256){
            float v = sv[j];
            if (v > bv){ bv = v; bi = j; }
        }
        rv[threadIdx.x] = bv; ri[threadIdx.x] = bi;
        __syncthreads();
        for (int s = 128; s; s >>= 1){
            if (threadIdx.x < s){
                float v2 = rv[threadIdx.x + s]; int i2 = ri[threadIdx.x + s];
                if (v2 > rv[threadIdx.x] || (v2 == rv[threadIdx.x] && i2 < ri[threadIdx.x])){
                    rv[threadIdx.x] = v2; ri[threadIdx.x] = i2;
                }
            }
            __syncthreads();
        }
        if (threadIdx.x == 0){
            topidx[b*K + t] = ri[0];
            sv[ri[0]] = -1e30f;
        }
        __syncthreads();
    }
}

// ---------------- exact fp32 rescore ----------------
__global__ __launch_bounds__(256)
void rescore_kernel(const float* __restrict__ pf, const float* __restrict__ W1,
                    const float* __restrict__ b1, const float* __restrict__ w2,
                    const int* __restrict__ cand, float* __restrict__ exsc){
    int b = blockIdx.x >> 4, c = blockIdx.x & 15;
    int idx = cand[b*NCAND + c];
    __shared__ float spf[C_];
    int tid = threadIdx.x;
    for (int i = tid; i < C_; i += 256) spf[i] = pf[((size_t)b*NPTS + idx)*C_ + i];
    __syncthreads();
    float a0 = b1[tid], a1 = b1[tid+256], a2 = b1[tid+512];
    for (int k = 0; k < C_; k++){
        float v = spf[k];
        const float* w = W1 + (size_t)k*C_;
        a0 += v * w[tid];
        a1 += v * w[tid+256];
        a2 += v * w[tid+512];
    }
    float p = fmaxf(a0,0.f)*w2[tid] + fmaxf(a1,0.f)*w2[tid+256] + fmaxf(a2,0.f)*w2[tid+512];
    #pragma unroll
    for (int o = 16; o; o >>= 1) p += __shfl_down_sync(0xffffffffu, p, o);
    __shared__ float red[8];
    if ((tid & 31) == 0) red[tid >> 5] = p;
    __syncthreads();
    if (tid == 0){
        float s = 0.f;
        #pragma unroll
        for (int i = 0; i < 8; i++) s += red[i];
        exsc[b*NCAND + c] = s;
    }
}

// ---------------- final exact top-5 ----------------
__global__ void final_top5_kernel(const float* __restrict__ exsc, const int* __restrict__ cand,
                                  int* __restrict__ topidx){
    int b = blockIdx.x;
    if (threadIdx.x == 0){
        float s[NCAND]; int id[NCAND];
        for (int i = 0; i < NCAND; i++){ s[i] = exsc[b*NCAND + i]; id[i] = cand[b*NCAND + i]; }
        for (int t = 0; t < TOPK_; t++){
            int bi = 0;
            float bv = -1e30f; int bid = 0x7fffffff;
            for (int i = 0; i < NCAND; i++){
                if (s[i] > bv || (s[i] == bv && id[i] < bid)){ bv = s[i]; bid = id[i]; bi = i; }
            }
            topidx[b*TOPK_ + t] = id[bi];
            s[bi] = -1e30f;
        }
    }
}

// ---------------- soft_align (coalesced via mainxT; writes fp16 mem rows) ----------------
__global__ void soft_align_kernel(const float* __restrict__ mainxT, const float* __restrict__ pe,
                                  const float* __restrict__ arand, const float* __restrict__ mqrow,
                                  const float* __restrict__ pf, const float* __restrict__ coords,
                                  const int* __restrict__ topidx, __half* __restrict__ memo16, int rowBase){
    int b  = blockIdx.x / TOPK_;
    int nk = blockIdx.x % TOPK_;
    int idx = topidx[b*TOPK_ + nk];
    float px = coords[((size_t)b*NPTS + idx)*2 + 0];
    float py = coords[((size_t)b*NPTS + idx)*2 + 1];
    __shared__ float semb[AROUND_*C_];
    __shared__ float red[256];
    __shared__ float res[11];
    __shared__ float sw[AROUND_];

    int   aidx[AROUND_][4];
    float awt [AROUND_][4];
    #pragma unroll
    for (int a = 0; a < AROUND_; a++){
        const float* ar = arand + (((size_t)b*AROUND_ + a)*TOPK_ + nk)*2;
        float g0 = px + (ar[0]*2.f - 0.5f)*0.2f;
        float g1 = py + (ar[1]*2.f - 0.5f)*0.2f;
        g0 = fminf(fmaxf(g0, -1.f), 1.f);
        g1 = fminf(fmaxf(g1, -1.f), 1.f);
        float ix = ((g0 + 1.f)*32.f - 1.f)*0.5f;
        float iy = ((g1 + 1.f)*32.f - 1.f)*0.5f;
        float x0f = floorf(ix), y0f = floorf(iy);
        int x0 = (int)x0f, y0 = (int)y0f;
        float wx1 = ix - x0f, wy1 = iy - y0f;
        float wxs[2] = {1.f - wx1, wx1};
        float wys[2] = {1.f - wy1, wy1};
        #pragma unroll
        for (int j = 0; j < 4; j++){
            int xi = x0 + (j & 1), yi = y0 + (j >> 1);
            bool v = (xi >= 0) & (xi < 32) & (yi >= 0) & (yi < 32);
            aidx[a][j] = v ? (yi*32 + xi) : 0;
            awt [a][j] = v ? (wxs[j & 1]*wys[j >> 1]) : 0.f;
        }
    }
    const float* xbase = mainxT + (size_t)b*T_*C_;
    const float* pfrow = pf + ((size_t)b*NPTS + idx)*C_;
    float rep2 = 0.f, num[AROUND_], af2[AROUND_];
    #pragma unroll
    for (int a = 0; a < AROUND_; a++){ num[a] = 0.f; af2[a] = 0.f; }
    for (int c = threadIdx.x; c < C_; c += 256){
        float r = pfrow[c];
        rep2 += r*r;
        #pragma unroll
        for (int a = 0; a < AROUND_; a++){
            float af = awt[a][0]*xbase[(size_t)aidx[a][0]*C_ + c]
                     + awt[a][1]*xbase[(size_t)aidx[a][1]*C_ + c]
                     + awt[a][2]*xbase[(size_t)aidx[a][2]*C_ + c]
                     + awt[a][3]*xbase[(size_t)aidx[a][3]*C_ + c];
            num[a] += r*af;
            af2[a] += af*af;
            semb[a*C_ + c] = awt[a][0]*pe[(size_t)aidx[a][0]*C_ + c]
                           + awt[a][1]*pe[(size_t)aidx[a][1]*C_ + c]
                           + awt[a][2]*pe[(size_t)aidx[a][2]*C_ + c]
                           + awt[a][3]*pe[(size_t)aidx[a][3]*C_ + c];
        }
    }
    float vals[11];
    vals[0] = rep2;
    #pragma unroll
    for (int a = 0; a < AROUND_; a++){ vals[1+a] = num[a]; vals[6+a] = af2[a]; }
    for (int v = 0; v < 11; v++){
        red[threadIdx.x] = vals[v];
        __syncthreads();
        for (int s = 128; s; s >>= 1){
            if (threadIdx.x < s) red[threadIdx.x] += red[threadIdx.x + s];
            __syncthreads();
        }
        if (threadIdx.x == 0) res[v] = red[0];
        __syncthreads();
    }
    if (threadIdx.x == 0){
        float rn = fmaxf(sqrtf(res[0]), 1e-8f);
        float s[AROUND_]; float mx = -1e30f;
        for (int a = 0; a < AROUND_; a++){
            s[a] = res[1+a] / (rn * fmaxf(sqrtf(res[6+a]), 1e-8f));
            mx = fmaxf(mx, s[a]);
        }
        float ss = 0.f;
        for (int a = 0; a < AROUND_; a++){ s[a] = expf(s[a] - mx); ss += s[a]; }
        for (int a = 0; a < AROUND_; a++) sw[a] = s[a] / ss;
    }
    __syncthreads();
    float w0 = sw[0], w1 = sw[1], w2 = sw[2], w3 = sw[3], w4 = sw[4];
    for (int c = threadIdx.x; c < C_; c += 256){
        float o = pfrow[c] + mqrow[c];
        o += semb[0*C_ + c]*w0 + semb[1*C_ + c]*w1 + semb[2*C_ + c]*w2
           + semb[3*C_ + c]*w3 + semb[4*C_ + c]*w4;
        memo16[((size_t)b*10 + rowBase + nk)*C_ + c] = __float2half_rn(o);
    }
}

// ---------------- tgt init (from mainxT; fp32 + fp16) ----------------
__global__ void tgt_init_kernel(const float* __restrict__ mainxT, const float* __restrict__ mq,
                                const float* __restrict__ pe, float* __restrict__ tgt,
                                __half* __restrict__ tgt16){
    size_t i = (size_t)blockIdx.x*256 + threadIdx.x;   // over B*T*C
    int c = i % C_;
    size_t tc = i % ((size_t)T_*C_);
    float v = mainxT[i] + mq[c] + pe[tc];
    tgt[i] = v;
    tgt16[i] = __float2half_rn(v);
}

// ---------------- cross-attention (10 keys; half out) ----------------
__global__ void ca_attn_kernel(const float* __restrict__ q, const float* __restrict__ kv,
                               __half* __restrict__ out16){
    int bh = blockIdx.y, b = bh >> 3, h = bh & 7;
    int i = blockIdx.x*256 + threadIdx.x;
    __shared__ float Ks[10][96];
    __shared__ float Vsm[10][96];
    for (int idx = threadIdx.x; idx < 960; idx += 256){
        int j = idx / 96, d = idx % 96;
        Ks[j][d]  = kv[((size_t)b*10 + j)*(2*C_) + h*HD_ + d];
        Vsm[j][d] = kv[((size_t)b*10 + j)*(2*C_) + C_ + h*HD_ + d];
    }
    __syncthreads();
    const float* qr = q + ((size_t)b*T_ + i)*C_ + h*HD_;
    float s[10];
    #pragma unroll
    for (int j = 0; j < 10; j++) s[j] = 0.f;
    for (int d = 0; d < HD_; d++){
        float qd = qr[d];
        #pragma unroll
        for (int j = 0; j < 10; j++) s[j] += qd * Ks[j][d];
    }
    const float scale = 0.10206207261596577f;
    float mx = -1e30f;
    #pragma unroll
    for (int j = 0; j < 10; j++){ s[j] *= scale; mx = fmaxf(mx, s[j]); }
    float sum = 0.f;
    #pragma unroll
    for (int j = 0; j < 10; j++){ s[j] = expf(s[j] - mx); sum += s[j]; }
    float inv = 1.f / sum;
    #pragma unroll
    for (int j = 0; j < 10; j++) s[j] *= inv;
    __half* orow = out16 + ((size_t)b*T_ + i)*C_ + h*HD_;
    for (int d = 0; d < HD_; d++){
        float o = 0.f;
        #pragma unroll
        for (int j = 0; j < 10; j++) o += s[j] * Vsm[j][d];
        orow[d] = __float2half_rn(o);
    }
}

// ---------------- residual add + layernorm (fp32 + fp16 out) ----------------
__global__ void add_ln_kernel(float* __restrict__ tgt, __half* __restrict__ tgt16,
                              const float* __restrict__ resid,
                              const float* __restrict__ w, const float* __restrict__ bb){
    int row = blockIdx.x, t = threadIdx.x;
    float* p = tgt + (size_t)row*C_;
    __half* p16 = tgt16 + (size_t)row*C_;
    const float* r = resid + (size_t)row*C_;
    float v[3];
    float sum = 0.f;
    #pragma unroll
    for (int i = 0; i < 3; i++){ v[i] = p[t + i*256] + r[t + i*256]; sum += v[i]; }
    __shared__ float red[256];
    red[t] = sum; __syncthreads();
    for (int s = 128; s; s >>= 1){ if (t < s) red[t] += red[t + s]; __syncthreads(); }
    float m = red[0] * (1.f/768.f);
    __syncthreads();
    float s2 = 0.f;
    #pragma unroll
    for (int i = 0; i < 3; i++){ float d = v[i] - m; s2 += d*d; }
    red[t] = s2; __syncthreads();
    for (int s = 128; s; s >>= 1){ if (t < s) red[t] += red[t + s]; __syncthreads(); }
    float var = red[0] * (1.f/768.f);
    float rstd = rsqrtf(var + 1e-5f);
    #pragma unroll
    for (int i = 0; i < 3; i++){
        int c = t + i*256;
        float o = (v[i] - m)*rstd*w[c] + bb[c];
        p[c] = o;
        p16[c] = __float2half_rn(o);
    }
}

// ---------------- final transpose ----------------
__global__ void transpose_out_kernel(const float* __restrict__ tgt, float* __restrict__ out){
    __shared__ float tile[32][33];
    int c0 = blockIdx.x*32, t0 = blockIdx.y*32, b = blockIdx.z;
    for (int i = threadIdx.y; i < 32; i += 8)
        tile[i][threadIdx.x] = tgt[((size_t)b*T_ + t0 + i)*C_ + c0 + threadIdx.x];
    __syncthreads();
    for (int i = threadIdx.y; i < 32; i += 8)
        out[((size_t)b*C_ + c0 + i)*T_ + t0 + threadIdx.x] = tile[threadIdx.x][i];
}

// ---------------- launch ----------------
extern "C" void kernel_launch(void* const* d_in, const int* in_sizes, int n_in,
                              void* d_out, int out_size){
    const float* mainx      = (const float*)d_in[0];
    const float* others[2]  = {(const float*)d_in[1], (const float*)d_in[2]};
    const float* pe         = (const float*)d_in[3];
    const float* mq         = (const float*)d_in[4];
    const float* s_w1       = (const float*)d_in[5];
    const float* s_b1       = (const float*)d_in[6];
    const float* s_w2       = (const float*)d_in[7];
    const float* s_b2       = (const float*)d_in[8];
    const float* sa_in_w    = (const float*)d_in[9];
    const float* sa_in_b    = (const float*)d_in[10];
    const float* sa_out_w   = (const float*)d_in[11];
    const float* sa_out_b   = (const float*)d_in[12];
    const float* ca_in_w    = (const float*)d_in[13];
    const float* ca_in_b    = (const float*)d_in[14];
    const float* ca_out_w   = (const float*)d_in[15];
    const float* ca_out_b   = (const float*)d_in[16];
    const float* ff1_w      = (const float*)d_in[17];
    const float* ff1_b      = (const float*)d_in[18];
    const float* ff2_w      = (const float*)d_in[19];
    const float* ff2_b      = (const float*)d_in[20];
    const float* ln_w       = (const float*)d_in[21];
    const float* ln_b       = (const float*)d_in[22];
    const float* block_rand = (const float*)d_in[23];
    const float* around_rand= (const float*)d_in[24];
    float* out = (float*)d_out;

    float *pf0, *hid0, *mainxT, *coords, *score, *tgt, *tmp, *qkv, *ffh, *memkv, *qb, *exsc;
    int *topidx, *top16;
    __half *pf16, *tgt16, *attn16, *memb16, *ffh16, *wt;
    cudaGetSymbolAddress((void**)&pf0,    g_pf);
    cudaGetSymbolAddress((void**)&hid0,   g_hid);
    cudaGetSymbolAddress((void**)&mainxT, g_mainxT);
    cudaGetSymbolAddress((void**)&coords, g_coords);
    cudaGetSymbolAddress((void**)&score,  g_score);
    cudaGetSymbolAddress((void**)&top16,  g_top16);
    cudaGetSymbolAddress((void**)&exsc,   g_exsc);
    cudaGetSymbolAddress((void**)&topidx, g_topidx);
    cudaGetSymbolAddress((void**)&tgt,    g_tgt);
    cudaGetSymbolAddress((void**)&tmp,    g_tmp);
    cudaGetSymbolAddress((void**)&qkv,    g_qkv);
    cudaGetSymbolAddress((void**)&ffh,    g_ffh);
    cudaGetSymbolAddress((void**)&memkv,  g_memkv);
    cudaGetSymbolAddress((void**)&qb,     g_q);
    cudaGetSymbolAddress((void**)&pf16,   g_pf16);
    cudaGetSymbolAddress((void**)&tgt16,  g_tgt16);
    cudaGetSymbolAddress((void**)&attn16, g_attn16);
    cudaGetSymbolAddress((void**)&memb16, g_memb16);
    cudaGetSymbolAddress((void**)&ffh16,  g_ffh16);
    cudaGetSymbolAddress((void**)&wt,     g_wt);

    size_t o = 0;
    __half* wtS = wt + o; o += (size_t)768*768;
    __half *wtSAin[L_], *wtSAout[L_], *wtCAin[L_], *wtCAout[L_], *wtFF1[L_], *wtFF2[L_];
    for (int l = 0; l < L_; l++){
        wtSAin[l]  = wt + o; o += (size_t)2304*768;
        wtSAout[l] = wt + o; o += (size_t)768*768;
        wtCAin[l]  = wt + o; o += (size_t)2304*768;
        wtCAout[l] = wt + o; o += (size_t)768*768;
        wtFF1[l]   = wt + o; o += (size_t)3072*768;
        wtFF2[l]   = wt + o; o += (size_t)768*3072;
    }

    float* pf1  = ffh;
    float* hid1 = ffh + (size_t)B_*NPTS*C_;

    const int FA_SMEM = (96*FA_PADK + 128*FA_PADV + 128*FA_PADK) * 4;
    cudaFuncSetAttribute(flash_attn_kernel, cudaFuncAttributeMaxDynamicSharedMemorySize, FA_SMEM);

    static cudaStream_t s_m[2] = {nullptr, nullptr};
    static cudaEvent_t  ev_start = nullptr, ev_m[2] = {nullptr, nullptr};
    if (s_m[0] == nullptr){
        cudaStreamCreateWithFlags(&s_m[0], cudaStreamNonBlocking);
        cudaStreamCreateWithFlags(&s_m[1], cudaStreamNonBlocking);
        cudaEventCreateWithFlags(&ev_start, cudaEventDisableTiming);
        cudaEventCreateWithFlags(&ev_m[0], cudaEventDisableTiming);
        cudaEventCreateWithFlags(&ev_m[1], cudaEventDisableTiming);
    }

    // pre-fork work side streams depend on: score weight + mainxT
    transpose_w(s_w1, wtS, 768, 768, 0);
    {
        dim3 g(C_/32, T_/32, B_); dim3 bl(32, 8);
        transpose_in_kernel<<<g, bl>>>(mainx, mainxT);
    }
    cudaEventRecord(ev_start, 0);

    // ---- fork: modality pipelines ----
    float*  pfs[2]   = {pf0, pf1};
    float*  hids[2]  = {hid0, hid1};
    for (int i = 0; i < 2; i++){
        cudaStream_t st = s_m[i];
        cudaStreamWaitEvent(st, ev_start, 0);
        float*  pf_i   = pfs[i];
        __half* pf16_i = pf16 + (size_t)i*B_*NPTS*C_;
        float*  hid_i  = hids[i];
        float* coords_i = coords + (size_t)i*B_*NPTS*2;
        float* score_i  = score  + (size_t)i*B_*NPTS;
        int*   top16_i  = top16  + i*B_*NCAND;
        float* exsc_i   = exsc   + i*B_*NCAND;
        int*   topidx_i = topidx + i*B_*TOPK_;
        {
            dim3 g(C_/32, T_/32, B_); dim3 bl(32, 8);
            transpose_in_kernel<<<g, bl, 0, st>>>(others[i], hid_i);
        }
        sample_kernel<<<B_*NPTS/16, 256, 0, st>>>(hid_i, block_rand + (size_t)i*B_*32*32*2*2,
                                                  pf_i, pf16_i, coords_i);
        zero_score_kernel<<<(B_*NPTS + 255)/256, 256, 0, st>>>(score_i);
        h_gemm<2>(pf16_i, wtS, s_b1, nullptr, nullptr, s_w2, score_i,
                  B_*NPTS, C_, C_, C_, C_, 0, st);
        topk_kernel<<<B_, 256, 0, st>>>(score_i, top16_i, NCAND);
        rescore_kernel<<<B_*NCAND, 256, 0, st>>>(pf_i, s_w1, s_b1, s_w2, top16_i, exsc_i);
        final_top5_kernel<<<B_, 32, 0, st>>>(exsc_i, top16_i, topidx_i);
        soft_align_kernel<<<B_*TOPK_, 256, 0, st>>>(mainxT, pe,
                                                    around_rand + (size_t)i*B_*AROUND_*TOPK_*2,
                                                    mq + (size_t)(i+1)*C_,
                                                    pf_i, coords_i, topidx_i, memb16, i*TOPK_);
        cudaEventRecord(ev_m[i], st);
    }

    // ---- decoder weight transposes + prefix on main stream ----
    for (int l = 0; l < L_; l++){
        transpose_w(sa_in_w  + (size_t)l*C_*3*C_, wtSAin[l],  768, 2304, 0);
        transpose_w(sa_out_w + (size_t)l*C_*C_,   wtSAout[l], 768, 768,  0);
        transpose_w(ca_in_w  + (size_t)l*C_*3*C_, wtCAin[l],  768, 2304, 0);
        transpose_w(ca_out_w + (size_t)l*C_*C_,   wtCAout[l], 768, 768,  0);
        transpose_w(ff1_w    + (size_t)l*C_*FF_,  wtFF1[l],   768, 3072, 0);
        transpose_w(ff2_w    + (size_t)l*FF_*C_,  wtFF2[l],   3072, 768, 0);
    }
    tgt_init_kernel<<<(int)(((size_t)B_*T_*C_ + 255)/256), 256>>>(mainxT, mq, pe, tgt, tgt16);

    // layer 0 SA block + CA-q (no memb dependency)
    h_gemm<0>(tgt16, wtSAin[0], sa_in_b, qkv, nullptr, nullptr, nullptr,
              B_*T_, 3*C_, C_, C_, C_, 3*C_, 0);
    { dim3 g(T_/128, B_*NHEAD_); flash_attn_kernel<<<g, 256, FA_SMEM>>>(qkv, attn16); }
    h_gemm<0>(attn16, wtSAout[0], sa_out_b, tmp, nullptr, nullptr, nullptr,
              B_*T_, C_, C_, C_, C_, C_, 0);
    add_ln_kernel<<<B_*T_, 256>>>(tgt, tgt16, tmp, ln_w, ln_b);
    h_gemm<0>(tgt16, wtCAin[0], ca_in_b, qb, nullptr, nullptr, nullptr,
              B_*T_, C_, C_, C_, C_, C_, 0);

    // ---- join ----
    cudaStreamWaitEvent(0, ev_m[0], 0);
    cudaStreamWaitEvent(0, ev_m[1], 0);

    for (int l = 0; l < L_; l++){
        if (l > 0){
            h_gemm<0>(tgt16, wtSAin[l], sa_in_b + (size_t)l*3*C_, qkv, nullptr, nullptr, nullptr,
                      B_*T_, 3*C_, C_, C_, C_, 3*C_, 0);
            { dim3 g(T_/128, B_*NHEAD_); flash_attn_kernel<<<g, 256, FA_SMEM>>>(qkv, attn16); }
            h_gemm<0>(attn16, wtSAout[l], sa_out_b + (size_t)l*C_, tmp, nullptr, nullptr, nullptr,
                      B_*T_, C_, C_, C_, C_, C_, 0);
            add_ln_kernel<<<B_*T_, 256>>>(tgt, tgt16, tmp, ln_w + (size_t)(l*3+0)*C_, ln_b + (size_t)(l*3+0)*C_);
            h_gemm<0>(tgt16, wtCAin[l], ca_in_b + (size_t)l*3*C_, qb, nullptr, nullptr, nullptr,
                      B_*T_, C_, C_, C_, C_, C_, 0);
        }
        h_gemm<0>(memb16, wtCAin[l] + (size_t)768*C_, ca_in_b + (size_t)l*3*C_ + C_, memkv,
                  nullptr, nullptr, nullptr, B_*10, 2*C_, C_, C_, C_, 2*C_, 0);
        { dim3 g(T_/256, B_*NHEAD_); ca_attn_kernel<<<g, 256>>>(qb, memkv, attn16); }
        h_gemm<0>(attn16, wtCAout[l], ca_out_b + (size_t)l*C_, tmp, nullptr, nullptr, nullptr,
                  B_*T_, C_, C_, C_, C_, C_, 0);
        add_ln_kernel<<<B_*T_, 256>>>(tgt, tgt16, tmp, ln_w + (size_t)(l*3+1)*C_, ln_b + (size_t)(l*3+1)*C_);

        h_gemm<1>(tgt16, wtFF1[l], ff1_b + (size_t)l*FF_, nullptr, ffh16, nullptr, nullptr,
                  B_*T_, FF_, C_, C_, C_, FF_, 0);
        h_gemm<0>(ffh16, wtFF2[l], ff2_b + (size_t)l*C_, tmp, nullptr, nullptr, nullptr,
                  B_*T_, C_, FF_, FF_, FF_, C_, 0);
        add_ln_kernel<<<B_*T_, 256>>>(tgt, tgt16, tmp, ln_w + (size_t)(l*3+2)*C_, ln_b + (size_t)(l*3+2)*C_);
    }

    {
        dim3 g(C_/32, T_/32, B_); dim3 bl(32, 8);
        transpose_out_kernel<<<g, bl>>>(tgt, out);
    }
}

// round 13
// speedup vs baseline: 1.0872x; 1.0872x over previous
#include <cuda_runtime.h>
#include <cuda_fp16.h>
#include <math.h>
#include <stdint.h>

// ---------------- constants ----------------
#define B_   8
#define C_   768
#define T_   1024
#define L_   2
#define FF_  3072
#define NPTS 2048
#define TOPK_ 5
#define NCAND 16
#define AROUND_ 5
#define NHEAD_ 8
#define HD_  96

// ---------------- scratch ----------------
__device__ float g_pf    [(size_t)B_*NPTS*C_];
__device__ float g_hid   [(size_t)B_*NPTS*C_];
__device__ float g_mainxT[(size_t)B_*T_*C_];
__device__ float g_coords[2*(size_t)B_*NPTS*2];
__device__ float g_score [2*(size_t)B_*NPTS];
__device__ int   g_top16 [2*B_*NCAND];
__device__ float g_exsc  [2*B_*NCAND];
__device__ int   g_topidx[2*B_*TOPK_];
__device__ float g_tgt   [(size_t)B_*T_*C_];
__device__ float g_tmp   [(size_t)B_*T_*C_];
__device__ float g_ffh   [(size_t)B_*T_*FF_];      // phase-A scratch: pf1 + xT1
__device__ float g_memkv [(size_t)B_*10*2*C_];
__device__ float g_q     [(size_t)B_*T_*C_];
// fp16 mirrors / weights
__device__ __align__(256) __half g_qkv16 [(size_t)B_*T_*3*C_];
__device__ __align__(256) __half g_pf16  [2*(size_t)B_*NPTS*C_];
__device__ __align__(256) __half g_tgt16 [(size_t)B_*T_*C_];
__device__ __align__(256) __half g_attn16[(size_t)B_*T_*C_];
__device__ __align__(256) __half g_memb16[(size_t)B_*10*C_];
__device__ __align__(256) __half g_ffh16 [(size_t)B_*T_*FF_];
__device__ __align__(256) __half g_wt    [19464192];

// ---------------- fp16 mma (m16n8k16) ----------------
__device__ __forceinline__ void mma16(float* d, const uint32_t* a, const uint32_t* b){
    asm volatile("mma.sync.aligned.m16n8k16.row.col.f32.f16.f16.f32 "
        "{%0,%1,%2,%3},{%4,%5,%6,%7},{%8,%9},{%0,%1,%2,%3};\n"
        : "+f"(d[0]), "+f"(d[1]), "+f"(d[2]), "+f"(d[3])
        : "r"(a[0]), "r"(a[1]), "r"(a[2]), "r"(a[3]), "r"(b[0]), "r"(b[1]));
}

// ---------------- fp16 GEMM (R11 scalar-LDS inner loop) ----------------
// MODE 0: fp32 C out. MODE 1: relu + half C16 out. MODE 2: score. MODE 3: half C16, no relu.
#define H_STRIDE_W 20
#define H_STAGE_B  20480
#define H_SMEM_B   (4*H_STAGE_B)

template<int MODE>
__global__ __launch_bounds__(256, 2)
void h_gemm_kernel(const __half* __restrict__ A, const __half* __restrict__ WT,
                   const float* __restrict__ bias, float* __restrict__ C,
                   __half* __restrict__ C16, const float* __restrict__ w2,
                   float* __restrict__ score,
                   int M, int N, int K, int lda, int ldb, int ldc)
{
    extern __shared__ char smraw[];

    int tid = threadIdx.x, lane = tid & 31, warp = tid >> 5;
    int gid = lane >> 2, tig = lane & 3;
    int wm = warp >> 2, wn = warp & 3;
    int row0 = blockIdx.y * 128, col0 = blockIdx.x * 128;

    float acc[4][4][4];
    #pragma unroll
    for (int i = 0; i < 4; i++)
        #pragma unroll
        for (int j = 0; j < 4; j++)
            #pragma unroll
            for (int r = 0; r < 4; r++) acc[i][j][r] = 0.f;

    int r0l = tid >> 2,         seg0 = tid & 3;
    int r1l = (tid + 256) >> 2, seg1 = tid & 3;
    int ss0 = (row0 + r0l < M) ? 16 : 0;
    int ss1 = (row0 + r1l < M) ? 16 : 0;
    int car0 = ss0 ? row0 + r0l : 0;
    int car1 = ss1 ? row0 + r1l : 0;

    auto issue_stage = [&](int stage, int k0){
        char* Ab = smraw + stage*H_STAGE_B;
        char* Bb = Ab + 10240;
        {
            uint32_t d = (uint32_t)__cvta_generic_to_shared(Ab + r0l*80 + seg0*16);
            const __half* s = A + (size_t)car0*lda + k0 + seg0*8;
            asm volatile("cp.async.cg.shared.global [%0], [%1], 16, %2;\n" :: "r"(d), "l"(s), "r"(ss0));
        }
        {
            uint32_t d = (uint32_t)__cvta_generic_to_shared(Ab + r1l*80 + seg1*16);
            const __half* s = A + (size_t)car1*lda + k0 + seg1*8;
            asm volatile("cp.async.cg.shared.global [%0], [%1], 16, %2;\n" :: "r"(d), "l"(s), "r"(ss1));
        }
        {
            uint32_t d = (uint32_t)__cvta_generic_to_shared(Bb + r0l*80 + seg0*16);
            const __half* s = WT + (size_t)(col0 + r0l)*ldb + k0 + seg0*8;
            asm volatile("cp.async.cg.shared.global [%0], [%1], 16;\n" :: "r"(d), "l"(s));
        }
        {
            uint32_t d = (uint32_t)__cvta_generic_to_shared(Bb + r1l*80 + seg1*16);
            const __half* s = WT + (size_t)(col0 + r1l)*ldb + k0 + seg1*8;
            asm volatile("cp.async.cg.shared.global [%0], [%1], 16;\n" :: "r"(d), "l"(s));
        }
        asm volatile("cp.async.commit_group;\n" ::: "memory");
    };

    auto compute = [&](int stage){
        const uint32_t* As = (const uint32_t*)(smraw + stage*H_STAGE_B);
        const uint32_t* Bs = As + 128*H_STRIDE_W;
        #pragma unroll
        for (int kk = 0; kk < 2; kk++){
            int kw = kk*8 + tig;
            uint32_t af[4][4], bf[4][2];
            #pragma unroll
            for (int ma = 0; ma < 4; ma++){
                int m = wm*64 + ma*16 + gid;
                af[ma][0] = As[m*H_STRIDE_W + kw];
                af[ma][1] = As[(m+8)*H_STRIDE_W + kw];
                af[ma][2] = As[m*H_STRIDE_W + kw + 4];
                af[ma][3] = As[(m+8)*H_STRIDE_W + kw + 4];
            }
            #pragma unroll
            for (int na = 0; na < 4; na++){
                int n = wn*32 + na*8 + gid;
                bf[na][0] = Bs[n*H_STRIDE_W + kw];
                bf[na][1] = Bs[n*H_STRIDE_W + kw + 4];
            }
            #pragma unroll
            for (int ma = 0; ma < 4; ma++)
                #pragma unroll
                for (int na = 0; na < 4; na++)
                    mma16(acc[ma][na], af[ma], bf[na]);
        }
    };

    int nc = K / 32;
    #pragma unroll
    for (int s = 0; s < 3; s++) issue_stage(s, s*32);
    for (int it = 0; it < nc; it++){
        asm volatile("cp.async.wait_group 2;\n" ::: "memory");
        __syncthreads();
        int nxt = it + 3;
        if (nxt < nc) issue_stage(nxt & 3, nxt*32);
        else asm volatile("cp.async.commit_group;\n" ::: "memory");
        compute(it & 3);
    }

    #pragma unroll
    for (int ma = 0; ma < 4; ma++){
        int r0 = row0 + wm*64 + ma*16 + gid;
        float s0 = 0.f, s1 = 0.f;
        #pragma unroll
        for (int na = 0; na < 4; na++){
            int c = col0 + wn*32 + na*8 + 2*tig;
            float b0 = bias ? bias[c] : 0.f;
            float b1 = bias ? bias[c+1] : 0.f;
            float x0 = acc[ma][na][0] + b0;
            float x1 = acc[ma][na][1] + b1;
            float x2 = acc[ma][na][2] + b0;
            float x3 = acc[ma][na][3] + b1;
            if (MODE == 1 || MODE == 2){
                x0 = fmaxf(x0, 0.f); x1 = fmaxf(x1, 0.f);
                x2 = fmaxf(x2, 0.f); x3 = fmaxf(x3, 0.f);
            }
            if (MODE == 2){
                float w0 = w2[c], w1 = w2[c+1];
                s0 += x0*w0 + x1*w1;
                s1 += x2*w0 + x3*w1;
            } else if (MODE == 1 || MODE == 3){
                if (r0 < M)     *(__half2*)&C16[(size_t)r0*ldc + c]     = __floats2half2_rn(x0, x1);
                if (r0 + 8 < M) *(__half2*)&C16[(size_t)(r0+8)*ldc + c] = __floats2half2_rn(x2, x3);
            } else {
                if (r0 < M){ float2 o = make_float2(x0, x1); *(float2*)&C[(size_t)r0*ldc + c] = o; }
                if (r0 + 8 < M){ float2 o = make_float2(x2, x3); *(float2*)&C[(size_t)(r0+8)*ldc + c] = o; }
            }
        }
        if (MODE == 2){
            s0 += __shfl_xor_sync(0xffffffffu, s0, 1);
            s0 += __shfl_xor_sync(0xffffffffu, s0, 2);
            s1 += __shfl_xor_sync(0xffffffffu, s1, 1);
            s1 += __shfl_xor_sync(0xffffffffu, s1, 2);
            if (tig == 0){
                if (r0 < M)     atomicAdd(&score[r0], s0);
                if (r0 + 8 < M) atomicAdd(&score[r0 + 8], s1);
            }
        }
    }
}

template<int MODE>
static void h_gemm(const __half* A, const __half* WT, const float* bias, float* C,
                   __half* C16, const float* w2, float* score,
                   int M, int N, int K, int lda, int ldb, int ldc, cudaStream_t st){
    cudaFuncSetAttribute(h_gemm_kernel<MODE>, cudaFuncAttributeMaxDynamicSharedMemorySize, H_SMEM_B);
    dim3 grid(N/128, (M + 127)/128);
    h_gemm_kernel<MODE><<<grid, 256, H_SMEM_B, st>>>(A, WT, bias, C, C16, w2, score, M, N, K, lda, ldb, ldc);
}

// ---------------- weight transpose+convert ----------------
__global__ void transpose_w_kernel(const float* __restrict__ W, __half* __restrict__ WT,
                                   int K, int N){
    __shared__ float tile[32][33];
    int n0 = blockIdx.x*32, k0 = blockIdx.y*32;
    for (int i = threadIdx.y; i < 32; i += 8)
        tile[i][threadIdx.x] = W[(size_t)(k0 + i)*N + n0 + threadIdx.x];
    __syncthreads();
    for (int i = threadIdx.y; i < 32; i += 8)
        WT[(size_t)(n0 + i)*K + k0 + threadIdx.x] = __float2half_rn(tile[threadIdx.x][i]);
}
static void transpose_w(const float* W, __half* WT, int K, int N, cudaStream_t st){
    dim3 g(N/32, K/32); dim3 bl(32, 8);
    transpose_w_kernel<<<g, bl, 0, st>>>(W, WT, K, N);
}

// ---------------- flash attention (fp16 mma, online softmax) ----------------
// smem (uint32 words): Ks [48][136], Vs [64][104], Ps [64][136]  -> 87552 B
#define FA_KS_STR 136
#define FA_VS_STR 104
#define FA_SMEM_B ((48*136 + 64*104 + 64*136)*4)
#define FA_LOG2E 1.4426950408889634f

__global__ __launch_bounds__(256, 1)
void flash_attn_kernel(const __half* __restrict__ qkv, __half* __restrict__ out16){
    extern __shared__ uint32_t sm32[];
    uint32_t* Ks = sm32;                 // [dpair 0..47][row 0..127]
    uint32_t* Vs = Ks + 48*FA_KS_STR;    // [seqpair 0..63][n 0..95]
    uint32_t* Ps = Vs + 64*FA_VS_STR;    // [seqpair 0..63][m 0..127]

    int qt = blockIdx.x, bh = blockIdx.y, b = bh >> 3, h = bh & 7;
    int tid = threadIdx.x, lane = tid & 31, warp = tid >> 5;
    int gid = lane >> 2, tig = lane & 3;
    int m0 = warp * 16;
    int q0 = qt * 128;
    const float iscale = 0.10206207261596577f;

    // Q fragments: packed half2 along headdim; 6 k16-steps
    uint32_t qf[6][4];
    {
        const __half* Qa = qkv + (size_t)(b*T_ + q0 + m0 + gid)*(3*C_) + h*HD_;
        const __half* Qb = Qa + 8*(3*C_);
        #pragma unroll
        for (int kk = 0; kk < 6; kk++){
            qf[kk][0] = *(const uint32_t*)&Qa[(kk*8 + tig)*2];
            qf[kk][1] = *(const uint32_t*)&Qb[(kk*8 + tig)*2];
            qf[kk][2] = *(const uint32_t*)&Qa[(kk*8 + tig + 4)*2];
            qf[kk][3] = *(const uint32_t*)&Qb[(kk*8 + tig + 4)*2];
        }
    }

    float oacc[12][4];
    #pragma unroll
    for (int i = 0; i < 12; i++)
        #pragma unroll
        for (int j = 0; j < 4; j++) oacc[i][j] = 0.f;
    float mrow0 = -1e30f, mrow1 = -1e30f, lrow0 = 0.f, lrow1 = 0.f;

    for (int kt = 0; kt < 8; kt++){
        __syncthreads();
        {
            const __half* Kb = qkv + (size_t)(b*T_ + kt*128)*(3*C_) + C_ + h*HD_;
            const __half* Vb = Kb + C_;
            // K: [dpair][row]
            for (int idx = tid; idx < 128*48; idx += 256){
                int r = idx / 48, d = idx % 48;
                Ks[d*FA_KS_STR + r] = *(const uint32_t*)&Kb[(size_t)r*(3*C_) + d*2];
            }
            // V: [seqpair][n] (pack two seq rows)
            for (int idx = tid; idx < 64*96; idx += 256){
                int p = idx / 96, n = idx % 96;
                __half lo = Vb[(size_t)(2*p)*(3*C_) + n];
                __half hi = Vb[(size_t)(2*p + 1)*(3*C_) + n];
                __half2 hv = __halves2half2(lo, hi);
                Vs[p*FA_VS_STR + n] = *(const uint32_t*)&hv;
            }
        }
        __syncthreads();

        float sacc[16][4];
        #pragma unroll
        for (int nf = 0; nf < 16; nf++)
            #pragma unroll
            for (int j = 0; j < 4; j++) sacc[nf][j] = 0.f;
        #pragma unroll
        for (int kk = 0; kk < 6; kk++){
            int k1 = (kk*8 + tig)*FA_KS_STR, k2 = (kk*8 + tig + 4)*FA_KS_STR;
            #pragma unroll
            for (int nf = 0; nf < 16; nf++){
                uint32_t bfr[2] = { Ks[k1 + nf*8 + gid], Ks[k2 + nf*8 + gid] };
                mma16(sacc[nf], qf[kk], bfr);
            }
        }
        #pragma unroll
        for (int nf = 0; nf < 16; nf++){
            sacc[nf][0] *= iscale; sacc[nf][1] *= iscale;
            sacc[nf][2] *= iscale; sacc[nf][3] *= iscale;
        }

        float rm0 = -1e30f, rm1 = -1e30f;
        #pragma unroll
        for (int nf = 0; nf < 16; nf++){
            rm0 = fmaxf(rm0, fmaxf(sacc[nf][0], sacc[nf][1]));
            rm1 = fmaxf(rm1, fmaxf(sacc[nf][2], sacc[nf][3]));
        }
        rm0 = fmaxf(rm0, __shfl_xor_sync(0xffffffffu, rm0, 1));
        rm0 = fmaxf(rm0, __shfl_xor_sync(0xffffffffu, rm0, 2));
        rm1 = fmaxf(rm1, __shfl_xor_sync(0xffffffffu, rm1, 1));
        rm1 = fmaxf(rm1, __shfl_xor_sync(0xffffffffu, rm1, 2));
        float mn0 = fmaxf(mrow0, rm0), mn1 = fmaxf(mrow1, rm1);
        float al0 = exp2f((mrow0 - mn0)*FA_LOG2E);
        float al1 = exp2f((mrow1 - mn1)*FA_LOG2E);
        mrow0 = mn0; mrow1 = mn1;
        float rs0 = 0.f, rs1 = 0.f;
        #pragma unroll
        for (int nf = 0; nf < 16; nf++){
            float p0 = exp2f((sacc[nf][0] - mn0)*FA_LOG2E);
            float p1 = exp2f((sacc[nf][1] - mn0)*FA_LOG2E);
            float p2 = exp2f((sacc[nf][2] - mn1)*FA_LOG2E);
            float p3 = exp2f((sacc[nf][3] - mn1)*FA_LOG2E);
            sacc[nf][0] = p0; sacc[nf][1] = p1; sacc[nf][2] = p2; sacc[nf][3] = p3;
            rs0 += p0 + p1; rs1 += p2 + p3;
        }
        rs0 += __shfl_xor_sync(0xffffffffu, rs0, 1);
        rs0 += __shfl_xor_sync(0xffffffffu, rs0, 2);
        rs1 += __shfl_xor_sync(0xffffffffu, rs1, 1);
        rs1 += __shfl_xor_sync(0xffffffffu, rs1, 2);
        lrow0 = lrow0*al0 + rs0;
        lrow1 = lrow1*al1 + rs1;
        #pragma unroll
        for (int nf = 0; nf < 12; nf++){
            oacc[nf][0] *= al0; oacc[nf][1] *= al0;
            oacc[nf][2] *= al1; oacc[nf][3] *= al1;
        }

        // store packed P: cols (2tig,2tig+1) -> seqpair word nf*4+tig
        #pragma unroll
        for (int nf = 0; nf < 16; nf++){
            int cp = nf*4 + tig;
            __half2 h0 = __floats2half2_rn(sacc[nf][0], sacc[nf][1]);
            __half2 h1 = __floats2half2_rn(sacc[nf][2], sacc[nf][3]);
            Ps[cp*FA_KS_STR + m0 + gid]     = *(const uint32_t*)&h0;
            Ps[cp*FA_KS_STR + m0 + gid + 8] = *(const uint32_t*)&h1;
        }
        __syncwarp();

        // O += P @ V : 8 k16-steps over 64 seq pairs
        #pragma unroll
        for (int kk = 0; kk < 8; kk++){
            int k1 = (kk*8 + tig)*FA_KS_STR, k2 = (kk*8 + tig + 4)*FA_KS_STR;
            uint32_t pa[4] = { Ps[k1 + m0 + gid], Ps[k1 + m0 + gid + 8],
                               Ps[k2 + m0 + gid], Ps[k2 + m0 + gid + 8] };
            int v1 = (kk*8 + tig)*FA_VS_STR, v2 = (kk*8 + tig + 4)*FA_VS_STR;
            #pragma unroll
            for (int nf = 0; nf < 12; nf++){
                uint32_t vb2[2] = { Vs[v1 + nf*8 + gid], Vs[v2 + nf*8 + gid] };
                mma16(oacc[nf], pa, vb2);
            }
        }
    }

    float inv0 = 1.f / lrow0, inv1 = 1.f / lrow1;
    size_t r0 = (size_t)(b*T_ + q0 + m0 + gid);
    #pragma unroll
    for (int nf = 0; nf < 12; nf++){
        int col = h*HD_ + nf*8 + 2*tig;
        *(__half2*)&out16[r0*C_ + col]       = __floats2half2_rn(oacc[nf][0]*inv0, oacc[nf][1]*inv0);
        *(__half2*)&out16[(r0 + 8)*C_ + col] = __floats2half2_rn(oacc[nf][2]*inv1, oacc[nf][3]*inv1);
    }
}

// ---------------- transpose x [B,C,T] -> xT [B,T,C] ----------------
__global__ void transpose_in_kernel(const float* __restrict__ x, float* __restrict__ xT){
    __shared__ float tile[32][33];
    int c0 = blockIdx.x*32, t0 = blockIdx.y*32, b = blockIdx.z;
    for (int i = threadIdx.y; i < 32; i += 8)
        tile[i][threadIdx.x] = x[((size_t)b*C_ + c0 + i)*T_ + t0 + threadIdx.x];
    __syncthreads();
    for (int i = threadIdx.y; i < 32; i += 8)
        xT[((size_t)b*T_ + t0 + i)*C_ + c0 + threadIdx.x] = tile[threadIdx.x][i];
}

// ---------------- blockwise sampling (fp32 + fp16 out) ----------------
__global__ void sample_kernel(const float* __restrict__ xT, const float* __restrict__ brand,
                              float* __restrict__ pf, __half* __restrict__ pf16,
                              float* __restrict__ coords){
    int p0 = blockIdx.x * 16;
    __shared__ int   sidx[16][4];
    __shared__ float swt [16][4];
    int tid = threadIdx.x;
    if (tid < 16){
        int bn = p0 + tid;
        int b  = bn >> 11;
        int n  = bn & 2047;
        int k  = n & 1;
        int pw = (n >> 1) & 31;
        int ph = n >> 6;
        const float bs = 0.0625f;
        const float* br = brand + ((((size_t)b*32 + ph)*32 + pw)*2 + k)*2;
        float gx = br[0]*bs + (-1.0f + ph*bs);
        float gy = br[1]*bs + (-1.0f + pw*bs);
        coords[(size_t)bn*2]     = gx;
        coords[(size_t)bn*2 + 1] = gy;
        float ix = ((gx + 1.0f)*32.0f - 1.0f)*0.5f;
        float iy = ((gy + 1.0f)*32.0f - 1.0f)*0.5f;
        float x0f = floorf(ix), y0f = floorf(iy);
        int x0 = (int)x0f, y0 = (int)y0f;
        float wx1 = ix - x0f, wy1 = iy - y0f;
        float wxs[2] = {1.f - wx1, wx1};
        float wys[2] = {1.f - wy1, wy1};
        #pragma unroll
        for (int j = 0; j < 4; j++){
            int xi = x0 + (j & 1), yi = y0 + (j >> 1);
            bool v = (xi >= 0) & (xi < 32) & (yi >= 0) & (yi < 32);
            sidx[tid][j] = v ? (yi*32 + xi) : 0;
            swt [tid][j] = v ? (wxs[j & 1]*wys[j >> 1]) : 0.f;
        }
    }
    __syncthreads();
    int b = (p0 >> 11);
    const float* base = xT + (size_t)b*T_*C_;
    for (int pt = 0; pt < 16; pt++){
        const float* r0 = base + (size_t)sidx[pt][0]*C_;
        const float* r1 = base + (size_t)sidx[pt][1]*C_;
        const float* r2 = base + (size_t)sidx[pt][2]*C_;
        const float* r3 = base + (size_t)sidx[pt][3]*C_;
        float w0 = swt[pt][0], w1 = swt[pt][1], w2 = swt[pt][2], w3 = swt[pt][3];
        float* dst = pf + (size_t)(p0 + pt)*C_;
        __half* dst16 = pf16 + (size_t)(p0 + pt)*C_;
        for (int c = tid; c < C_; c += 256){
            float v = r0[c]*w0 + r1[c]*w1 + r2[c]*w2 + r3[c]*w3;
            dst[c] = v;
            dst16[c] = __float2half_rn(v);
        }
    }
}

// ---------------- zero score ----------------
__global__ void zero_score_kernel(float* __restrict__ score){
    int i = blockIdx.x*256 + threadIdx.x;
    if (i < B_*NPTS) score[i] = 0.f;
}

// ---------------- top-K ----------------
__global__ void topk_kernel(const float* __restrict__ score, int* __restrict__ topidx, int K){
    int b = blockIdx.x;
    __shared__ float sv[2048];
    __shared__ float rv[256];
    __shared__ int   ri[256];
    for (int j = threadIdx.x; j < 2048; j += 256) sv[j] = score[(size_t)b*2048 + j];
    __syncthreads();
    for (int t = 0; t < K; t++){
        float bv = -1e30f; int bi = 0x7fffffff;
        for (int j = threadIdx.x; j < 2048; j += 256){
            float v = sv[j];
            if (v > bv){ bv = v; bi = j; }
        }
        rv[threadIdx.x] = bv; ri[threadIdx.x] = bi;
        __syncthreads();
        for (int s = 128; s; s >>= 1){
            if (threadIdx.x < s){
                float v2 = rv[threadIdx.x + s]; int i2 = ri[threadIdx.x + s];
                if (v2 > rv[threadIdx.x] || (v2 == rv[threadIdx.x] && i2 < ri[threadIdx.x])){
                    rv[threadIdx.x] = v2; ri[threadIdx.x] = i2;
                }
            }
            __syncthreads();
        }
        if (threadIdx.x == 0){
            topidx[b*K + t] = ri[0];
            sv[ri[0]] = -1e30f;
        }
        __syncthreads();
    }
}

// ---------------- exact fp32 rescore ----------------
__global__ __launch_bounds__(256)
void rescore_kernel(const float* __restrict__ pf, const float* __restrict__ W1,
                    const float* __restrict__ b1, const float* __restrict__ w2,
                    const int* __restrict__ cand, float* __restrict__ exsc){
    int b = blockIdx.x >> 4, c = blockIdx.x & 15;
    int idx = cand[b*NCAND + c];
    __shared__ float spf[C_];
    int tid = threadIdx.x;
    for (int i = tid; i < C_; i += 256) spf[i] = pf[((size_t)b*NPTS + idx)*C_ + i];
    __syncthreads();
    float a0 = b1[tid], a1 = b1[tid+256], a2 = b1[tid+512];
    for (int k = 0; k < C_; k++){
        float v = spf[k];
        const float* w = W1 + (size_t)k*C_;
        a0 += v * w[tid];
        a1 += v * w[tid+256];
        a2 += v * w[tid+512];
    }
    float p = fmaxf(a0,0.f)*w2[tid] + fmaxf(a1,0.f)*w2[tid+256] + fmaxf(a2,0.f)*w2[tid+512];
    #pragma unroll
    for (int o = 16; o; o >>= 1) p += __shfl_down_sync(0xffffffffu, p, o);
    __shared__ float red[8];
    if ((tid & 31) == 0) red[tid >> 5] = p;
    __syncthreads();
    if (tid == 0){
        float s = 0.f;
        #pragma unroll
        for (int i = 0; i < 8; i++) s += red[i];
        exsc[b*NCAND + c] = s;
    }
}

// ---------------- final exact top-5 ----------------
__global__ void final_top5_kernel(const float* __restrict__ exsc, const int* __restrict__ cand,
                                  int* __restrict__ topidx){
    int b = blockIdx.x;
    if (threadIdx.x == 0){
        float s[NCAND]; int id[NCAND];
        for (int i = 0; i < NCAND; i++){ s[i] = exsc[b*NCAND + i]; id[i] = cand[b*NCAND + i]; }
        for (int t = 0; t < TOPK_; t++){
            int bi = 0;
            float bv = -1e30f; int bid = 0x7fffffff;
            for (int i = 0; i < NCAND; i++){
                if (s[i] > bv || (s[i] == bv && id[i] < bid)){ bv = s[i]; bid = id[i]; bi = i; }
            }
            topidx[b*TOPK_ + t] = id[bi];
            s[bi] = -1e30f;
        }
    }
}

// ---------------- soft_align (coalesced via mainxT; fp16 mem rows) ----------------
__global__ void soft_align_kernel(const float* __restrict__ mainxT, const float* __restrict__ pe,
                                  const float* __restrict__ arand, const float* __restrict__ mqrow,
                                  const float* __restrict__ pf, const float* __restrict__ coords,
                                  const int* __restrict__ topidx, __half* __restrict__ memo16, int rowBase){
    int b  = blockIdx.x / TOPK_;
    int nk = blockIdx.x % TOPK_;
    int idx = topidx[b*TOPK_ + nk];
    float px = coords[((size_t)b*NPTS + idx)*2 + 0];
    float py = coords[((size_t)b*NPTS + idx)*2 + 1];
    __shared__ float semb[AROUND_*C_];
    __shared__ float red[256];
    __shared__ float res[11];
    __shared__ float sw[AROUND_];

    int   aidx[AROUND_][4];
    float awt [AROUND_][4];
    #pragma unroll
    for (int a = 0; a < AROUND_; a++){
        const float* ar = arand + (((size_t)b*AROUND_ + a)*TOPK_ + nk)*2;
        float g0 = px + (ar[0]*2.f - 0.5f)*0.2f;
        float g1 = py + (ar[1]*2.f - 0.5f)*0.2f;
        g0 = fminf(fmaxf(g0, -1.f), 1.f);
        g1 = fminf(fmaxf(g1, -1.f), 1.f);
        float ix = ((g0 + 1.f)*32.f - 1.f)*0.5f;
        float iy = ((g1 + 1.f)*32.f - 1.f)*0.5f;
        float x0f = floorf(ix), y0f = floorf(iy);
        int x0 = (int)x0f, y0 = (int)y0f;
        float wx1 = ix - x0f, wy1 = iy - y0f;
        float wxs[2] = {1.f - wx1, wx1};
        float wys[2] = {1.f - wy1, wy1};
        #pragma unroll
        for (int j = 0; j < 4; j++){
            int xi = x0 + (j & 1), yi = y0 + (j >> 1);
            bool v = (xi >= 0) & (xi < 32) & (yi >= 0) & (yi < 32);
            aidx[a][j] = v ? (yi*32 + xi) : 0;
            awt [a][j] = v ? (wxs[j & 1]*wys[j >> 1]) : 0.f;
        }
    }
    const float* xbase = mainxT + (size_t)b*T_*C_;
    const float* pfrow = pf + ((size_t)b*NPTS + idx)*C_;
    float rep2 = 0.f, num[AROUND_], af2[AROUND_];
    #pragma unroll
    for (int a = 0; a < AROUND_; a++){ num[a] = 0.f; af2[a] = 0.f; }
    for (int c = threadIdx.x; c < C_; c += 256){
        float r = pfrow[c];
        rep2 += r*r;
        #pragma unroll
        for (int a = 0; a < AROUND_; a++){
            float af = awt[a][0]*xbase[(size_t)aidx[a][0]*C_ + c]
                     + awt[a][1]*xbase[(size_t)aidx[a][1]*C_ + c]
                     + awt[a][2]*xbase[(size_t)aidx[a][2]*C_ + c]
                     + awt[a][3]*xbase[(size_t)aidx[a][3]*C_ + c];
            num[a] += r*af;
            af2[a] += af*af;
            semb[a*C_ + c] = awt[a][0]*pe[(size_t)aidx[a][0]*C_ + c]
                           + awt[a][1]*pe[(size_t)aidx[a][1]*C_ + c]
                           + awt[a][2]*pe[(size_t)aidx[a][2]*C_ + c]
                           + awt[a][3]*pe[(size_t)aidx[a][3]*C_ + c];
        }
    }
    float vals[11];
    vals[0] = rep2;
    #pragma unroll
    for (int a = 0; a < AROUND_; a++){ vals[1+a] = num[a]; vals[6+a] = af2[a]; }
    for (int v = 0; v < 11; v++){
        red[threadIdx.x] = vals[v];
        __syncthreads();
        for (int s = 128; s; s >>= 1){
            if (threadIdx.x < s) red[threadIdx.x] += red[threadIdx.x + s];
            __syncthreads();
        }
        if (threadIdx.x == 0) res[v] = red[0];
        __syncthreads();
    }
    if (threadIdx.x == 0){
        float rn = fmaxf(sqrtf(res[0]), 1e-8f);
        float s[AROUND_]; float mx = -1e30f;
        for (int a = 0; a < AROUND_; a++){
            s[a] = res[1+a] / (rn * fmaxf(sqrtf(res[6+a]), 1e-8f));
            mx = fmaxf(mx, s[a]);
        }
        float ss = 0.f;
        for (int a = 0; a < AROUND_; a++){ s[a] = expf(s[a] - mx); ss += s[a]; }
        for (int a = 0; a < AROUND_; a++) sw[a] = s[a] / ss;
    }
    __syncthreads();
    float w0 = sw[0], w1 = sw[1], w2 = sw[2], w3 = sw[3], w4 = sw[4];
    for (int c = threadIdx.x; c < C_; c += 256){
        float o = pfrow[c] + mqrow[c];
        o += semb[0*C_ + c]*w0 + semb[1*C_ + c]*w1 + semb[2*C_ + c]*w2
           + semb[3*C_ + c]*w3 + semb[4*C_ + c]*w4;
        memo16[((size_t)b*10 + rowBase + nk)*C_ + c] = __float2half_rn(o);
    }
}

// ---------------- tgt init (from mainxT; fp32 + fp16) ----------------
__global__ void tgt_init_kernel(const float* __restrict__ mainxT, const float* __restrict__ mq,
                                const float* __restrict__ pe, float* __restrict__ tgt,
                                __half* __restrict__ tgt16){
    size_t i = (size_t)blockIdx.x*256 + threadIdx.x;
    int c = i % C_;
    size_t tc = i % ((size_t)T_*C_);
    float v = mainxT[i] + mq[c] + pe[tc];
    tgt[i] = v;
    tgt16[i] = __float2half_rn(v);
}

// ---------------- cross-attention (10 keys; half out) ----------------
__global__ void ca_attn_kernel(const float* __restrict__ q, const float* __restrict__ kv,
                               __half* __restrict__ out16){
    int bh = blockIdx.y, b = bh >> 3, h = bh & 7;
    int i = blockIdx.x*256 + threadIdx.x;
    __shared__ float Ks[10][96];
    __shared__ float Vsm[10][96];
    for (int idx = threadIdx.x; idx < 960; idx += 256){
        int j = idx / 96, d = idx % 96;
        Ks[j][d]  = kv[((size_t)b*10 + j)*(2*C_) + h*HD_ + d];
        Vsm[j][d] = kv[((size_t)b*10 + j)*(2*C_) + C_ + h*HD_ + d];
    }
    __syncthreads();
    const float* qr = q + ((size_t)b*T_ + i)*C_ + h*HD_;
    float s[10];
    #pragma unroll
    for (int j = 0; j < 10; j++) s[j] = 0.f;
    for (int d = 0; d < HD_; d++){
        float qd = qr[d];
        #pragma unroll
        for (int j = 0; j < 10; j++) s[j] += qd * Ks[j][d];
    }
    const float scale = 0.10206207261596577f;
    float mx = -1e30f;
    #pragma unroll
    for (int j = 0; j < 10; j++){ s[j] *= scale; mx = fmaxf(mx, s[j]); }
    float sum = 0.f;
    #pragma unroll
    for (int j = 0; j < 10; j++){ s[j] = expf(s[j] - mx); sum += s[j]; }
    float inv = 1.f / sum;
    #pragma unroll
    for (int j = 0; j < 10; j++) s[j] *= inv;
    __half* orow = out16 + ((size_t)b*T_ + i)*C_ + h*HD_;
    for (int d = 0; d < HD_; d++){
        float o = 0.f;
        #pragma unroll
        for (int j = 0; j < 10; j++) o += s[j] * Vsm[j][d];
        orow[d] = __float2half_rn(o);
    }
}

// ---------------- residual add + layernorm (fp32 + fp16 out) ----------------
__global__ void add_ln_kernel(float* __restrict__ tgt, __half* __restrict__ tgt16,
                              const float* __restrict__ resid,
                              const float* __restrict__ w, const float* __restrict__ bb){
    int row = blockIdx.x, t = threadIdx.x;
    float* p = tgt + (size_t)row*C_;
    __half* p16 = tgt16 + (size_t)row*C_;
    const float* r = resid + (size_t)row*C_;
    float v[3];
    float sum = 0.f;
    #pragma unroll
    for (int i = 0; i < 3; i++){ v[i] = p[t + i*256] + r[t + i*256]; sum += v[i]; }
    __shared__ float red[256];
    red[t] = sum; __syncthreads();
    for (int s = 128; s; s >>= 1){ if (t < s) red[t] += red[t + s]; __syncthreads(); }
    float m = red[0] * (1.f/768.f);
    __syncthreads();
    float s2 = 0.f;
    #pragma unroll
    for (int i = 0; i < 3; i++){ float d = v[i] - m; s2 += d*d; }
    red[t] = s2; __syncthreads();
    for (int s = 128; s; s >>= 1){ if (t < s) red[t] += red[t + s]; __syncthreads(); }
    float var = red[0] * (1.f/768.f);
    float rstd = rsqrtf(var + 1e-5f);
    #pragma unroll
    for (int i = 0; i < 3; i++){
        int c = t + i*256;
        float o = (v[i] - m)*rstd*w[c] + bb[c];
        p[c] = o;
        p16[c] = __float2half_rn(o);
    }
}

// ---------------- final transpose ----------------
__global__ void transpose_out_kernel(const float* __restrict__ tgt, float* __restrict__ out){
    __shared__ float tile[32][33];
    int c0 = blockIdx.x*32, t0 = blockIdx.y*32, b = blockIdx.z;
    for (int i = threadIdx.y; i < 32; i += 8)
        tile[i][threadIdx.x] = tgt[((size_t)b*T_ + t0 + i)*C_ + c0 + threadIdx.x];
    __syncthreads();
    for (int i = threadIdx.y; i < 32; i += 8)
        out[((size_t)b*C_ + c0 + i)*T_ + t0 + threadIdx.x] = tile[threadIdx.x][i];
}

// ---------------- launch ----------------
extern "C" void kernel_launch(void* const* d_in, const int* in_sizes, int n_in,
                              void* d_out, int out_size){
    const float* mainx      = (const float*)d_in[0];
    const float* others[2]  = {(const float*)d_in[1], (const float*)d_in[2]};
    const float* pe         = (const float*)d_in[3];
    const float* mq         = (const float*)d_in[4];
    const float* s_w1       = (const float*)d_in[5];
    const float* s_b1       = (const float*)d_in[6];
    const float* s_w2       = (const float*)d_in[7];
    const float* s_b2       = (const float*)d_in[8];
    const float* sa_in_w    = (const float*)d_in[9];
    const float* sa_in_b    = (const float*)d_in[10];
    const float* sa_out_w   = (const float*)d_in[11];
    const float* sa_out_b   = (const float*)d_in[12];
    const float* ca_in_w    = (const float*)d_in[13];
    const float* ca_in_b    = (const float*)d_in[14];
    const float* ca_out_w   = (const float*)d_in[15];
    const float* ca_out_b   = (const float*)d_in[16];
    const float* ff1_w      = (const float*)d_in[17];
    const float* ff1_b      = (const float*)d_in[18];
    const float* ff2_w      = (const float*)d_in[19];
    const float* ff2_b      = (const float*)d_in[20];
    const float* ln_w       = (const float*)d_in[21];
    const float* ln_b       = (const float*)d_in[22];
    const float* block_rand = (const float*)d_in[23];
    const float* around_rand= (const float*)d_in[24];
    float* out = (float*)d_out;

    float *pf0, *hid0, *mainxT, *coords, *score, *tgt, *tmp, *ffh, *memkv, *qb, *exsc;
    int *topidx, *top16;
    __half *qkv16, *pf16, *tgt16, *attn16, *memb16, *ffh16, *wt;
    cudaGetSymbolAddress((void**)&pf0,    g_pf);
    cudaGetSymbolAddress((void**)&hid0,   g_hid);
    cudaGetSymbolAddress((void**)&mainxT, g_mainxT);
    cudaGetSymbolAddress((void**)&coords, g_coords);
    cudaGetSymbolAddress((void**)&score,  g_score);
    cudaGetSymbolAddress((void**)&top16,  g_top16);
    cudaGetSymbolAddress((void**)&exsc,   g_exsc);
    cudaGetSymbolAddress((void**)&topidx, g_topidx);
    cudaGetSymbolAddress((void**)&tgt,    g_tgt);
    cudaGetSymbolAddress((void**)&tmp,    g_tmp);
    cudaGetSymbolAddress((void**)&ffh,    g_ffh);
    cudaGetSymbolAddress((void**)&memkv,  g_memkv);
    cudaGetSymbolAddress((void**)&qb,     g_q);
    cudaGetSymbolAddress((void**)&qkv16,  g_qkv16);
    cudaGetSymbolAddress((void**)&pf16,   g_pf16);
    cudaGetSymbolAddress((void**)&tgt16,  g_tgt16);
    cudaGetSymbolAddress((void**)&attn16, g_attn16);
    cudaGetSymbolAddress((void**)&memb16, g_memb16);
    cudaGetSymbolAddress((void**)&ffh16,  g_ffh16);
    cudaGetSymbolAddress((void**)&wt,     g_wt);

    size_t o = 0;
    __half* wtS = wt + o; o += (size_t)768*768;
    __half *wtSAin[L_], *wtSAout[L_], *wtCAin[L_], *wtCAout[L_], *wtFF1[L_], *wtFF2[L_];
    for (int l = 0; l < L_; l++){
        wtSAin[l]  = wt + o; o += (size_t)2304*768;
        wtSAout[l] = wt + o; o += (size_t)768*768;
        wtCAin[l]  = wt + o; o += (size_t)2304*768;
        wtCAout[l] = wt + o; o += (size_t)768*768;
        wtFF1[l]   = wt + o; o += (size_t)3072*768;
        wtFF2[l]   = wt + o; o += (size_t)768*3072;
    }

    float* pf1  = ffh;
    float* hid1 = ffh + (size_t)B_*NPTS*C_;

    cudaFuncSetAttribute(flash_attn_kernel, cudaFuncAttributeMaxDynamicSharedMemorySize, FA_SMEM_B);

    static cudaStream_t s_m[2] = {nullptr, nullptr};
    static cudaEvent_t  ev_start = nullptr, ev_m[2] = {nullptr, nullptr};
    if (s_m[0] == nullptr){
        cudaStreamCreateWithFlags(&s_m[0], cudaStreamNonBlocking);
        cudaStreamCreateWithFlags(&s_m[1], cudaStreamNonBlocking);
        cudaEventCreateWithFlags(&ev_start, cudaEventDisableTiming);
        cudaEventCreateWithFlags(&ev_m[0], cudaEventDisableTiming);
        cudaEventCreateWithFlags(&ev_m[1], cudaEventDisableTiming);
    }

    // pre-fork work side streams depend on: score weight + mainxT
    transpose_w(s_w1, wtS, 768, 768, 0);
    {
        dim3 g(C_/32, T_/32, B_); dim3 bl(32, 8);
        transpose_in_kernel<<<g, bl>>>(mainx, mainxT);
    }
    cudaEventRecord(ev_start, 0);

    // ---- fork: modality pipelines ----
    float*  pfs[2]   = {pf0, pf1};
    float*  hids[2]  = {hid0, hid1};
    for (int i = 0; i < 2; i++){
        cudaStream_t st = s_m[i];
        cudaStreamWaitEvent(st, ev_start, 0);
        float*  pf_i   = pfs[i];
        __half* pf16_i = pf16 + (size_t)i*B_*NPTS*C_;
        float*  hid_i  = hids[i];
        float* coords_i = coords + (size_t)i*B_*NPTS*2;
        float* score_i  = score  + (size_t)i*B_*NPTS;
        int*   top16_i  = top16  + i*B_*NCAND;
        float* exsc_i   = exsc   + i*B_*NCAND;
        int*   topidx_i = topidx + i*B_*TOPK_;
        {
            dim3 g(C_/32, T_/32, B_); dim3 bl(32, 8);
            transpose_in_kernel<<<g, bl, 0, st>>>(others[i], hid_i);
        }
        sample_kernel<<<B_*NPTS/16, 256, 0, st>>>(hid_i, block_rand + (size_t)i*B_*32*32*2*2,
                                                  pf_i, pf16_i, coords_i);
        zero_score_kernel<<<(B_*NPTS + 255)/256, 256, 0, st>>>(score_i);
        h_gemm<2>(pf16_i, wtS, s_b1, nullptr, nullptr, s_w2, score_i,
                  B_*NPTS, C_, C_, C_, C_, 0, st);
        topk_kernel<<<B_, 256, 0, st>>>(score_i, top16_i, NCAND);
        rescore_kernel<<<B_*NCAND, 256, 0, st>>>(pf_i, s_w1, s_b1, s_w2, top16_i, exsc_i);
        final_top5_kernel<<<B_, 32, 0, st>>>(exsc_i, top16_i, topidx_i);
        soft_align_kernel<<<B_*TOPK_, 256, 0, st>>>(mainxT, pe,
                                                    around_rand + (size_t)i*B_*AROUND_*TOPK_*2,
                                                    mq + (size_t)(i+1)*C_,
                                                    pf_i, coords_i, topidx_i, memb16, i*TOPK_);
        cudaEventRecord(ev_m[i], st);
    }

    // ---- decoder weight transposes + prefix on main stream ----
    for (int l = 0; l < L_; l++){
        transpose_w(sa_in_w  + (size_t)l*C_*3*C_, wtSAin[l],  768, 2304, 0);
        transpose_w(sa_out_w + (size_t)l*C_*C_,   wtSAout[l], 768, 768,  0);
        transpose_w(ca_in_w  + (size_t)l*C_*3*C_, wtCAin[l],  768, 2304, 0);
        transpose_w(ca_out_w + (size_t)l*C_*C_,   wtCAout[l], 768, 768,  0);
        transpose_w(ff1_w    + (size_t)l*C_*FF_,  wtFF1[l],   768, 3072, 0);
        transpose_w(ff2_w    + (size_t)l*FF_*C_,  wtFF2[l],   3072, 768, 0);
    }
    tgt_init_kernel<<<(int)(((size_t)B_*T_*C_ + 255)/256), 256>>>(mainxT, mq, pe, tgt, tgt16);

    // layer 0 SA block + CA-q (no memb dependency)
    h_gemm<3>(tgt16, wtSAin[0], sa_in_b, nullptr, qkv16, nullptr, nullptr,
              B_*T_, 3*C_, C_, C_, C_, 3*C_, 0);
    { dim3 g(T_/128, B_*NHEAD_); flash_attn_kernel<<<g, 256, FA_SMEM_B>>>(qkv16, attn16); }
    h_gemm<0>(attn16, wtSAout[0], sa_out_b, tmp, nullptr, nullptr, nullptr,
              B_*T_, C_, C_, C_, C_, C_, 0);
    add_ln_kernel<<<B_*T_, 256>>>(tgt, tgt16, tmp, ln_w, ln_b);
    h_gemm<0>(tgt16, wtCAin[0], ca_in_b, qb, nullptr, nullptr, nullptr,
              B_*T_, C_, C_, C_, C_, C_, 0);

    // ---- join ----
    cudaStreamWaitEvent(0, ev_m[0], 0);
    cudaStreamWaitEvent(0, ev_m[1], 0);

    for (int l = 0; l < L_; l++){
        if (l > 0){
            h_gemm<3>(tgt16, wtSAin[l], sa_in_b + (size_t)l*3*C_, nullptr, qkv16, nullptr, nullptr,
                      B_*T_, 3*C_, C_, C_, C_, 3*C_, 0);
            { dim3 g(T_/128, B_*NHEAD_); flash_attn_kernel<<<g, 256, FA_SMEM_B>>>(qkv16, attn16); }
            h_gemm<0>(attn16, wtSAout[l], sa_out_b + (size_t)l*C_, tmp, nullptr, nullptr, nullptr,
                      B_*T_, C_, C_, C_, C_, C_, 0);
            add_ln_kernel<<<B_*T_, 256>>>(tgt, tgt16, tmp, ln_w + (size_t)(l*3+0)*C_, ln_b + (size_t)(l*3+0)*C_);
            h_gemm<0>(tgt16, wtCAin[l], ca_in_b + (size_t)l*3*C_, qb, nullptr, nullptr, nullptr,
                      B_*T_, C_, C_, C_, C_, C_, 0);
        }
        h_gemm<0>(memb16, wtCAin[l] + (size_t)768*C_, ca_in_b + (size_t)l*3*C_ + C_, memkv,
                  nullptr, nullptr, nullptr, B_*10, 2*C_, C_, C_, C_, 2*C_, 0);
        { dim3 g(T_/256, B_*NHEAD_); ca_attn_kernel<<<g, 256>>>(qb, memkv, attn16); }
        h_gemm<0>(attn16, wtCAout[l], ca_out_b + (size_t)l*C_, tmp, nullptr, nullptr, nullptr,
                  B_*T_, C_, C_, C_, C_, C_, 0);
        add_ln_kernel<<<B_*T_, 256>>>(tgt, tgt16, tmp, ln_w + (size_t)(l*3+1)*C_, ln_b + (size_t)(l*3+1)*C_);

        h_gemm<1>(tgt16, wtFF1[l], ff1_b + (size_t)l*FF_, nullptr, ffh16, nullptr, nullptr,
                  B_*T_, FF_, C_, C_, C_, FF_, 0);
        h_gemm<0>(ffh16, wtFF2[l], ff2_b + (size_t)l*C_, tmp, nullptr, nullptr, nullptr,
                  B_*T_, C_, FF_, FF_, FF_, C_, 0);
        add_ln_kernel<<<B_*T_, 256>>>(tgt, tgt16, tmp, ln_w + (size_t)(l*3+2)*C_, ln_b + (size_t)(l*3+2)*C_);
    }

    {
        dim3 g(C_/32, T_/32, B_); dim3 bl(32, 8);
        transpose_out_kernel<<<g, bl>>>(tgt, out);
    }
}

// round 14
// speedup vs baseline: 1.0996x; 1.0114x over previous
#include <cuda_runtime.h>
#include <cuda_fp16.h>
#include <math.h>
#include <stdint.h>

// ---------------- constants ----------------
#define B_   8
#define C_   768
#define T_   1024
#define L_   2
#define FF_  3072
#define NPTS 2048
#define TOPK_ 5
#define NCAND 16
#define AROUND_ 5
#define NHEAD_ 8
#define HD_  96

// ---------------- scratch ----------------
__device__ float g_pf    [(size_t)B_*NPTS*C_];
__device__ float g_hid   [(size_t)B_*NPTS*C_];
__device__ float g_mainxT[(size_t)B_*T_*C_];
__device__ float g_coords[2*(size_t)B_*NPTS*2];
__device__ float g_score [2*(size_t)B_*NPTS];
__device__ int   g_top16 [2*B_*NCAND];
__device__ float g_exsc  [2*B_*NCAND];
__device__ int   g_topidx[2*B_*TOPK_];
__device__ float g_tgt   [(size_t)B_*T_*C_];
__device__ float g_tmp   [(size_t)B_*T_*C_];
__device__ float g_ffh   [(size_t)B_*T_*FF_];      // phase-A scratch: pf1 + xT1
__device__ float g_memkv [(size_t)B_*10*2*C_];
__device__ float g_q     [(size_t)B_*T_*C_];
// fp16 mirrors / weights
__device__ __align__(256) __half g_qkv16 [(size_t)B_*T_*3*C_];
__device__ __align__(256) __half g_pf16  [2*(size_t)B_*NPTS*C_];
__device__ __align__(256) __half g_tgt16 [(size_t)B_*T_*C_];
__device__ __align__(256) __half g_attn16[(size_t)B_*T_*C_];
__device__ __align__(256) __half g_memb16[(size_t)B_*10*C_];
__device__ __align__(256) __half g_ffh16 [(size_t)B_*T_*FF_];
__device__ __align__(256) __half g_wt    [19464192];

// ---------------- fp16 mma (m16n8k16) ----------------
__device__ __forceinline__ void mma16(float* d, const uint32_t* a, const uint32_t* b){
    asm volatile("mma.sync.aligned.m16n8k16.row.col.f32.f16.f16.f32 "
        "{%0,%1,%2,%3},{%4,%5,%6,%7},{%8,%9},{%0,%1,%2,%3};\n"
        : "+f"(d[0]), "+f"(d[1]), "+f"(d[2]), "+f"(d[3])
        : "r"(a[0]), "r"(a[1]), "r"(a[2]), "r"(a[3]), "r"(b[0]), "r"(b[1]));
}

// ---------------- fp16 GEMM: 128 threads, 2x2 warps, 64x64 warp tiles ----------------
// MODE 0: fp32 C out. MODE 1: relu + half C16 out. MODE 2: score. MODE 3: half C16, no relu.
#define H_STRIDE_W 20
#define H_STAGE_B  20480
#define H_SMEM_B   (4*H_STAGE_B)

template<int MODE>
__global__ __launch_bounds__(128, 2)
void h_gemm_kernel(const __half* __restrict__ A, const __half* __restrict__ WT,
                   const float* __restrict__ bias, float* __restrict__ C,
                   __half* __restrict__ C16, const float* __restrict__ w2,
                   float* __restrict__ score,
                   int M, int N, int K, int lda, int ldb, int ldc)
{
    extern __shared__ char smraw[];

    int tid = threadIdx.x, lane = tid & 31, warp = tid >> 5;
    int gid = lane >> 2, tig = lane & 3;
    int wm = warp >> 1, wn = warp & 1;
    int row0 = blockIdx.y * 128, col0 = blockIdx.x * 128;

    float acc[4][8][4];
    #pragma unroll
    for (int i = 0; i < 4; i++)
        #pragma unroll
        for (int j = 0; j < 8; j++)
            #pragma unroll
            for (int r = 0; r < 4; r++) acc[i][j][r] = 0.f;

    // copy coords: 128 threads x 4 iters cover 512 x 16B chunks per operand
    int crow[4], cseg[4], assz[4], acar[4];
    #pragma unroll
    for (int i = 0; i < 4; i++){
        int idx = tid + i*128;
        crow[i] = idx >> 2; cseg[i] = idx & 3;
        assz[i] = (row0 + crow[i] < M) ? 16 : 0;
        acar[i] = assz[i] ? row0 + crow[i] : 0;
    }

    auto issue_stage = [&](int stage, int k0){
        char* Ab = smraw + stage*H_STAGE_B;
        char* Bb = Ab + 10240;
        #pragma unroll
        for (int i = 0; i < 4; i++){
            uint32_t d = (uint32_t)__cvta_generic_to_shared(Ab + crow[i]*80 + cseg[i]*16);
            const __half* s = A + (size_t)acar[i]*lda + k0 + cseg[i]*8;
            asm volatile("cp.async.cg.shared.global [%0], [%1], 16, %2;\n" :: "r"(d), "l"(s), "r"(assz[i]));
        }
        #pragma unroll
        for (int i = 0; i < 4; i++){
            uint32_t d = (uint32_t)__cvta_generic_to_shared(Bb + crow[i]*80 + cseg[i]*16);
            const __half* s = WT + (size_t)(col0 + crow[i])*ldb + k0 + cseg[i]*8;
            asm volatile("cp.async.cg.shared.global [%0], [%1], 16;\n" :: "r"(d), "l"(s));
        }
        asm volatile("cp.async.commit_group;\n" ::: "memory");
    };

    auto compute = [&](int stage){
        const uint32_t* As = (const uint32_t*)(smraw + stage*H_STAGE_B);
        const uint32_t* Bs = As + 128*H_STRIDE_W;
        #pragma unroll
        for (int kk = 0; kk < 2; kk++){
            int kw = kk*8 + tig;
            uint32_t af[4][4], bf[8][2];
            #pragma unroll
            for (int ma = 0; ma < 4; ma++){
                int m = wm*64 + ma*16 + gid;
                af[ma][0] = As[m*H_STRIDE_W + kw];
                af[ma][1] = As[(m+8)*H_STRIDE_W + kw];
                af[ma][2] = As[m*H_STRIDE_W + kw + 4];
                af[ma][3] = As[(m+8)*H_STRIDE_W + kw + 4];
            }
            #pragma unroll
            for (int na = 0; na < 8; na++){
                int n = wn*64 + na*8 + gid;
                bf[na][0] = Bs[n*H_STRIDE_W + kw];
                bf[na][1] = Bs[n*H_STRIDE_W + kw + 4];
            }
            #pragma unroll
            for (int ma = 0; ma < 4; ma++)
                #pragma unroll
                for (int na = 0; na < 8; na++)
                    mma16(acc[ma][na], af[ma], bf[na]);
        }
    };

    int nc = K / 32;
    #pragma unroll
    for (int s = 0; s < 3; s++) issue_stage(s, s*32);
    for (int it = 0; it < nc; it++){
        asm volatile("cp.async.wait_group 2;\n" ::: "memory");
        __syncthreads();
        int nxt = it + 3;
        if (nxt < nc) issue_stage(nxt & 3, nxt*32);
        else asm volatile("cp.async.commit_group;\n" ::: "memory");
        compute(it & 3);
    }

    #pragma unroll
    for (int ma = 0; ma < 4; ma++){
        int r0 = row0 + wm*64 + ma*16 + gid;
        float s0 = 0.f, s1 = 0.f;
        #pragma unroll
        for (int na = 0; na < 8; na++){
            int c = col0 + wn*64 + na*8 + 2*tig;
            float b0 = bias ? bias[c] : 0.f;
            float b1 = bias ? bias[c+1] : 0.f;
            float x0 = acc[ma][na][0] + b0;
            float x1 = acc[ma][na][1] + b1;
            float x2 = acc[ma][na][2] + b0;
            float x3 = acc[ma][na][3] + b1;
            if (MODE == 1 || MODE == 2){
                x0 = fmaxf(x0, 0.f); x1 = fmaxf(x1, 0.f);
                x2 = fmaxf(x2, 0.f); x3 = fmaxf(x3, 0.f);
            }
            if (MODE == 2){
                float w0 = w2[c], w1 = w2[c+1];
                s0 += x0*w0 + x1*w1;
                s1 += x2*w0 + x3*w1;
            } else if (MODE == 1 || MODE == 3){
                if (r0 < M)     *(__half2*)&C16[(size_t)r0*ldc + c]     = __floats2half2_rn(x0, x1);
                if (r0 + 8 < M) *(__half2*)&C16[(size_t)(r0+8)*ldc + c] = __floats2half2_rn(x2, x3);
            } else {
                if (r0 < M){ float2 o = make_float2(x0, x1); *(float2*)&C[(size_t)r0*ldc + c] = o; }
                if (r0 + 8 < M){ float2 o = make_float2(x2, x3); *(float2*)&C[(size_t)(r0+8)*ldc + c] = o; }
            }
        }
        if (MODE == 2){
            s0 += __shfl_xor_sync(0xffffffffu, s0, 1);
            s0 += __shfl_xor_sync(0xffffffffu, s0, 2);
            s1 += __shfl_xor_sync(0xffffffffu, s1, 1);
            s1 += __shfl_xor_sync(0xffffffffu, s1, 2);
            if (tig == 0){
                if (r0 < M)     atomicAdd(&score[r0], s0);
                if (r0 + 8 < M) atomicAdd(&score[r0 + 8], s1);
            }
        }
    }
}

template<int MODE>
static void h_gemm(const __half* A, const __half* WT, const float* bias, float* C,
                   __half* C16, const float* w2, float* score,
                   int M, int N, int K, int lda, int ldb, int ldc, cudaStream_t st){
    cudaFuncSetAttribute(h_gemm_kernel<MODE>, cudaFuncAttributeMaxDynamicSharedMemorySize, H_SMEM_B);
    dim3 grid(N/128, (M + 127)/128);
    h_gemm_kernel<MODE><<<grid, 128, H_SMEM_B, st>>>(A, WT, bias, C, C16, w2, score, M, N, K, lda, ldb, ldc);
}

// ---------------- weight transpose+convert ----------------
__global__ void transpose_w_kernel(const float* __restrict__ W, __half* __restrict__ WT,
                                   int K, int N){
    __shared__ float tile[32][33];
    int n0 = blockIdx.x*32, k0 = blockIdx.y*32;
    for (int i = threadIdx.y; i < 32; i += 8)
        tile[i][threadIdx.x] = W[(size_t)(k0 + i)*N + n0 + threadIdx.x];
    __syncthreads();
    for (int i = threadIdx.y; i < 32; i += 8)
        WT[(size_t)(n0 + i)*K + k0 + threadIdx.x] = __float2half_rn(tile[threadIdx.x][i]);
}
static void transpose_w(const float* W, __half* WT, int K, int N, cudaStream_t st){
    dim3 g(N/32, K/32); dim3 bl(32, 8);
    transpose_w_kernel<<<g, bl, 0, st>>>(W, WT, K, N);
}

// ---------------- flash attention (fp16 mma, online softmax) ----------------
#define FA_KS_STR 136
#define FA_VS_STR 104
#define FA_SMEM_B ((48*136 + 64*104 + 64*136)*4)
#define FA_LOG2E 1.4426950408889634f

__global__ __launch_bounds__(256, 1)
void flash_attn_kernel(const __half* __restrict__ qkv, __half* __restrict__ out16){
    extern __shared__ uint32_t sm32[];
    uint32_t* Ks = sm32;
    uint32_t* Vs = Ks + 48*FA_KS_STR;
    uint32_t* Ps = Vs + 64*FA_VS_STR;

    int qt = blockIdx.x, bh = blockIdx.y, b = bh >> 3, h = bh & 7;
    int tid = threadIdx.x, lane = tid & 31, warp = tid >> 5;
    int gid = lane >> 2, tig = lane & 3;
    int m0 = warp * 16;
    int q0 = qt * 128;
    const float iscale = 0.10206207261596577f;

    uint32_t qf[6][4];
    {
        const __half* Qa = qkv + (size_t)(b*T_ + q0 + m0 + gid)*(3*C_) + h*HD_;
        const __half* Qb = Qa + 8*(3*C_);
        #pragma unroll
        for (int kk = 0; kk < 6; kk++){
            qf[kk][0] = *(const uint32_t*)&Qa[(kk*8 + tig)*2];
            qf[kk][1] = *(const uint32_t*)&Qb[(kk*8 + tig)*2];
            qf[kk][2] = *(const uint32_t*)&Qa[(kk*8 + tig + 4)*2];
            qf[kk][3] = *(const uint32_t*)&Qb[(kk*8 + tig + 4)*2];
        }
    }

    float oacc[12][4];
    #pragma unroll
    for (int i = 0; i < 12; i++)
        #pragma unroll
        for (int j = 0; j < 4; j++) oacc[i][j] = 0.f;
    float mrow0 = -1e30f, mrow1 = -1e30f, lrow0 = 0.f, lrow1 = 0.f;

    for (int kt = 0; kt < 8; kt++){
        __syncthreads();
        {
            const __half* Kb = qkv + (size_t)(b*T_ + kt*128)*(3*C_) + C_ + h*HD_;
            const __half* Vb = Kb + C_;
            for (int idx = tid; idx < 128*48; idx += 256){
                int r = idx / 48, d = idx % 48;
                Ks[d*FA_KS_STR + r] = *(const uint32_t*)&Kb[(size_t)r*(3*C_) + d*2];
            }
            for (int idx = tid; idx < 64*96; idx += 256){
                int p = idx / 96, n = idx % 96;
                __half lo = Vb[(size_t)(2*p)*(3*C_) + n];
                __half hi = Vb[(size_t)(2*p + 1)*(3*C_) + n];
                __half2 hv = __halves2half2(lo, hi);
                Vs[p*FA_VS_STR + n] = *(const uint32_t*)&hv;
            }
        }
        __syncthreads();

        float sacc[16][4];
        #pragma unroll
        for (int nf = 0; nf < 16; nf++)
            #pragma unroll
            for (int j = 0; j < 4; j++) sacc[nf][j] = 0.f;
        #pragma unroll
        for (int kk = 0; kk < 6; kk++){
            int k1 = (kk*8 + tig)*FA_KS_STR, k2 = (kk*8 + tig + 4)*FA_KS_STR;
            #pragma unroll
            for (int nf = 0; nf < 16; nf++){
                uint32_t bfr[2] = { Ks[k1 + nf*8 + gid], Ks[k2 + nf*8 + gid] };
                mma16(sacc[nf], qf[kk], bfr);
            }
        }
        #pragma unroll
        for (int nf = 0; nf < 16; nf++){
            sacc[nf][0] *= iscale; sacc[nf][1] *= iscale;
            sacc[nf][2] *= iscale; sacc[nf][3] *= iscale;
        }

        float rm0 = -1e30f, rm1 = -1e30f;
        #pragma unroll
        for (int nf = 0; nf < 16; nf++){
            rm0 = fmaxf(rm0, fmaxf(sacc[nf][0], sacc[nf][1]));
            rm1 = fmaxf(rm1, fmaxf(sacc[nf][2], sacc[nf][3]));
        }
        rm0 = fmaxf(rm0, __shfl_xor_sync(0xffffffffu, rm0, 1));
        rm0 = fmaxf(rm0, __shfl_xor_sync(0xffffffffu, rm0, 2));
        rm1 = fmaxf(rm1, __shfl_xor_sync(0xffffffffu, rm1, 1));
        rm1 = fmaxf(rm1, __shfl_xor_sync(0xffffffffu, rm1, 2));
        float mn0 = fmaxf(mrow0, rm0), mn1 = fmaxf(mrow1, rm1);
        float al0 = exp2f((mrow0 - mn0)*FA_LOG2E);
        float al1 = exp2f((mrow1 - mn1)*FA_LOG2E);
        mrow0 = mn0; mrow1 = mn1;
        float rs0 = 0.f, rs1 = 0.f;
        #pragma unroll
        for (int nf = 0; nf < 16; nf++){
            float p0 = exp2f((sacc[nf][0] - mn0)*FA_LOG2E);
            float p1 = exp2f((sacc[nf][1] - mn0)*FA_LOG2E);
            float p2 = exp2f((sacc[nf][2] - mn1)*FA_LOG2E);
            float p3 = exp2f((sacc[nf][3] - mn1)*FA_LOG2E);
            sacc[nf][0] = p0; sacc[nf][1] = p1; sacc[nf][2] = p2; sacc[nf][3] = p3;
            rs0 += p0 + p1; rs1 += p2 + p3;
        }
        rs0 += __shfl_xor_sync(0xffffffffu, rs0, 1);
        rs0 += __shfl_xor_sync(0xffffffffu, rs0, 2);
        rs1 += __shfl_xor_sync(0xffffffffu, rs1, 1);
        rs1 += __shfl_xor_sync(0xffffffffu, rs1, 2);
        lrow0 = lrow0*al0 + rs0;
        lrow1 = lrow1*al1 + rs1;
        #pragma unroll
        for (int nf = 0; nf < 12; nf++){
            oacc[nf][0] *= al0; oacc[nf][1] *= al0;
            oacc[nf][2] *= al1; oacc[nf][3] *= al1;
        }

        #pragma unroll
        for (int nf = 0; nf < 16; nf++){
            int cp = nf*4 + tig;
            __half2 h0 = __floats2half2_rn(sacc[nf][0], sacc[nf][1]);
            __half2 h1 = __floats2half2_rn(sacc[nf][2], sacc[nf][3]);
            Ps[cp*FA_KS_STR + m0 + gid]     = *(const uint32_t*)&h0;
            Ps[cp*FA_KS_STR + m0 + gid + 8] = *(const uint32_t*)&h1;
        }
        __syncwarp();

        #pragma unroll
        for (int kk = 0; kk < 8; kk++){
            int k1 = (kk*8 + tig)*FA_KS_STR, k2 = (kk*8 + tig + 4)*FA_KS_STR;
            uint32_t pa[4] = { Ps[k1 + m0 + gid], Ps[k1 + m0 + gid + 8],
                               Ps[k2 + m0 + gid], Ps[k2 + m0 + gid + 8] };
            int v1 = (kk*8 + tig)*FA_VS_STR, v2 = (kk*8 + tig + 4)*FA_VS_STR;
            #pragma unroll
            for (int nf = 0; nf < 12; nf++){
                uint32_t vb2[2] = { Vs[v1 + nf*8 + gid], Vs[v2 + nf*8 + gid] };
                mma16(oacc[nf], pa, vb2);
            }
        }
    }

    float inv0 = 1.f / lrow0, inv1 = 1.f / lrow1;
    size_t r0 = (size_t)(b*T_ + q0 + m0 + gid);
    #pragma unroll
    for (int nf = 0; nf < 12; nf++){
        int col = h*HD_ + nf*8 + 2*tig;
        *(__half2*)&out16[r0*C_ + col]       = __floats2half2_rn(oacc[nf][0]*inv0, oacc[nf][1]*inv0);
        *(__half2*)&out16[(r0 + 8)*C_ + col] = __floats2half2_rn(oacc[nf][2]*inv1, oacc[nf][3]*inv1);
    }
}

// ---------------- transpose x [B,C,T] -> xT [B,T,C] ----------------
__global__ void transpose_in_kernel(const float* __restrict__ x, float* __restrict__ xT){
    __shared__ float tile[32][33];
    int c0 = blockIdx.x*32, t0 = blockIdx.y*32, b = blockIdx.z;
    for (int i = threadIdx.y; i < 32; i += 8)
        tile[i][threadIdx.x] = x[((size_t)b*C_ + c0 + i)*T_ + t0 + threadIdx.x];
    __syncthreads();
    for (int i = threadIdx.y; i < 32; i += 8)
        xT[((size_t)b*T_ + t0 + i)*C_ + c0 + threadIdx.x] = tile[threadIdx.x][i];
}

// ---------------- blockwise sampling (fp32 + fp16 out) ----------------
__global__ void sample_kernel(const float* __restrict__ xT, const float* __restrict__ brand,
                              float* __restrict__ pf, __half* __restrict__ pf16,
                              float* __restrict__ coords){
    int p0 = blockIdx.x * 16;
    __shared__ int   sidx[16][4];
    __shared__ float swt [16][4];
    int tid = threadIdx.x;
    if (tid < 16){
        int bn = p0 + tid;
        int b  = bn >> 11;
        int n  = bn & 2047;
        int k  = n & 1;
        int pw = (n >> 1) & 31;
        int ph = n >> 6;
        const float bs = 0.0625f;
        const float* br = brand + ((((size_t)b*32 + ph)*32 + pw)*2 + k)*2;
        float gx = br[0]*bs + (-1.0f + ph*bs);
        float gy = br[1]*bs + (-1.0f + pw*bs);
        coords[(size_t)bn*2]     = gx;
        coords[(size_t)bn*2 + 1] = gy;
        float ix = ((gx + 1.0f)*32.0f - 1.0f)*0.5f;
        float iy = ((gy + 1.0f)*32.0f - 1.0f)*0.5f;
        float x0f = floorf(ix), y0f = floorf(iy);
        int x0 = (int)x0f, y0 = (int)y0f;
        float wx1 = ix - x0f, wy1 = iy - y0f;
        float wxs[2] = {1.f - wx1, wx1};
        float wys[2] = {1.f - wy1, wy1};
        #pragma unroll
        for (int j = 0; j < 4; j++){
            int xi = x0 + (j & 1), yi = y0 + (j >> 1);
            bool v = (xi >= 0) & (xi < 32) & (yi >= 0) & (yi < 32);
            sidx[tid][j] = v ? (yi*32 + xi) : 0;
            swt [tid][j] = v ? (wxs[j & 1]*wys[j >> 1]) : 0.f;
        }
    }
    __syncthreads();
    int b = (p0 >> 11);
    const float* base = xT + (size_t)b*T_*C_;
    for (int pt = 0; pt < 16; pt++){
        const float* r0 = base + (size_t)sidx[pt][0]*C_;
        const float* r1 = base + (size_t)sidx[pt][1]*C_;
        const float* r2 = base + (size_t)sidx[pt][2]*C_;
        const float* r3 = base + (size_t)sidx[pt][3]*C_;
        float w0 = swt[pt][0], w1 = swt[pt][1], w2 = swt[pt][2], w3 = swt[pt][3];
        float* dst = pf + (size_t)(p0 + pt)*C_;
        __half* dst16 = pf16 + (size_t)(p0 + pt)*C_;
        for (int c = tid; c < C_; c += 256){
            float v = r0[c]*w0 + r1[c]*w1 + r2[c]*w2 + r3[c]*w3;
            dst[c] = v;
            dst16[c] = __float2half_rn(v);
        }
    }
}

// ---------------- zero score ----------------
__global__ void zero_score_kernel(float* __restrict__ score){
    int i = blockIdx.x*256 + threadIdx.x;
    if (i < B_*NPTS) score[i] = 0.f;
}

// ---------------- top-K ----------------
__global__ void topk_kernel(const float* __restrict__ score, int* __restrict__ topidx, int K){
    int b = blockIdx.x;
    __shared__ float sv[2048];
    __shared__ float rv[256];
    __shared__ int   ri[256];
    for (int j = threadIdx.x; j < 2048; j += 256) sv[j] = score[(size_t)b*2048 + j];
    __syncthreads();
    for (int t = 0; t < K; t++){
        float bv = -1e30f; int bi = 0x7fffffff;
        for (int j = threadIdx.x; j < 2048; j += 256){
            float v = sv[j];
            if (v > bv){ bv = v; bi = j; }
        }
        rv[threadIdx.x] = bv; ri[threadIdx.x] = bi;
        __syncthreads();
        for (int s = 128; s; s >>= 1){
            if (threadIdx.x < s){
                float v2 = rv[threadIdx.x + s]; int i2 = ri[threadIdx.x + s];
                if (v2 > rv[threadIdx.x] || (v2 == rv[threadIdx.x] && i2 < ri[threadIdx.x])){
                    rv[threadIdx.x] = v2; ri[threadIdx.x] = i2;
                }
            }
            __syncthreads();
        }
        if (threadIdx.x == 0){
            topidx[b*K + t] = ri[0];
            sv[ri[0]] = -1e30f;
        }
        __syncthreads();
    }
}

// ---------------- exact fp32 rescore ----------------
__global__ __launch_bounds__(256)
void rescore_kernel(const float* __restrict__ pf, const float* __restrict__ W1,
                    const float* __restrict__ b1, const float* __restrict__ w2,
                    const int* __restrict__ cand, float* __restrict__ exsc){
    int b = blockIdx.x >> 4, c = blockIdx.x & 15;
    int idx = cand[b*NCAND + c];
    __shared__ float spf[C_];
    int tid = threadIdx.x;
    for (int i = tid; i < C_; i += 256) spf[i] = pf[((size_t)b*NPTS + idx)*C_ + i];
    __syncthreads();
    float a0 = b1[tid], a1 = b1[tid+256], a2 = b1[tid+512];
    for (int k = 0; k < C_; k++){
        float v = spf[k];
        const float* w = W1 + (size_t)k*C_;
        a0 += v * w[tid];
        a1 += v * w[tid+256];
        a2 += v * w[tid+512];
    }
    float p = fmaxf(a0,0.f)*w2[tid] + fmaxf(a1,0.f)*w2[tid+256] + fmaxf(a2,0.f)*w2[tid+512];
    #pragma unroll
    for (int o = 16; o; o >>= 1) p += __shfl_down_sync(0xffffffffu, p, o);
    __shared__ float red[8];
    if ((tid & 31) == 0) red[tid >> 5] = p;
    __syncthreads();
    if (tid == 0){
        float s = 0.f;
        #pragma unroll
        for (int i = 0; i < 8; i++) s += red[i];
        exsc[b*NCAND + c] = s;
    }
}

// ---------------- final exact top-5 ----------------
__global__ void final_top5_kernel(const float* __restrict__ exsc, const int* __restrict__ cand,
                                  int* __restrict__ topidx){
    int b = blockIdx.x;
    if (threadIdx.x == 0){
        float s[NCAND]; int id[NCAND];
        for (int i = 0; i < NCAND; i++){ s[i] = exsc[b*NCAND + i]; id[i] = cand[b*NCAND + i]; }
        for (int t = 0; t < TOPK_; t++){
            int bi = 0;
            float bv = -1e30f; int bid = 0x7fffffff;
            for (int i = 0; i < NCAND; i++){
                if (s[i] > bv || (s[i] == bv && id[i] < bid)){ bv = s[i]; bid = id[i]; bi = i; }
            }
            topidx[b*TOPK_ + t] = id[bi];
            s[bi] = -1e30f;
        }
    }
}

// ---------------- soft_align (coalesced via mainxT; fp16 mem rows) ----------------
__global__ void soft_align_kernel(const float* __restrict__ mainxT, const float* __restrict__ pe,
                                  const float* __restrict__ arand, const float* __restrict__ mqrow,
                                  const float* __restrict__ pf, const float* __restrict__ coords,
                                  const int* __restrict__ topidx, __half* __restrict__ memo16, int rowBase){
    int b  = blockIdx.x / TOPK_;
    int nk = blockIdx.x % TOPK_;
    int idx = topidx[b*TOPK_ + nk];
    float px = coords[((size_t)b*NPTS + idx)*2 + 0];
    float py = coords[((size_t)b*NPTS + idx)*2 + 1];
    __shared__ float semb[AROUND_*C_];
    __shared__ float red[256];
    __shared__ float res[11];
    __shared__ float sw[AROUND_];

    int   aidx[AROUND_][4];
    float awt [AROUND_][4];
    #pragma unroll
    for (int a = 0; a < AROUND_; a++){
        const float* ar = arand + (((size_t)b*AROUND_ + a)*TOPK_ + nk)*2;
        float g0 = px + (ar[0]*2.f - 0.5f)*0.2f;
        float g1 = py + (ar[1]*2.f - 0.5f)*0.2f;
        g0 = fminf(fmaxf(g0, -1.f), 1.f);
        g1 = fminf(fmaxf(g1, -1.f), 1.f);
        float ix = ((g0 + 1.f)*32.f - 1.f)*0.5f;
        float iy = ((g1 + 1.f)*32.f - 1.f)*0.5f;
        float x0f = floorf(ix), y0f = floorf(iy);
        int x0 = (int)x0f, y0 = (int)y0f;
        float wx1 = ix - x0f, wy1 = iy - y0f;
        float wxs[2] = {1.f - wx1, wx1};
        float wys[2] = {1.f - wy1, wy1};
        #pragma unroll
        for (int j = 0; j < 4; j++){
            int xi = x0 + (j & 1), yi = y0 + (j >> 1);
            bool v = (xi >= 0) & (xi < 32) & (yi >= 0) & (yi < 32);
            aidx[a][j] = v ? (yi*32 + xi) : 0;
            awt [a][j] = v ? (wxs[j & 1]*wys[j >> 1]) : 0.f;
        }
    }
    const float* xbase = mainxT + (size_t)b*T_*C_;
    const float* pfrow = pf + ((size_t)b*NPTS + idx)*C_;
    float rep2 = 0.f, num[AROUND_], af2[AROUND_];
    #pragma unroll
    for (int a = 0; a < AROUND_; a++){ num[a] = 0.f; af2[a] = 0.f; }
    for (int c = threadIdx.x; c < C_; c += 256){
        float r = pfrow[c];
        rep2 += r*r;
        #pragma unroll
        for (int a = 0; a < AROUND_; a++){
            float af = awt[a][0]*xbase[(size_t)aidx[a][0]*C_ + c]
                     + awt[a][1]*xbase[(size_t)aidx[a][1]*C_ + c]
                     + awt[a][2]*xbase[(size_t)aidx[a][2]*C_ + c]
                     + awt[a][3]*xbase[(size_t)aidx[a][3]*C_ + c];
            num[a] += r*af;
            af2[a] += af*af;
            semb[a*C_ + c] = awt[a][0]*pe[(size_t)aidx[a][0]*C_ + c]
                           + awt[a][1]*pe[(size_t)aidx[a][1]*C_ + c]
                           + awt[a][2]*pe[(size_t)aidx[a][2]*C_ + c]
                           + awt[a][3]*pe[(size_t)aidx[a][3]*C_ + c];
        }
    }
    float vals[11];
    vals[0] = rep2;
    #pragma unroll
    for (int a = 0; a < AROUND_; a++){ vals[1+a] = num[a]; vals[6+a] = af2[a]; }
    for (int v = 0; v < 11; v++){
        red[threadIdx.x] = vals[v];
        __syncthreads();
        for (int s = 128; s; s >>= 1){
            if (threadIdx.x < s) red[threadIdx.x] += red[threadIdx.x + s];
            __syncthreads();
        }
        if (threadIdx.x == 0) res[v] = red[0];
        __syncthreads();
    }
    if (threadIdx.x == 0){
        float rn = fmaxf(sqrtf(res[0]), 1e-8f);
        float s[AROUND_]; float mx = -1e30f;
        for (int a = 0; a < AROUND_; a++){
            s[a] = res[1+a] / (rn * fmaxf(sqrtf(res[6+a]), 1e-8f));
            mx = fmaxf(mx, s[a]);
        }
        float ss = 0.f;
        for (int a = 0; a < AROUND_; a++){ s[a] = expf(s[a] - mx); ss += s[a]; }
        for (int a = 0; a < AROUND_; a++) sw[a] = s[a] / ss;
    }
    __syncthreads();
    float w0 = sw[0], w1 = sw[1], w2 = sw[2], w3 = sw[3], w4 = sw[4];
    for (int c = threadIdx.x; c < C_; c += 256){
        float o = pfrow[c] + mqrow[c];
        o += semb[0*C_ + c]*w0 + semb[1*C_ + c]*w1 + semb[2*C_ + c]*w2
           + semb[3*C_ + c]*w3 + semb[4*C_ + c]*w4;
        memo16[((size_t)b*10 + rowBase + nk)*C_ + c] = __float2half_rn(o);
    }
}

// ---------------- tgt init (from mainxT; fp32 + fp16) ----------------
__global__ void tgt_init_kernel(const float* __restrict__ mainxT, const float* __restrict__ mq,
                                const float* __restrict__ pe, float* __restrict__ tgt,
                                __half* __restrict__ tgt16){
    size_t i = (size_t)blockIdx.x*256 + threadIdx.x;
    int c = i % C_;
    size_t tc = i % ((size_t)T_*C_);
    float v = mainxT[i] + mq[c] + pe[tc];
    tgt[i] = v;
    tgt16[i] = __float2half_rn(v);
}

// ---------------- cross-attention (10 keys; half out) ----------------
__global__ void ca_attn_kernel(const float* __restrict__ q, const float* __restrict__ kv,
                               __half* __restrict__ out16){
    int bh = blockIdx.y, b = bh >> 3, h = bh & 7;
    int i = blockIdx.x*256 + threadIdx.x;
    __shared__ float Ks[10][96];
    __shared__ float Vsm[10][96];
    for (int idx = threadIdx.x; idx < 960; idx += 256){
        int j = idx / 96, d = idx % 96;
        Ks[j][d]  = kv[((size_t)b*10 + j)*(2*C_) + h*HD_ + d];
        Vsm[j][d] = kv[((size_t)b*10 + j)*(2*C_) + C_ + h*HD_ + d];
    }
    __syncthreads();
    const float* qr = q + ((size_t)b*T_ + i)*C_ + h*HD_;
    float s[10];
    #pragma unroll
    for (int j = 0; j < 10; j++) s[j] = 0.f;
    for (int d = 0; d < HD_; d++){
        float qd = qr[d];
        #pragma unroll
        for (int j = 0; j < 10; j++) s[j] += qd * Ks[j][d];
    }
    const float scale = 0.10206207261596577f;
    float mx = -1e30f;
    #pragma unroll
    for (int j = 0; j < 10; j++){ s[j] *= scale; mx = fmaxf(mx, s[j]); }
    float sum = 0.f;
    #pragma unroll
    for (int j = 0; j < 10; j++){ s[j] = expf(s[j] - mx); sum += s[j]; }
    float inv = 1.f / sum;
    #pragma unroll
    for (int j = 0; j < 10; j++) s[j] *= inv;
    __half* orow = out16 + ((size_t)b*T_ + i)*C_ + h*HD_;
    for (int d = 0; d < HD_; d++){
        float o = 0.f;
        #pragma unroll
        for (int j = 0; j < 10; j++) o += s[j] * Vsm[j][d];
        orow[d] = __float2half_rn(o);
    }
}

// ---------------- residual add + layernorm (fp32 + fp16 out) ----------------
__global__ void add_ln_kernel(float* __restrict__ tgt, __half* __restrict__ tgt16,
                              const float* __restrict__ resid,
                              const float* __restrict__ w, const float* __restrict__ bb){
    int row = blockIdx.x, t = threadIdx.x;
    float* p = tgt + (size_t)row*C_;
    __half* p16 = tgt16 + (size_t)row*C_;
    const float* r = resid + (size_t)row*C_;
    float v[3];
    float sum = 0.f;
    #pragma unroll
    for (int i = 0; i < 3; i++){ v[i] = p[t + i*256] + r[t + i*256]; sum += v[i]; }
    __shared__ float red[256];
    red[t] = sum; __syncthreads();
    for (int s = 128; s; s >>= 1){ if (t < s) red[t] += red[t + s]; __syncthreads(); }
    float m = red[0] * (1.f/768.f);
    __syncthreads();
    float s2 = 0.f;
    #pragma unroll
    for (int i = 0; i < 3; i++){ float d = v[i] - m; s2 += d*d; }
    red[t] = s2; __syncthreads();
    for (int s = 128; s; s >>= 1){ if (t < s) red[t] += red[t + s]; __syncthreads(); }
    float var = red[0] * (1.f/768.f);
    float rstd = rsqrtf(var + 1e-5f);
    #pragma unroll
    for (int i = 0; i < 3; i++){
        int c = t + i*256;
        float o = (v[i] - m)*rstd*w[c] + bb[c];
        p[c] = o;
        p16[c] = __float2half_rn(o);
    }
}

// ---------------- final transpose ----------------
__global__ void transpose_out_kernel(const float* __restrict__ tgt, float* __restrict__ out){
    __shared__ float tile[32][33];
    int c0 = blockIdx.x*32, t0 = blockIdx.y*32, b = blockIdx.z;
    for (int i = threadIdx.y; i < 32; i += 8)
        tile[i][threadIdx.x] = tgt[((size_t)b*T_ + t0 + i)*C_ + c0 + threadIdx.x];
    __syncthreads();
    for (int i = threadIdx.y; i < 32; i += 8)
        out[((size_t)b*C_ + c0 + i)*T_ + t0 + threadIdx.x] = tile[threadIdx.x][i];
}

// ---------------- launch ----------------
extern "C" void kernel_launch(void* const* d_in, const int* in_sizes, int n_in,
                              void* d_out, int out_size){
    const float* mainx      = (const float*)d_in[0];
    const float* others[2]  = {(const float*)d_in[1], (const float*)d_in[2]};
    const float* pe         = (const float*)d_in[3];
    const float* mq         = (const float*)d_in[4];
    const float* s_w1       = (const float*)d_in[5];
    const float* s_b1       = (const float*)d_in[6];
    const float* s_w2       = (const float*)d_in[7];
    const float* s_b2       = (const float*)d_in[8];
    const float* sa_in_w    = (const float*)d_in[9];
    const float* sa_in_b    = (const float*)d_in[10];
    const float* sa_out_w   = (const float*)d_in[11];
    const float* sa_out_b   = (const float*)d_in[12];
    const float* ca_in_w    = (const float*)d_in[13];
    const float* ca_in_b    = (const float*)d_in[14];
    const float* ca_out_w   = (const float*)d_in[15];
    const float* ca_out_b   = (const float*)d_in[16];
    const float* ff1_w      = (const float*)d_in[17];
    const float* ff1_b      = (const float*)d_in[18];
    const float* ff2_w      = (const float*)d_in[19];
    const float* ff2_b      = (const float*)d_in[20];
    const float* ln_w       = (const float*)d_in[21];
    const float* ln_b       = (const float*)d_in[22];
    const float* block_rand = (const float*)d_in[23];
    const float* around_rand= (const float*)d_in[24];
    float* out = (float*)d_out;

    float *pf0, *hid0, *mainxT, *coords, *score, *tgt, *tmp, *ffh, *memkv, *qb, *exsc;
    int *topidx, *top16;
    __half *qkv16, *pf16, *tgt16, *attn16, *memb16, *ffh16, *wt;
    cudaGetSymbolAddress((void**)&pf0,    g_pf);
    cudaGetSymbolAddress((void**)&hid0,   g_hid);
    cudaGetSymbolAddress((void**)&mainxT, g_mainxT);
    cudaGetSymbolAddress((void**)&coords, g_coords);
    cudaGetSymbolAddress((void**)&score,  g_score);
    cudaGetSymbolAddress((void**)&top16,  g_top16);
    cudaGetSymbolAddress((void**)&exsc,   g_exsc);
    cudaGetSymbolAddress((void**)&topidx, g_topidx);
    cudaGetSymbolAddress((void**)&tgt,    g_tgt);
    cudaGetSymbolAddress((void**)&tmp,    g_tmp);
    cudaGetSymbolAddress((void**)&ffh,    g_ffh);
    cudaGetSymbolAddress((void**)&memkv,  g_memkv);
    cudaGetSymbolAddress((void**)&qb,     g_q);
    cudaGetSymbolAddress((void**)&qkv16,  g_qkv16);
    cudaGetSymbolAddress((void**)&pf16,   g_pf16);
    cudaGetSymbolAddress((void**)&tgt16,  g_tgt16);
    cudaGetSymbolAddress((void**)&attn16, g_attn16);
    cudaGetSymbolAddress((void**)&memb16, g_memb16);
    cudaGetSymbolAddress((void**)&ffh16,  g_ffh16);
    cudaGetSymbolAddress((void**)&wt,     g_wt);

    size_t o = 0;
    __half* wtS = wt + o; o += (size_t)768*768;
    __half *wtSAin[L_], *wtSAout[L_], *wtCAin[L_], *wtCAout[L_], *wtFF1[L_], *wtFF2[L_];
    for (int l = 0; l < L_; l++){
        wtSAin[l]  = wt + o; o += (size_t)2304*768;
        wtSAout[l] = wt + o; o += (size_t)768*768;
        wtCAin[l]  = wt + o; o += (size_t)2304*768;
        wtCAout[l] = wt + o; o += (size_t)768*768;
        wtFF1[l]   = wt + o; o += (size_t)3072*768;
        wtFF2[l]   = wt + o; o += (size_t)768*3072;
    }

    float* pf1  = ffh;
    float* hid1 = ffh + (size_t)B_*NPTS*C_;

    cudaFuncSetAttribute(flash_attn_kernel, cudaFuncAttributeMaxDynamicSharedMemorySize, FA_SMEM_B);

    static cudaStream_t s_m[2] = {nullptr, nullptr};
    static cudaEvent_t  ev_start = nullptr, ev_m[2] = {nullptr, nullptr};
    if (s_m[0] == nullptr){
        cudaStreamCreateWithFlags(&s_m[0], cudaStreamNonBlocking);
        cudaStreamCreateWithFlags(&s_m[1], cudaStreamNonBlocking);
        cudaEventCreateWithFlags(&ev_start, cudaEventDisableTiming);
        cudaEventCreateWithFlags(&ev_m[0], cudaEventDisableTiming);
        cudaEventCreateWithFlags(&ev_m[1], cudaEventDisableTiming);
    }

    // pre-fork work side streams depend on: score weight + mainxT
    transpose_w(s_w1, wtS, 768, 768, 0);
    {
        dim3 g(C_/32, T_/32, B_); dim3 bl(32, 8);
        transpose_in_kernel<<<g, bl>>>(mainx, mainxT);
    }
    cudaEventRecord(ev_start, 0);

    // ---- fork: modality pipelines ----
    float*  pfs[2]   = {pf0, pf1};
    float*  hids[2]  = {hid0, hid1};
    for (int i = 0; i < 2; i++){
        cudaStream_t st = s_m[i];
        cudaStreamWaitEvent(st, ev_start, 0);
        float*  pf_i   = pfs[i];
        __half* pf16_i = pf16 + (size_t)i*B_*NPTS*C_;
        float*  hid_i  = hids[i];
        float* coords_i = coords + (size_t)i*B_*NPTS*2;
        float* score_i  = score  + (size_t)i*B_*NPTS;
        int*   top16_i  = top16  + i*B_*NCAND;
        float* exsc_i   = exsc   + i*B_*NCAND;
        int*   topidx_i = topidx + i*B_*TOPK_;
        {
            dim3 g(C_/32, T_/32, B_); dim3 bl(32, 8);
            transpose_in_kernel<<<g, bl, 0, st>>>(others[i], hid_i);
        }
        sample_kernel<<<B_*NPTS/16, 256, 0, st>>>(hid_i, block_rand + (size_t)i*B_*32*32*2*2,
                                                  pf_i, pf16_i, coords_i);
        zero_score_kernel<<<(B_*NPTS + 255)/256, 256, 0, st>>>(score_i);
        h_gemm<2>(pf16_i, wtS, s_b1, nullptr, nullptr, s_w2, score_i,
                  B_*NPTS, C_, C_, C_, C_, 0, st);
        topk_kernel<<<B_, 256, 0, st>>>(score_i, top16_i, NCAND);
        rescore_kernel<<<B_*NCAND, 256, 0, st>>>(pf_i, s_w1, s_b1, s_w2, top16_i, exsc_i);
        final_top5_kernel<<<B_, 32, 0, st>>>(exsc_i, top16_i, topidx_i);
        soft_align_kernel<<<B_*TOPK_, 256, 0, st>>>(mainxT, pe,
                                                    around_rand + (size_t)i*B_*AROUND_*TOPK_*2,
                                                    mq + (size_t)(i+1)*C_,
                                                    pf_i, coords_i, topidx_i, memb16, i*TOPK_);
        cudaEventRecord(ev_m[i], st);
    }

    // ---- decoder weight transposes + prefix on main stream ----
    for (int l = 0; l < L_; l++){
        transpose_w(sa_in_w  + (size_t)l*C_*3*C_, wtSAin[l],  768, 2304, 0);
        transpose_w(sa_out_w + (size_t)l*C_*C_,   wtSAout[l], 768, 768,  0);
        transpose_w(ca_in_w  + (size_t)l*C_*3*C_, wtCAin[l],  768, 2304, 0);
        transpose_w(ca_out_w + (size_t)l*C_*C_,   wtCAout[l], 768, 768,  0);
        transpose_w(ff1_w    + (size_t)l*C_*FF_,  wtFF1[l],   768, 3072, 0);
        transpose_w(ff2_w    + (size_t)l*FF_*C_,  wtFF2[l],   3072, 768, 0);
    }
    tgt_init_kernel<<<(int)(((size_t)B_*T_*C_ + 255)/256), 256>>>(mainxT, mq, pe, tgt, tgt16);

    // layer 0 SA block + CA-q (no memb dependency)
    h_gemm<3>(tgt16, wtSAin[0], sa_in_b, nullptr, qkv16, nullptr, nullptr,
              B_*T_, 3*C_, C_, C_, C_, 3*C_, 0);
    { dim3 g(T_/128, B_*NHEAD_); flash_attn_kernel<<<g, 256, FA_SMEM_B>>>(qkv16, attn16); }
    h_gemm<0>(attn16, wtSAout[0], sa_out_b, tmp, nullptr, nullptr, nullptr,
              B_*T_, C_, C_, C_, C_, C_, 0);
    add_ln_kernel<<<B_*T_, 256>>>(tgt, tgt16, tmp, ln_w, ln_b);
    h_gemm<0>(tgt16, wtCAin[0], ca_in_b, qb, nullptr, nullptr, nullptr,
              B_*T_, C_, C_, C_, C_, C_, 0);

    // ---- join ----
    cudaStreamWaitEvent(0, ev_m[0], 0);
    cudaStreamWaitEvent(0, ev_m[1], 0);

    for (int l = 0; l < L_; l++){
        if (l > 0){
            h_gemm<3>(tgt16, wtSAin[l], sa_in_b + (size_t)l*3*C_, nullptr, qkv16, nullptr, nullptr,
                      B_*T_, 3*C_, C_, C_, C_, 3*C_, 0);
            { dim3 g(T_/128, B_*NHEAD_); flash_attn_kernel<<<g, 256, FA_SMEM_B>>>(qkv16, attn16); }
            h_gemm<0>(attn16, wtSAout[l], sa_out_b + (size_t)l*C_, tmp, nullptr, nullptr, nullptr,
                      B_*T_, C_, C_, C_, C_, C_, 0);
            add_ln_kernel<<<B_*T_, 256>>>(tgt, tgt16, tmp, ln_w + (size_t)(l*3+0)*C_, ln_b + (size_t)(l*3+0)*C_);
            h_gemm<0>(tgt16, wtCAin[l], ca_in_b + (size_t)l*3*C_, qb, nullptr, nullptr, nullptr,
                      B_*T_, C_, C_, C_, C_, C_, 0);
        }
        h_gemm<0>(memb16, wtCAin[l] + (size_t)768*C_, ca_in_b + (size_t)l*3*C_ + C_, memkv,
                  nullptr, nullptr, nullptr, B_*10, 2*C_, C_, C_, C_, 2*C_, 0);
        { dim3 g(T_/256, B_*NHEAD_); ca_attn_kernel<<<g, 256>>>(qb, memkv, attn16); }
        h_gemm<0>(attn16, wtCAout[l], ca_out_b + (size_t)l*C_, tmp, nullptr, nullptr, nullptr,
                  B_*T_, C_, C_, C_, C_, C_, 0);
        add_ln_kernel<<<B_*T_, 256>>>(tgt, tgt16, tmp, ln_w + (size_t)(l*3+1)*C_, ln_b + (size_t)(l*3+1)*C_);

        h_gemm<1>(tgt16, wtFF1[l], ff1_b + (size_t)l*FF_, nullptr, ffh16, nullptr, nullptr,
                  B_*T_, FF_, C_, C_, C_, FF_, 0);
        h_gemm<0>(ffh16, wtFF2[l], ff2_b + (size_t)l*C_, tmp, nullptr, nullptr, nullptr,
                  B_*T_, C_, FF_, FF_, FF_, C_, 0);
        add_ln_kernel<<<B_*T_, 256>>>(tgt, tgt16, tmp, ln_w + (size_t)(l*3+2)*C_, ln_b + (size_t)(l*3+2)*C_);
    }

    {
        dim3 g(C_/32, T_/32, B_); dim3 bl(32, 8);
        transpose_out_kernel<<<g, bl>>>(tgt, out);
    }
}

// round 15
// speedup vs baseline: 1.1946x; 1.0864x over previous
#include <cuda_runtime.h>
#include <cuda_fp16.h>
#include <math.h>
#include <stdint.h>

// ---------------- constants ----------------
#define B_   8
#define C_   768
#define T_   1024
#define L_   2
#define FF_  3072
#define NPTS 2048
#define TOPK_ 5
#define NCAND 16
#define AROUND_ 5
#define NHEAD_ 8
#define HD_  96

// ---------------- scratch ----------------
__device__ float g_pf    [(size_t)B_*NPTS*C_];
__device__ float g_hid   [(size_t)B_*NPTS*C_];
__device__ float g_mainxT[(size_t)B_*T_*C_];
__device__ float g_coords[2*(size_t)B_*NPTS*2];
__device__ float g_score [2*(size_t)B_*NPTS];
__device__ int   g_top16 [2*B_*NCAND];
__device__ float g_exsc  [2*B_*NCAND];
__device__ int   g_topidx[2*B_*TOPK_];
__device__ float g_tgt   [(size_t)B_*T_*C_];
__device__ float g_tmp   [(size_t)B_*T_*C_];
__device__ float g_ffh   [(size_t)B_*T_*FF_];      // phase-A scratch: pf1 + xT1
__device__ float g_memkv [2*(size_t)B_*10*2*C_];   // per-layer buffers
__device__ float g_q     [(size_t)B_*T_*C_];
// fp16 mirrors / weights
__device__ __align__(256) __half g_qkv16 [(size_t)B_*T_*3*C_];
__device__ __align__(256) __half g_pf16  [2*(size_t)B_*NPTS*C_];
__device__ __align__(256) __half g_tgt16 [(size_t)B_*T_*C_];
__device__ __align__(256) __half g_attn16[(size_t)B_*T_*C_];
__device__ __align__(256) __half g_memb16[(size_t)B_*10*C_];
__device__ __align__(256) __half g_ffh16 [(size_t)B_*T_*FF_];
__device__ __align__(256) __half g_wt    [19464192];

// ---------------- fp16 mma (m16n8k16) ----------------
__device__ __forceinline__ void mma16(float* d, const uint32_t* a, const uint32_t* b){
    asm volatile("mma.sync.aligned.m16n8k16.row.col.f32.f16.f16.f32 "
        "{%0,%1,%2,%3},{%4,%5,%6,%7},{%8,%9},{%0,%1,%2,%3};\n"
        : "+f"(d[0]), "+f"(d[1]), "+f"(d[2]), "+f"(d[3])
        : "r"(a[0]), "r"(a[1]), "r"(a[2]), "r"(a[3]), "r"(b[0]), "r"(b[1]));
}

// ---------------- fp16 GEMM: 128 threads, 2x2 warps, 64x64 tiles, k64 stages ----------------
// MODE 0: fp32 C out. MODE 1: relu + half C16 out. MODE 2: score. MODE 3: half C16, no relu.
#define H_STRIDE_W 36          // 32-bit words per row (64 halves + 8 pad)
#define H_ROW_B    144
#define H_STAGE_B  (128*H_ROW_B*2)   // 36864 B (A + B halves)
#define H_SMEM_B   (3*H_STAGE_B)     // 110592 B

template<int MODE>
__global__ __launch_bounds__(128, 2)
void h_gemm_kernel(const __half* __restrict__ A, const __half* __restrict__ WT,
                   const float* __restrict__ bias, float* __restrict__ C,
                   __half* __restrict__ C16, const float* __restrict__ w2,
                   float* __restrict__ score,
                   int M, int N, int K, int lda, int ldb, int ldc)
{
    extern __shared__ char smraw[];

    int tid = threadIdx.x, lane = tid & 31, warp = tid >> 5;
    int gid = lane >> 2, tig = lane & 3;
    int wm = warp >> 1, wn = warp & 1;
    int row0 = blockIdx.y * 128, col0 = blockIdx.x * 128;

    float acc[4][8][4];
    #pragma unroll
    for (int i = 0; i < 4; i++)
        #pragma unroll
        for (int j = 0; j < 8; j++)
            #pragma unroll
            for (int r = 0; r < 4; r++) acc[i][j][r] = 0.f;

    // copy coords: per operand 128 rows x 8 chunks of 16B; 128 threads x 8 iters
    int crow[8], cseg[8], assz[8], acar[8];
    #pragma unroll
    for (int i = 0; i < 8; i++){
        int idx = tid + i*128;
        crow[i] = idx >> 3; cseg[i] = idx & 7;
        assz[i] = (row0 + crow[i] < M) ? 16 : 0;
        acar[i] = assz[i] ? row0 + crow[i] : 0;
    }

    auto issue_stage = [&](int stage, int k0){
        char* Ab = smraw + stage*H_STAGE_B;
        char* Bb = Ab + 128*H_ROW_B;
        #pragma unroll
        for (int i = 0; i < 8; i++){
            uint32_t d = (uint32_t)__cvta_generic_to_shared(Ab + crow[i]*H_ROW_B + cseg[i]*16);
            const __half* s = A + (size_t)acar[i]*lda + k0 + cseg[i]*8;
            asm volatile("cp.async.cg.shared.global [%0], [%1], 16, %2;\n" :: "r"(d), "l"(s), "r"(assz[i]));
        }
        #pragma unroll
        for (int i = 0; i < 8; i++){
            uint32_t d = (uint32_t)__cvta_generic_to_shared(Bb + crow[i]*H_ROW_B + cseg[i]*16);
            const __half* s = WT + (size_t)(col0 + crow[i])*ldb + k0 + cseg[i]*8;
            asm volatile("cp.async.cg.shared.global [%0], [%1], 16;\n" :: "r"(d), "l"(s));
        }
        asm volatile("cp.async.commit_group;\n" ::: "memory");
    };

    auto compute = [&](int stage){
        const uint32_t* As = (const uint32_t*)(smraw + stage*H_STAGE_B);
        const uint32_t* Bs = As + 128*H_STRIDE_W;
        #pragma unroll
        for (int kk = 0; kk < 4; kk++){
            int kw = kk*8 + tig;
            uint32_t af[4][4], bf[8][2];
            #pragma unroll
            for (int ma = 0; ma < 4; ma++){
                int m = wm*64 + ma*16 + gid;
                af[ma][0] = As[m*H_STRIDE_W + kw];
                af[ma][1] = As[(m+8)*H_STRIDE_W + kw];
                af[ma][2] = As[m*H_STRIDE_W + kw + 4];
                af[ma][3] = As[(m+8)*H_STRIDE_W + kw + 4];
            }
            #pragma unroll
            for (int na = 0; na < 8; na++){
                int n = wn*64 + na*8 + gid;
                bf[na][0] = Bs[n*H_STRIDE_W + kw];
                bf[na][1] = Bs[n*H_STRIDE_W + kw + 4];
            }
            #pragma unroll
            for (int ma = 0; ma < 4; ma++)
                #pragma unroll
                for (int na = 0; na < 8; na++)
                    mma16(acc[ma][na], af[ma], bf[na]);
        }
    };

    int nc = K / 64;
    issue_stage(0, 0);
    issue_stage(1, 64);
    for (int it = 0; it < nc; it++){
        asm volatile("cp.async.wait_group 1;\n" ::: "memory");
        __syncthreads();
        int nxt = it + 2;
        if (nxt < nc){
            int st = nxt % 3;
            issue_stage(st, nxt*64);
        } else {
            asm volatile("cp.async.commit_group;\n" ::: "memory");
        }
        compute(it % 3);
    }

    #pragma unroll
    for (int ma = 0; ma < 4; ma++){
        int r0 = row0 + wm*64 + ma*16 + gid;
        float s0 = 0.f, s1 = 0.f;
        #pragma unroll
        for (int na = 0; na < 8; na++){
            int c = col0 + wn*64 + na*8 + 2*tig;
            float b0 = bias ? bias[c] : 0.f;
            float b1 = bias ? bias[c+1] : 0.f;
            float x0 = acc[ma][na][0] + b0;
            float x1 = acc[ma][na][1] + b1;
            float x2 = acc[ma][na][2] + b0;
            float x3 = acc[ma][na][3] + b1;
            if (MODE == 1 || MODE == 2){
                x0 = fmaxf(x0, 0.f); x1 = fmaxf(x1, 0.f);
                x2 = fmaxf(x2, 0.f); x3 = fmaxf(x3, 0.f);
            }
            if (MODE == 2){
                float w0 = w2[c], w1 = w2[c+1];
                s0 += x0*w0 + x1*w1;
                s1 += x2*w0 + x3*w1;
            } else if (MODE == 1 || MODE == 3){
                if (r0 < M)     *(__half2*)&C16[(size_t)r0*ldc + c]     = __floats2half2_rn(x0, x1);
                if (r0 + 8 < M) *(__half2*)&C16[(size_t)(r0+8)*ldc + c] = __floats2half2_rn(x2, x3);
            } else {
                if (r0 < M){ float2 o = make_float2(x0, x1); *(float2*)&C[(size_t)r0*ldc + c] = o; }
                if (r0 + 8 < M){ float2 o = make_float2(x2, x3); *(float2*)&C[(size_t)(r0+8)*ldc + c] = o; }
            }
        }
        if (MODE == 2){
            s0 += __shfl_xor_sync(0xffffffffu, s0, 1);
            s0 += __shfl_xor_sync(0xffffffffu, s0, 2);
            s1 += __shfl_xor_sync(0xffffffffu, s1, 1);
            s1 += __shfl_xor_sync(0xffffffffu, s1, 2);
            if (tig == 0){
                if (r0 < M)     atomicAdd(&score[r0], s0);
                if (r0 + 8 < M) atomicAdd(&score[r0 + 8], s1);
            }
        }
    }
}

template<int MODE>
static void h_gemm(const __half* A, const __half* WT, const float* bias, float* C,
                   __half* C16, const float* w2, float* score,
                   int M, int N, int K, int lda, int ldb, int ldc, cudaStream_t st){
    cudaFuncSetAttribute(h_gemm_kernel<MODE>, cudaFuncAttributeMaxDynamicSharedMemorySize, H_SMEM_B);
    dim3 grid(N/128, (M + 127)/128);
    h_gemm_kernel<MODE><<<grid, 128, H_SMEM_B, st>>>(A, WT, bias, C, C16, w2, score, M, N, K, lda, ldb, ldc);
}

// ---------------- weight transpose+convert (single + batched) ----------------
__device__ __forceinline__ void wt_tile(const float* W, __half* WT, int K, int N,
                                        int n0, int k0, float tile[32][33]){
    for (int i = threadIdx.y; i < 32; i += 8)
        tile[i][threadIdx.x] = W[(size_t)(k0 + i)*N + n0 + threadIdx.x];
    __syncthreads();
    for (int i = threadIdx.y; i < 32; i += 8)
        WT[(size_t)(n0 + i)*K + k0 + threadIdx.x] = __float2half_rn(tile[threadIdx.x][i]);
}

__global__ void transpose_w_kernel(const float* __restrict__ W, __half* __restrict__ WT,
                                   int K, int N){
    __shared__ float tile[32][33];
    wt_tile(W, WT, K, N, blockIdx.x*32, blockIdx.y*32, tile);
}
static void transpose_w(const float* W, __half* WT, int K, int N, cudaStream_t st){
    dim3 g(N/32, K/32); dim3 bl(32, 8);
    transpose_w_kernel<<<g, bl, 0, st>>>(W, WT, K, N);
}

struct WTJobs {
    const float* src[12];
    __half*      dst[12];
    int K[12];
    int N[12];
};
__global__ void transpose_w_all_kernel(WTJobs jobs){
    __shared__ float tile[32][33];
    int j = blockIdx.y;
    int K = jobs.K[j], N = jobs.N[j];
    int tilesX = N >> 5;
    int t = blockIdx.x;
    if (t >= tilesX * (K >> 5)) return;
    int n0 = (t % tilesX)*32, k0 = (t / tilesX)*32;
    wt_tile(jobs.src[j], jobs.dst[j], K, N, n0, k0, tile);
}

// ---------------- flash attention (fp16 mma, online softmax) ----------------
#define FA_KS_STR 136
#define FA_VS_STR 104
#define FA_SMEM_B ((48*136 + 64*104 + 64*136)*4)
#define FA_LOG2E 1.4426950408889634f

__global__ __launch_bounds__(256, 1)
void flash_attn_kernel(const __half* __restrict__ qkv, __half* __restrict__ out16){
    extern __shared__ uint32_t sm32[];
    uint32_t* Ks = sm32;
    uint32_t* Vs = Ks + 48*FA_KS_STR;
    uint32_t* Ps = Vs + 64*FA_VS_STR;

    int qt = blockIdx.x, bh = blockIdx.y, b = bh >> 3, h = bh & 7;
    int tid = threadIdx.x, lane = tid & 31, warp = tid >> 5;
    int gid = lane >> 2, tig = lane & 3;
    int m0 = warp * 16;
    int q0 = qt * 128;
    const float iscale = 0.10206207261596577f;

    uint32_t qf[6][4];
    {
        const __half* Qa = qkv + (size_t)(b*T_ + q0 + m0 + gid)*(3*C_) + h*HD_;
        const __half* Qb = Qa + 8*(3*C_);
        #pragma unroll
        for (int kk = 0; kk < 6; kk++){
            qf[kk][0] = *(const uint32_t*)&Qa[(kk*8 + tig)*2];
            qf[kk][1] = *(const uint32_t*)&Qb[(kk*8 + tig)*2];
            qf[kk][2] = *(const uint32_t*)&Qa[(kk*8 + tig + 4)*2];
            qf[kk][3] = *(const uint32_t*)&Qb[(kk*8 + tig + 4)*2];
        }
    }

    float oacc[12][4];
    #pragma unroll
    for (int i = 0; i < 12; i++)
        #pragma unroll
        for (int j = 0; j < 4; j++) oacc[i][j] = 0.f;
    float mrow0 = -1e30f, mrow1 = -1e30f, lrow0 = 0.f, lrow1 = 0.f;

    for (int kt = 0; kt < 8; kt++){
        __syncthreads();
        {
            const __half* Kb = qkv + (size_t)(b*T_ + kt*128)*(3*C_) + C_ + h*HD_;
            const __half* Vb = Kb + C_;
            for (int idx = tid; idx < 128*48; idx += 256){
                int r = idx / 48, d = idx % 48;
                Ks[d*FA_KS_STR + r] = *(const uint32_t*)&Kb[(size_t)r*(3*C_) + d*2];
            }
            for (int idx = tid; idx < 64*96; idx += 256){
                int p = idx / 96, n = idx % 96;
                __half lo = Vb[(size_t)(2*p)*(3*C_) + n];
                __half hi = Vb[(size_t)(2*p + 1)*(3*C_) + n];
                __half2 hv = __halves2half2(lo, hi);
                Vs[p*FA_VS_STR + n] = *(const uint32_t*)&hv;
            }
        }
        __syncthreads();

        float sacc[16][4];
        #pragma unroll
        for (int nf = 0; nf < 16; nf++)
            #pragma unroll
            for (int j = 0; j < 4; j++) sacc[nf][j] = 0.f;
        #pragma unroll
        for (int kk = 0; kk < 6; kk++){
            int k1 = (kk*8 + tig)*FA_KS_STR, k2 = (kk*8 + tig + 4)*FA_KS_STR;
            #pragma unroll
            for (int nf = 0; nf < 16; nf++){
                uint32_t bfr[2] = { Ks[k1 + nf*8 + gid], Ks[k2 + nf*8 + gid] };
                mma16(sacc[nf], qf[kk], bfr);
            }
        }
        #pragma unroll
        for (int nf = 0; nf < 16; nf++){
            sacc[nf][0] *= iscale; sacc[nf][1] *= iscale;
            sacc[nf][2] *= iscale; sacc[nf][3] *= iscale;
        }

        float rm0 = -1e30f, rm1 = -1e30f;
        #pragma unroll
        for (int nf = 0; nf < 16; nf++){
            rm0 = fmaxf(rm0, fmaxf(sacc[nf][0], sacc[nf][1]));
            rm1 = fmaxf(rm1, fmaxf(sacc[nf][2], sacc[nf][3]));
        }
        rm0 = fmaxf(rm0, __shfl_xor_sync(0xffffffffu, rm0, 1));
        rm0 = fmaxf(rm0, __shfl_xor_sync(0xffffffffu, rm0, 2));
        rm1 = fmaxf(rm1, __shfl_xor_sync(0xffffffffu, rm1, 1));
        rm1 = fmaxf(rm1, __shfl_xor_sync(0xffffffffu, rm1, 2));
        float mn0 = fmaxf(mrow0, rm0), mn1 = fmaxf(mrow1, rm1);
        float al0 = exp2f((mrow0 - mn0)*FA_LOG2E);
        float al1 = exp2f((mrow1 - mn1)*FA_LOG2E);
        mrow0 = mn0; mrow1 = mn1;
        float rs0 = 0.f, rs1 = 0.f;
        #pragma unroll
        for (int nf = 0; nf < 16; nf++){
            float p0 = exp2f((sacc[nf][0] - mn0)*FA_LOG2E);
            float p1 = exp2f((sacc[nf][1] - mn0)*FA_LOG2E);
            float p2 = exp2f((sacc[nf][2] - mn1)*FA_LOG2E);
            float p3 = exp2f((sacc[nf][3] - mn1)*FA_LOG2E);
            sacc[nf][0] = p0; sacc[nf][1] = p1; sacc[nf][2] = p2; sacc[nf][3] = p3;
            rs0 += p0 + p1; rs1 += p2 + p3;
        }
        rs0 += __shfl_xor_sync(0xffffffffu, rs0, 1);
        rs0 += __shfl_xor_sync(0xffffffffu, rs0, 2);
        rs1 += __shfl_xor_sync(0xffffffffu, rs1, 1);
        rs1 += __shfl_xor_sync(0xffffffffu, rs1, 2);
        lrow0 = lrow0*al0 + rs0;
        lrow1 = lrow1*al1 + rs1;
        #pragma unroll
        for (int nf = 0; nf < 12; nf++){
            oacc[nf][0] *= al0; oacc[nf][1] *= al0;
            oacc[nf][2] *= al1; oacc[nf][3] *= al1;
        }

        #pragma unroll
        for (int nf = 0; nf < 16; nf++){
            int cp = nf*4 + tig;
            __half2 h0 = __floats2half2_rn(sacc[nf][0], sacc[nf][1]);
            __half2 h1 = __floats2half2_rn(sacc[nf][2], sacc[nf][3]);
            Ps[cp*FA_KS_STR + m0 + gid]     = *(const uint32_t*)&h0;
            Ps[cp*FA_KS_STR + m0 + gid + 8] = *(const uint32_t*)&h1;
        }
        __syncwarp();

        #pragma unroll
        for (int kk = 0; kk < 8; kk++){
            int k1 = (kk*8 + tig)*FA_KS_STR, k2 = (kk*8 + tig + 4)*FA_KS_STR;
            uint32_t pa[4] = { Ps[k1 + m0 + gid], Ps[k1 + m0 + gid + 8],
                               Ps[k2 + m0 + gid], Ps[k2 + m0 + gid + 8] };
            int v1 = (kk*8 + tig)*FA_VS_STR, v2 = (kk*8 + tig + 4)*FA_VS_STR;
            #pragma unroll
            for (int nf = 0; nf < 12; nf++){
                uint32_t vb2[2] = { Vs[v1 + nf*8 + gid], Vs[v2 + nf*8 + gid] };
                mma16(oacc[nf], pa, vb2);
            }
        }
    }

    float inv0 = 1.f / lrow0, inv1 = 1.f / lrow1;
    size_t r0 = (size_t)(b*T_ + q0 + m0 + gid);
    #pragma unroll
    for (int nf = 0; nf < 12; nf++){
        int col = h*HD_ + nf*8 + 2*tig;
        *(__half2*)&out16[r0*C_ + col]       = __floats2half2_rn(oacc[nf][0]*inv0, oacc[nf][1]*inv0);
        *(__half2*)&out16[(r0 + 8)*C_ + col] = __floats2half2_rn(oacc[nf][2]*inv1, oacc[nf][3]*inv1);
    }
}

// ---------------- transpose x [B,C,T] -> xT [B,T,C] ----------------
__global__ void transpose_in_kernel(const float* __restrict__ x, float* __restrict__ xT){
    __shared__ float tile[32][33];
    int c0 = blockIdx.x*32, t0 = blockIdx.y*32, b = blockIdx.z;
    for (int i = threadIdx.y; i < 32; i += 8)
        tile[i][threadIdx.x] = x[((size_t)b*C_ + c0 + i)*T_ + t0 + threadIdx.x];
    __syncthreads();
    for (int i = threadIdx.y; i < 32; i += 8)
        xT[((size_t)b*T_ + t0 + i)*C_ + c0 + threadIdx.x] = tile[threadIdx.x][i];
}

// ---------------- blockwise sampling (fp32 + fp16 out) ----------------
__global__ void sample_kernel(const float* __restrict__ xT, const float* __restrict__ brand,
                              float* __restrict__ pf, __half* __restrict__ pf16,
                              float* __restrict__ coords){
    int p0 = blockIdx.x * 16;
    __shared__ int   sidx[16][4];
    __shared__ float swt [16][4];
    int tid = threadIdx.x;
    if (tid < 16){
        int bn = p0 + tid;
        int b  = bn >> 11;
        int n  = bn & 2047;
        int k  = n & 1;
        int pw = (n >> 1) & 31;
        int ph = n >> 6;
        const float bs = 0.0625f;
        const float* br = brand + ((((size_t)b*32 + ph)*32 + pw)*2 + k)*2;
        float gx = br[0]*bs + (-1.0f + ph*bs);
        float gy = br[1]*bs + (-1.0f + pw*bs);
        coords[(size_t)bn*2]     = gx;
        coords[(size_t)bn*2 + 1] = gy;
        float ix = ((gx + 1.0f)*32.0f - 1.0f)*0.5f;
        float iy = ((gy + 1.0f)*32.0f - 1.0f)*0.5f;
        float x0f = floorf(ix), y0f = floorf(iy);
        int x0 = (int)x0f, y0 = (int)y0f;
        float wx1 = ix - x0f, wy1 = iy - y0f;
        float wxs[2] = {1.f - wx1, wx1};
        float wys[2] = {1.f - wy1, wy1};
        #pragma unroll
        for (int j = 0; j < 4; j++){
            int xi = x0 + (j & 1), yi = y0 + (j >> 1);
            bool v = (xi >= 0) & (xi < 32) & (yi >= 0) & (yi < 32);
            sidx[tid][j] = v ? (yi*32 + xi) : 0;
            swt [tid][j] = v ? (wxs[j & 1]*wys[j >> 1]) : 0.f;
        }
    }
    __syncthreads();
    int b = (p0 >> 11);
    const float* base = xT + (size_t)b*T_*C_;
    for (int pt = 0; pt < 16; pt++){
        const float* r0 = base + (size_t)sidx[pt][0]*C_;
        const float* r1 = base + (size_t)sidx[pt][1]*C_;
        const float* r2 = base + (size_t)sidx[pt][2]*C_;
        const float* r3 = base + (size_t)sidx[pt][3]*C_;
        float w0 = swt[pt][0], w1 = swt[pt][1], w2 = swt[pt][2], w3 = swt[pt][3];
        float* dst = pf + (size_t)(p0 + pt)*C_;
        __half* dst16 = pf16 + (size_t)(p0 + pt)*C_;
        for (int c = tid; c < C_; c += 256){
            float v = r0[c]*w0 + r1[c]*w1 + r2[c]*w2 + r3[c]*w3;
            dst[c] = v;
            dst16[c] = __float2half_rn(v);
        }
    }
}

// ---------------- zero score ----------------
__global__ void zero_score_kernel(float* __restrict__ score){
    int i = blockIdx.x*256 + threadIdx.x;
    if (i < B_*NPTS) score[i] = 0.f;
}

// ---------------- top-K ----------------
__global__ void topk_kernel(const float* __restrict__ score, int* __restrict__ topidx, int K){
    int b = blockIdx.x;
    __shared__ float sv[2048];
    __shared__ float rv[256];
    __shared__ int   ri[256];
    for (int j = threadIdx.x; j < 2048; j += 256) sv[j] = score[(size_t)b*2048 + j];
    __syncthreads();
    for (int t = 0; t < K; t++){
        float bv = -1e30f; int bi = 0x7fffffff;
        for (int j = threadIdx.x; j < 2048; j += 256){
            float v = sv[j];
            if (v > bv){ bv = v; bi = j; }
        }
        rv[threadIdx.x] = bv; ri[threadIdx.x] = bi;
        __syncthreads();
        for (int s = 128; s; s >>= 1){
            if (threadIdx.x < s){
                float v2 = rv[threadIdx.x + s]; int i2 = ri[threadIdx.x + s];
                if (v2 > rv[threadIdx.x] || (v2 == rv[threadIdx.x] && i2 < ri[threadIdx.x])){
                    rv[threadIdx.x] = v2; ri[threadIdx.x] = i2;
                }
            }
            __syncthreads();
        }
        if (threadIdx.x == 0){
            topidx[b*K + t] = ri[0];
            sv[ri[0]] = -1e30f;
        }
        __syncthreads();
    }
}

// ---------------- exact fp32 rescore ----------------
__global__ __launch_bounds__(256)
void rescore_kernel(const float* __restrict__ pf, const float* __restrict__ W1,
                    const float* __restrict__ b1, const float* __restrict__ w2,
                    const int* __restrict__ cand, float* __restrict__ exsc){
    int b = blockIdx.x >> 4, c = blockIdx.x & 15;
    int idx = cand[b*NCAND + c];
    __shared__ float spf[C_];
    int tid = threadIdx.x;
    for (int i = tid; i < C_; i += 256) spf[i] = pf[((size_t)b*NPTS + idx)*C_ + i];
    __syncthreads();
    float a0 = b1[tid], a1 = b1[tid+256], a2 = b1[tid+512];
    for (int k = 0; k < C_; k++){
        float v = spf[k];
        const float* w = W1 + (size_t)k*C_;
        a0 += v * w[tid];
        a1 += v * w[tid+256];
        a2 += v * w[tid+512];
    }
    float p = fmaxf(a0,0.f)*w2[tid] + fmaxf(a1,0.f)*w2[tid+256] + fmaxf(a2,0.f)*w2[tid+512];
    #pragma unroll
    for (int o = 16; o; o >>= 1) p += __shfl_down_sync(0xffffffffu, p, o);
    __shared__ float red[8];
    if ((tid & 31) == 0) red[tid >> 5] = p;
    __syncthreads();
    if (tid == 0){
        float s = 0.f;
        #pragma unroll
        for (int i = 0; i < 8; i++) s += red[i];
        exsc[b*NCAND + c] = s;
    }
}

// ---------------- final exact top-5 ----------------
__global__ void final_top5_kernel(const float* __restrict__ exsc, const int* __restrict__ cand,
                                  int* __restrict__ topidx){
    int b = blockIdx.x;
    if (threadIdx.x == 0){
        float s[NCAND]; int id[NCAND];
        for (int i = 0; i < NCAND; i++){ s[i] = exsc[b*NCAND + i]; id[i] = cand[b*NCAND + i]; }
        for (int t = 0; t < TOPK_; t++){
            int bi = 0;
            float bv = -1e30f; int bid = 0x7fffffff;
            for (int i = 0; i < NCAND; i++){
                if (s[i] > bv || (s[i] == bv && id[i] < bid)){ bv = s[i]; bid = id[i]; bi = i; }
            }
            topidx[b*TOPK_ + t] = id[bi];
            s[bi] = -1e30f;
        }
    }
}

// ---------------- soft_align (coalesced via mainxT; fp16 mem rows) ----------------
__global__ void soft_align_kernel(const float* __restrict__ mainxT, const float* __restrict__ pe,
                                  const float* __restrict__ arand, const float* __restrict__ mqrow,
                                  const float* __restrict__ pf, const float* __restrict__ coords,
                                  const int* __restrict__ topidx, __half* __restrict__ memo16, int rowBase){
    int b  = blockIdx.x / TOPK_;
    int nk = blockIdx.x % TOPK_;
    int idx = topidx[b*TOPK_ + nk];
    float px = coords[((size_t)b*NPTS + idx)*2 + 0];
    float py = coords[((size_t)b*NPTS + idx)*2 + 1];
    __shared__ float semb[AROUND_*C_];
    __shared__ float red[256];
    __shared__ float res[11];
    __shared__ float sw[AROUND_];

    int   aidx[AROUND_][4];
    float awt [AROUND_][4];
    #pragma unroll
    for (int a = 0; a < AROUND_; a++){
        const float* ar = arand + (((size_t)b*AROUND_ + a)*TOPK_ + nk)*2;
        float g0 = px + (ar[0]*2.f - 0.5f)*0.2f;
        float g1 = py + (ar[1]*2.f - 0.5f)*0.2f;
        g0 = fminf(fmaxf(g0, -1.f), 1.f);
        g1 = fminf(fmaxf(g1, -1.f), 1.f);
        float ix = ((g0 + 1.f)*32.f - 1.f)*0.5f;
        float iy = ((g1 + 1.f)*32.f - 1.f)*0.5f;
        float x0f = floorf(ix), y0f = floorf(iy);
        int x0 = (int)x0f, y0 = (int)y0f;
        float wx1 = ix - x0f, wy1 = iy - y0f;
        float wxs[2] = {1.f - wx1, wx1};
        float wys[2] = {1.f - wy1, wy1};
        #pragma unroll
        for (int j = 0; j < 4; j++){
            int xi = x0 + (j & 1), yi = y0 + (j >> 1);
            bool v = (xi >= 0) & (xi < 32) & (yi >= 0) & (yi < 32);
            aidx[a][j] = v ? (yi*32 + xi) : 0;
            awt [a][j] = v ? (wxs[j & 1]*wys[j >> 1]) : 0.f;
        }
    }
    const float* xbase = mainxT + (size_t)b*T_*C_;
    const float* pfrow = pf + ((size_t)b*NPTS + idx)*C_;
    float rep2 = 0.f, num[AROUND_], af2[AROUND_];
    #pragma unroll
    for (int a = 0; a < AROUND_; a++){ num[a] = 0.f; af2[a] = 0.f; }
    for (int c = threadIdx.x; c < C_; c += 256){
        float r = pfrow[c];
        rep2 += r*r;
        #pragma unroll
        for (int a = 0; a < AROUND_; a++){
            float af = awt[a][0]*xbase[(size_t)aidx[a][0]*C_ + c]
                     + awt[a][1]*xbase[(size_t)aidx[a][1]*C_ + c]
                     + awt[a][2]*xbase[(size_t)aidx[a][2]*C_ + c]
                     + awt[a][3]*xbase[(size_t)aidx[a][3]*C_ + c];
            num[a] += r*af;
            af2[a] += af*af;
            semb[a*C_ + c] = awt[a][0]*pe[(size_t)aidx[a][0]*C_ + c]
                           + awt[a][1]*pe[(size_t)aidx[a][1]*C_ + c]
                           + awt[a][2]*pe[(size_t)aidx[a][2]*C_ + c]
                           + awt[a][3]*pe[(size_t)aidx[a][3]*C_ + c];
        }
    }
    float vals[11];
    vals[0] = rep2;
    #pragma unroll
    for (int a = 0; a < AROUND_; a++){ vals[1+a] = num[a]; vals[6+a] = af2[a]; }
    for (int v = 0; v < 11; v++){
        red[threadIdx.x] = vals[v];
        __syncthreads();
        for (int s = 128; s; s >>= 1){
            if (threadIdx.x < s) red[threadIdx.x] += red[threadIdx.x + s];
            __syncthreads();
        }
        if (threadIdx.x == 0) res[v] = red[0];
        __syncthreads();
    }
    if (threadIdx.x == 0){
        float rn = fmaxf(sqrtf(res[0]), 1e-8f);
        float s[AROUND_]; float mx = -1e30f;
        for (int a = 0; a < AROUND_; a++){
            s[a] = res[1+a] / (rn * fmaxf(sqrtf(res[6+a]), 1e-8f));
            mx = fmaxf(mx, s[a]);
        }
        float ss = 0.f;
        for (int a = 0; a < AROUND_; a++){ s[a] = expf(s[a] - mx); ss += s[a]; }
        for (int a = 0; a < AROUND_; a++) sw[a] = s[a] / ss;
    }
    __syncthreads();
    float w0 = sw[0], w1 = sw[1], w2 = sw[2], w3 = sw[3], w4 = sw[4];
    for (int c = threadIdx.x; c < C_; c += 256){
        float o = pfrow[c] + mqrow[c];
        o += semb[0*C_ + c]*w0 + semb[1*C_ + c]*w1 + semb[2*C_ + c]*w2
           + semb[3*C_ + c]*w3 + semb[4*C_ + c]*w4;
        memo16[((size_t)b*10 + rowBase + nk)*C_ + c] = __float2half_rn(o);
    }
}

// ---------------- tgt init (from mainxT; fp32 + fp16) ----------------
__global__ void tgt_init_kernel(const float* __restrict__ mainxT, const float* __restrict__ mq,
                                const float* __restrict__ pe, float* __restrict__ tgt,
                                __half* __restrict__ tgt16){
    size_t i = (size_t)blockIdx.x*256 + threadIdx.x;
    int c = i % C_;
    size_t tc = i % ((size_t)T_*C_);
    float v = mainxT[i] + mq[c] + pe[tc];
    tgt[i] = v;
    tgt16[i] = __float2half_rn(v);
}

// ---------------- cross-attention (10 keys; half out) ----------------
__global__ void ca_attn_kernel(const float* __restrict__ q, const float* __restrict__ kv,
                               __half* __restrict__ out16){
    int bh = blockIdx.y, b = bh >> 3, h = bh & 7;
    int i = blockIdx.x*256 + threadIdx.x;
    __shared__ float Ks[10][96];
    __shared__ float Vsm[10][96];
    for (int idx = threadIdx.x; idx < 960; idx += 256){
        int j = idx / 96, d = idx % 96;
        Ks[j][d]  = kv[((size_t)b*10 + j)*(2*C_) + h*HD_ + d];
        Vsm[j][d] = kv[((size_t)b*10 + j)*(2*C_) + C_ + h*HD_ + d];
    }
    __syncthreads();
    const float* qr = q + ((size_t)b*T_ + i)*C_ + h*HD_;
    float s[10];
    #pragma unroll
    for (int j = 0; j < 10; j++) s[j] = 0.f;
    for (int d = 0; d < HD_; d++){
        float qd = qr[d];
        #pragma unroll
        for (int j = 0; j < 10; j++) s[j] += qd * Ks[j][d];
    }
    const float scale = 0.10206207261596577f;
    float mx = -1e30f;
    #pragma unroll
    for (int j = 0; j < 10; j++){ s[j] *= scale; mx = fmaxf(mx, s[j]); }
    float sum = 0.f;
    #pragma unroll
    for (int j = 0; j < 10; j++){ s[j] = expf(s[j] - mx); sum += s[j]; }
    float inv = 1.f / sum;
    #pragma unroll
    for (int j = 0; j < 10; j++) s[j] *= inv;
    __half* orow = out16 + ((size_t)b*T_ + i)*C_ + h*HD_;
    for (int d = 0; d < HD_; d++){
        float o = 0.f;
        #pragma unroll
        for (int j = 0; j < 10; j++) o += s[j] * Vsm[j][d];
        orow[d] = __float2half_rn(o);
    }
}

// ---------------- residual add + layernorm (fp32 + fp16 out) ----------------
__global__ void add_ln_kernel(float* __restrict__ tgt, __half* __restrict__ tgt16,
                              const float* __restrict__ resid,
                              const float* __restrict__ w, const float* __restrict__ bb){
    int row = blockIdx.x, t = threadIdx.x;
    float* p = tgt + (size_t)row*C_;
    __half* p16 = tgt16 + (size_t)row*C_;
    const float* r = resid + (size_t)row*C_;
    float v[3];
    float sum = 0.f;
    #pragma unroll
    for (int i = 0; i < 3; i++){ v[i] = p[t + i*256] + r[t + i*256]; sum += v[i]; }
    __shared__ float red[256];
    red[t] = sum; __syncthreads();
    for (int s = 128; s; s >>= 1){ if (t < s) red[t] += red[t + s]; __syncthreads(); }
    float m = red[0] * (1.f/768.f);
    __syncthreads();
    float s2 = 0.f;
    #pragma unroll
    for (int i = 0; i < 3; i++){ float d = v[i] - m; s2 += d*d; }
    red[t] = s2; __syncthreads();
    for (int s = 128; s; s >>= 1){ if (t < s) red[t] += red[t + s]; __syncthreads(); }
    float var = red[0] * (1.f/768.f);
    float rstd = rsqrtf(var + 1e-5f);
    #pragma unroll
    for (int i = 0; i < 3; i++){
        int c = t + i*256;
        float o = (v[i] - m)*rstd*w[c] + bb[c];
        p[c] = o;
        p16[c] = __float2half_rn(o);
    }
}

// ---------------- final transpose ----------------
__global__ void transpose_out_kernel(const float* __restrict__ tgt, float* __restrict__ out){
    __shared__ float tile[32][33];
    int c0 = blockIdx.x*32, t0 = blockIdx.y*32, b = blockIdx.z;
    for (int i = threadIdx.y; i < 32; i += 8)
        tile[i][threadIdx.x] = tgt[((size_t)b*T_ + t0 + i)*C_ + c0 + threadIdx.x];
    __syncthreads();
    for (int i = threadIdx.y; i < 32; i += 8)
        out[((size_t)b*C_ + c0 + i)*T_ + t0 + threadIdx.x] = tile[threadIdx.x][i];
}

// ---------------- launch ----------------
extern "C" void kernel_launch(void* const* d_in, const int* in_sizes, int n_in,
                              void* d_out, int out_size){
    const float* mainx      = (const float*)d_in[0];
    const float* others[2]  = {(const float*)d_in[1], (const float*)d_in[2]};
    const float* pe         = (const float*)d_in[3];
    const float* mq         = (const float*)d_in[4];
    const float* s_w1       = (const float*)d_in[5];
    const float* s_b1       = (const float*)d_in[6];
    const float* s_w2       = (const float*)d_in[7];
    const float* s_b2       = (const float*)d_in[8];
    const float* sa_in_w    = (const float*)d_in[9];
    const float* sa_in_b    = (const float*)d_in[10];
    const float* sa_out_w   = (const float*)d_in[11];
    const float* sa_out_b   = (const float*)d_in[12];
    const float* ca_in_w    = (const float*)d_in[13];
    const float* ca_in_b    = (const float*)d_in[14];
    const float* ca_out_w   = (const float*)d_in[15];
    const float* ca_out_b   = (const float*)d_in[16];
    const float* ff1_w      = (const float*)d_in[17];
    const float* ff1_b      = (const float*)d_in[18];
    const float* ff2_w      = (const float*)d_in[19];
    const float* ff2_b      = (const float*)d_in[20];
    const float* ln_w       = (const float*)d_in[21];
    const float* ln_b       = (const float*)d_in[22];
    const float* block_rand = (const float*)d_in[23];
    const float* around_rand= (const float*)d_in[24];
    float* out = (float*)d_out;

    float *pf0, *hid0, *mainxT, *coords, *score, *tgt, *tmp, *ffh, *memkv, *qb, *exsc;
    int *topidx, *top16;
    __half *qkv16, *pf16, *tgt16, *attn16, *memb16, *ffh16, *wt;
    cudaGetSymbolAddress((void**)&pf0,    g_pf);
    cudaGetSymbolAddress((void**)&hid0,   g_hid);
    cudaGetSymbolAddress((void**)&mainxT, g_mainxT);
    cudaGetSymbolAddress((void**)&coords, g_coords);
    cudaGetSymbolAddress((void**)&score,  g_score);
    cudaGetSymbolAddress((void**)&top16,  g_top16);
    cudaGetSymbolAddress((void**)&exsc,   g_exsc);
    cudaGetSymbolAddress((void**)&topidx, g_topidx);
    cudaGetSymbolAddress((void**)&tgt,    g_tgt);
    cudaGetSymbolAddress((void**)&tmp,    g_tmp);
    cudaGetSymbolAddress((void**)&ffh,    g_ffh);
    cudaGetSymbolAddress((void**)&memkv,  g_memkv);
    cudaGetSymbolAddress((void**)&qb,     g_q);
    cudaGetSymbolAddress((void**)&qkv16,  g_qkv16);
    cudaGetSymbolAddress((void**)&pf16,   g_pf16);
    cudaGetSymbolAddress((void**)&tgt16,  g_tgt16);
    cudaGetSymbolAddress((void**)&attn16, g_attn16);
    cudaGetSymbolAddress((void**)&memb16, g_memb16);
    cudaGetSymbolAddress((void**)&ffh16,  g_ffh16);
    cudaGetSymbolAddress((void**)&wt,     g_wt);

    size_t o = 0;
    __half* wtS = wt + o; o += (size_t)768*768;
    __half *wtSAin[L_], *wtSAout[L_], *wtCAin[L_], *wtCAout[L_], *wtFF1[L_], *wtFF2[L_];
    for (int l = 0; l < L_; l++){
        wtSAin[l]  = wt + o; o += (size_t)2304*768;
        wtSAout[l] = wt + o; o += (size_t)768*768;
        wtCAin[l]  = wt + o; o += (size_t)2304*768;
        wtCAout[l] = wt + o; o += (size_t)768*768;
        wtFF1[l]   = wt + o; o += (size_t)3072*768;
        wtFF2[l]   = wt + o; o += (size_t)768*3072;
    }

    float* pf1  = ffh;
    float* hid1 = ffh + (size_t)B_*NPTS*C_;
    float* memkvL[2] = { memkv, memkv + (size_t)B_*10*2*C_ };

    cudaFuncSetAttribute(flash_attn_kernel, cudaFuncAttributeMaxDynamicSharedMemorySize, FA_SMEM_B);

    static cudaStream_t s_m[2] = {nullptr, nullptr};
    static cudaEvent_t  ev_start = nullptr, ev_m[2] = {nullptr, nullptr};
    static cudaEvent_t  ev_w = nullptr, ev_k[2] = {nullptr, nullptr};
    if (s_m[0] == nullptr){
        cudaStreamCreateWithFlags(&s_m[0], cudaStreamNonBlocking);
        cudaStreamCreateWithFlags(&s_m[1], cudaStreamNonBlocking);
        cudaEventCreateWithFlags(&ev_start, cudaEventDisableTiming);
        cudaEventCreateWithFlags(&ev_m[0], cudaEventDisableTiming);
        cudaEventCreateWithFlags(&ev_m[1], cudaEventDisableTiming);
        cudaEventCreateWithFlags(&ev_w, cudaEventDisableTiming);
        cudaEventCreateWithFlags(&ev_k[0], cudaEventDisableTiming);
        cudaEventCreateWithFlags(&ev_k[1], cudaEventDisableTiming);
    }

    // pre-fork work side streams depend on: score weight + mainxT
    transpose_w(s_w1, wtS, 768, 768, 0);
    {
        dim3 g(C_/32, T_/32, B_); dim3 bl(32, 8);
        transpose_in_kernel<<<g, bl>>>(mainx, mainxT);
    }
    cudaEventRecord(ev_start, 0);

    // ---- fork: modality pipelines ----
    float*  pfs[2]   = {pf0, pf1};
    float*  hids[2]  = {hid0, hid1};
    for (int i = 0; i < 2; i++){
        cudaStream_t st = s_m[i];
        cudaStreamWaitEvent(st, ev_start, 0);
        float*  pf_i   = pfs[i];
        __half* pf16_i = pf16 + (size_t)i*B_*NPTS*C_;
        float*  hid_i  = hids[i];
        float* coords_i = coords + (size_t)i*B_*NPTS*2;
        float* score_i  = score  + (size_t)i*B_*NPTS;
        int*   top16_i  = top16  + i*B_*NCAND;
        float* exsc_i   = exsc   + i*B_*NCAND;
        int*   topidx_i = topidx + i*B_*TOPK_;
        {
            dim3 g(C_/32, T_/32, B_); dim3 bl(32, 8);
            transpose_in_kernel<<<g, bl, 0, st>>>(others[i], hid_i);
        }
        sample_kernel<<<B_*NPTS/16, 256, 0, st>>>(hid_i, block_rand + (size_t)i*B_*32*32*2*2,
                                                  pf_i, pf16_i, coords_i);
        zero_score_kernel<<<(B_*NPTS + 255)/256, 256, 0, st>>>(score_i);
        h_gemm<2>(pf16_i, wtS, s_b1, nullptr, nullptr, s_w2, score_i,
                  B_*NPTS, C_, C_, C_, C_, 0, st);
        topk_kernel<<<B_, 256, 0, st>>>(score_i, top16_i, NCAND);
        rescore_kernel<<<B_*NCAND, 256, 0, st>>>(pf_i, s_w1, s_b1, s_w2, top16_i, exsc_i);
        final_top5_kernel<<<B_, 32, 0, st>>>(exsc_i, top16_i, topidx_i);
        soft_align_kernel<<<B_*TOPK_, 256, 0, st>>>(mainxT, pe,
                                                    around_rand + (size_t)i*B_*AROUND_*TOPK_*2,
                                                    mq + (size_t)(i+1)*C_,
                                                    pf_i, coords_i, topidx_i, memb16, i*TOPK_);
        cudaEventRecord(ev_m[i], st);
    }

    // ---- decoder weight transposes (ONE batched launch) + prefix on main stream ----
    {
        WTJobs jobs;
        for (int l = 0; l < L_; l++){
            jobs.src[l*6+0] = sa_in_w  + (size_t)l*C_*3*C_; jobs.dst[l*6+0] = wtSAin[l];  jobs.K[l*6+0] = 768;  jobs.N[l*6+0] = 2304;
            jobs.src[l*6+1] = sa_out_w + (size_t)l*C_*C_;   jobs.dst[l*6+1] = wtSAout[l]; jobs.K[l*6+1] = 768;  jobs.N[l*6+1] = 768;
            jobs.src[l*6+2] = ca_in_w  + (size_t)l*C_*3*C_; jobs.dst[l*6+2] = wtCAin[l];  jobs.K[l*6+2] = 768;  jobs.N[l*6+2] = 2304;
            jobs.src[l*6+3] = ca_out_w + (size_t)l*C_*C_;   jobs.dst[l*6+3] = wtCAout[l]; jobs.K[l*6+3] = 768;  jobs.N[l*6+3] = 768;
            jobs.src[l*6+4] = ff1_w    + (size_t)l*C_*FF_;  jobs.dst[l*6+4] = wtFF1[l];   jobs.K[l*6+4] = 768;  jobs.N[l*6+4] = 3072;
            jobs.src[l*6+5] = ff2_w    + (size_t)l*FF_*C_;  jobs.dst[l*6+5] = wtFF2[l];   jobs.K[l*6+5] = 3072; jobs.N[l*6+5] = 768;
        }
        dim3 g(2304, 12); dim3 bl(32, 8);
        transpose_w_all_kernel<<<g, bl>>>(jobs);
        cudaEventRecord(ev_w, 0);
    }
    tgt_init_kernel<<<(int)(((size_t)B_*T_*C_ + 255)/256), 256>>>(mainxT, mq, pe, tgt, tgt16);

    // memkv GEMMs on side streams (need memb16 from BOTH streams + weights)
    for (int l = 0; l < L_; l++){
        cudaStream_t st = s_m[l];
        cudaStreamWaitEvent(st, ev_m[0], 0);
        cudaStreamWaitEvent(st, ev_m[1], 0);
        cudaStreamWaitEvent(st, ev_w, 0);
        h_gemm<0>(memb16, wtCAin[l] + (size_t)768*C_, ca_in_b + (size_t)l*3*C_ + C_, memkvL[l],
                  nullptr, nullptr, nullptr, B_*10, 2*C_, C_, C_, C_, 2*C_, st);
        cudaEventRecord(ev_k[l], st);
    }

    // layer 0 SA block + CA-q (no memb dependency)
    h_gemm<3>(tgt16, wtSAin[0], sa_in_b, nullptr, qkv16, nullptr, nullptr,
              B_*T_, 3*C_, C_, C_, C_, 3*C_, 0);
    { dim3 g(T_/128, B_*NHEAD_); flash_attn_kernel<<<g, 256, FA_SMEM_B>>>(qkv16, attn16); }
    h_gemm<0>(attn16, wtSAout[0], sa_out_b, tmp, nullptr, nullptr, nullptr,
              B_*T_, C_, C_, C_, C_, C_, 0);
    add_ln_kernel<<<B_*T_, 256>>>(tgt, tgt16, tmp, ln_w, ln_b);
    h_gemm<0>(tgt16, wtCAin[0], ca_in_b, qb, nullptr, nullptr, nullptr,
              B_*T_, C_, C_, C_, C_, C_, 0);

    for (int l = 0; l < L_; l++){
        if (l > 0){
            h_gemm<3>(tgt16, wtSAin[l], sa_in_b + (size_t)l*3*C_, nullptr, qkv16, nullptr, nullptr,
                      B_*T_, 3*C_, C_, C_, C_, 3*C_, 0);
            { dim3 g(T_/128, B_*NHEAD_); flash_attn_kernel<<<g, 256, FA_SMEM_B>>>(qkv16, attn16); }
            h_gemm<0>(attn16, wtSAout[l], sa_out_b + (size_t)l*C_, tmp, nullptr, nullptr, nullptr,
                      B_*T_, C_, C_, C_, C_, C_, 0);
            add_ln_kernel<<<B_*T_, 256>>>(tgt, tgt16, tmp, ln_w + (size_t)(l*3+0)*C_, ln_b + (size_t)(l*3+0)*C_);
            h_gemm<0>(tgt16, wtCAin[l], ca_in_b + (size_t)l*3*C_, qb, nullptr, nullptr, nullptr,
                      B_*T_, C_, C_, C_, C_, C_, 0);
        }
        cudaStreamWaitEvent(0, ev_k[l], 0);
        { dim3 g(T_/256, B_*NHEAD_); ca_attn_kernel<<<g, 256>>>(qb, memkvL[l], attn16); }
        h_gemm<0>(attn16, wtCAout[l], ca_out_b + (size_t)l*C_, tmp, nullptr, nullptr, nullptr,
                  B_*T_, C_, C_, C_, C_, C_, 0);
        add_ln_kernel<<<B_*T_, 256>>>(tgt, tgt16, tmp, ln_w + (size_t)(l*3+1)*C_, ln_b + (size_t)(l*3+1)*C_);

        h_gemm<1>(tgt16, wtFF1[l], ff1_b + (size_t)l*FF_, nullptr, ffh16, nullptr, nullptr,
                  B_*T_, FF_, C_, C_, C_, FF_, 0);
        h_gemm<0>(ffh16, wtFF2[l], ff2_b + (size_t)l*C_, tmp, nullptr, nullptr, nullptr,
                  B_*T_, C_, FF_, FF_, FF_, C_, 0);
        add_ln_kernel<<<B_*T_, 256>>>(tgt, tgt16, tmp, ln_w + (size_t)(l*3+2)*C_, ln_b + (size_t)(l*3+2)*C_);
    }

    {
        dim3 g(C_/32, T_/32, B_); dim3 bl(32, 8);
        transpose_out_kernel<<<g, bl>>>(tgt, out);
    }
}

// round 16
// speedup vs baseline: 1.2482x; 1.0449x over previous
#include <cuda_runtime.h>
#include <cuda_fp16.h>
#include <math.h>
#include <stdint.h>

// ---------------- constants ----------------
#define B_   8
#define C_   768
#define T_   1024
#define L_   2
#define FF_  3072
#define NPTS 2048
#define TOPK_ 5
#define NCAND 16
#define AROUND_ 5
#define NHEAD_ 8
#define HD_  96

// ---------------- scratch ----------------
__device__ float g_pf    [(size_t)B_*NPTS*C_];
__device__ float g_hid   [(size_t)B_*NPTS*C_];
__device__ float g_mainxT[(size_t)B_*T_*C_];
__device__ float g_coords[2*(size_t)B_*NPTS*2];
__device__ float g_score [2*(size_t)B_*NPTS];
__device__ int   g_top16 [2*B_*NCAND];
__device__ float g_exsc  [2*B_*NCAND];
__device__ int   g_topidx[2*B_*TOPK_];
__device__ float g_tgt   [(size_t)B_*T_*C_];
__device__ float g_tmp   [(size_t)B_*T_*C_];
__device__ float g_ffh   [(size_t)B_*T_*FF_];      // phase-A scratch: pf1 + xT1
__device__ float g_memkv [2*(size_t)B_*10*2*C_];   // per-layer buffers
__device__ float g_q     [(size_t)B_*T_*C_];
// fp16 mirrors / weights
__device__ __align__(256) __half g_qkv16 [(size_t)B_*T_*3*C_];
__device__ __align__(256) __half g_pf16  [2*(size_t)B_*NPTS*C_];
__device__ __align__(256) __half g_tgt16 [(size_t)B_*T_*C_];
__device__ __align__(256) __half g_attn16[(size_t)B_*T_*C_];
__device__ __align__(256) __half g_memb16[(size_t)B_*10*C_];
__device__ __align__(256) __half g_ffh16 [(size_t)B_*T_*FF_];
__device__ __align__(256) __half g_wt    [19464192];

// ---------------- fp16 mma (m16n8k16) ----------------
__device__ __forceinline__ void mma16(float* d, const uint32_t* a, const uint32_t* b){
    asm volatile("mma.sync.aligned.m16n8k16.row.col.f32.f16.f16.f32 "
        "{%0,%1,%2,%3},{%4,%5,%6,%7},{%8,%9},{%0,%1,%2,%3};\n"
        : "+f"(d[0]), "+f"(d[1]), "+f"(d[2]), "+f"(d[3])
        : "r"(a[0]), "r"(a[1]), "r"(a[2]), "r"(a[3]), "r"(b[0]), "r"(b[1]));
}

// ---------------- fp16 GEMM: 128 threads, 2x2 warps, 64x64 tiles, k64 stages ----------------
// MODE 0: fp32 C out. MODE 1: relu + half C16 out. MODE 2: score. MODE 3: half C16, no relu.
#define H_STRIDE_W 36          // 32-bit words per row (64 halves + 8 pad)
#define H_ROW_B    144
#define H_STAGE_B  (128*H_ROW_B*2)   // 36864 B (A + B halves)
#define H_SMEM_B   (3*H_STAGE_B)     // 110592 B

template<int MODE>
__global__ __launch_bounds__(128, 2)
void h_gemm_kernel(const __half* __restrict__ A, const __half* __restrict__ WT,
                   const float* __restrict__ bias, float* __restrict__ C,
                   __half* __restrict__ C16, const float* __restrict__ w2,
                   float* __restrict__ score,
                   int M, int N, int K, int lda, int ldb, int ldc)
{
    extern __shared__ char smraw[];

    int tid = threadIdx.x, lane = tid & 31, warp = tid >> 5;
    int gid = lane >> 2, tig = lane & 3;
    int wm = warp >> 1, wn = warp & 1;
    int row0 = blockIdx.y * 128, col0 = blockIdx.x * 128;

    float acc[4][8][4];
    #pragma unroll
    for (int i = 0; i < 4; i++)
        #pragma unroll
        for (int j = 0; j < 8; j++)
            #pragma unroll
            for (int r = 0; r < 4; r++) acc[i][j][r] = 0.f;

    int crow[8], cseg[8], assz[8], acar[8];
    #pragma unroll
    for (int i = 0; i < 8; i++){
        int idx = tid + i*128;
        crow[i] = idx >> 3; cseg[i] = idx & 7;
        assz[i] = (row0 + crow[i] < M) ? 16 : 0;
        acar[i] = assz[i] ? row0 + crow[i] : 0;
    }

    auto issue_stage = [&](int stage, int k0){
        char* Ab = smraw + stage*H_STAGE_B;
        char* Bb = Ab + 128*H_ROW_B;
        #pragma unroll
        for (int i = 0; i < 8; i++){
            uint32_t d = (uint32_t)__cvta_generic_to_shared(Ab + crow[i]*H_ROW_B + cseg[i]*16);
            const __half* s = A + (size_t)acar[i]*lda + k0 + cseg[i]*8;
            asm volatile("cp.async.cg.shared.global [%0], [%1], 16, %2;\n" :: "r"(d), "l"(s), "r"(assz[i]));
        }
        #pragma unroll
        for (int i = 0; i < 8; i++){
            uint32_t d = (uint32_t)__cvta_generic_to_shared(Bb + crow[i]*H_ROW_B + cseg[i]*16);
            const __half* s = WT + (size_t)(col0 + crow[i])*ldb + k0 + cseg[i]*8;
            asm volatile("cp.async.cg.shared.global [%0], [%1], 16;\n" :: "r"(d), "l"(s));
        }
        asm volatile("cp.async.commit_group;\n" ::: "memory");
    };

    auto compute = [&](int stage){
        const uint32_t* As = (const uint32_t*)(smraw + stage*H_STAGE_B);
        const uint32_t* Bs = As + 128*H_STRIDE_W;
        #pragma unroll
        for (int kk = 0; kk < 4; kk++){
            int kw = kk*8 + tig;
            uint32_t af[4][4], bf[8][2];
            #pragma unroll
            for (int ma = 0; ma < 4; ma++){
                int m = wm*64 + ma*16 + gid;
                af[ma][0] = As[m*H_STRIDE_W + kw];
                af[ma][1] = As[(m+8)*H_STRIDE_W + kw];
                af[ma][2] = As[m*H_STRIDE_W + kw + 4];
                af[ma][3] = As[(m+8)*H_STRIDE_W + kw + 4];
            }
            #pragma unroll
            for (int na = 0; na < 8; na++){
                int n = wn*64 + na*8 + gid;
                bf[na][0] = Bs[n*H_STRIDE_W + kw];
                bf[na][1] = Bs[n*H_STRIDE_W + kw + 4];
            }
            #pragma unroll
            for (int ma = 0; ma < 4; ma++)
                #pragma unroll
                for (int na = 0; na < 8; na++)
                    mma16(acc[ma][na], af[ma], bf[na]);
        }
    };

    int nc = K / 64;
    issue_stage(0, 0);
    issue_stage(1, 64);
    for (int it = 0; it < nc; it++){
        asm volatile("cp.async.wait_group 1;\n" ::: "memory");
        __syncthreads();
        int nxt = it + 2;
        if (nxt < nc){
            int st = nxt % 3;
            issue_stage(st, nxt*64);
        } else {
            asm volatile("cp.async.commit_group;\n" ::: "memory");
        }
        compute(it % 3);
    }

    #pragma unroll
    for (int ma = 0; ma < 4; ma++){
        int r0 = row0 + wm*64 + ma*16 + gid;
        float s0 = 0.f, s1 = 0.f;
        #pragma unroll
        for (int na = 0; na < 8; na++){
            int c = col0 + wn*64 + na*8 + 2*tig;
            float b0 = bias ? bias[c] : 0.f;
            float b1 = bias ? bias[c+1] : 0.f;
            float x0 = acc[ma][na][0] + b0;
            float x1 = acc[ma][na][1] + b1;
            float x2 = acc[ma][na][2] + b0;
            float x3 = acc[ma][na][3] + b1;
            if (MODE == 1 || MODE == 2){
                x0 = fmaxf(x0, 0.f); x1 = fmaxf(x1, 0.f);
                x2 = fmaxf(x2, 0.f); x3 = fmaxf(x3, 0.f);
            }
            if (MODE == 2){
                float w0 = w2[c], w1 = w2[c+1];
                s0 += x0*w0 + x1*w1;
                s1 += x2*w0 + x3*w1;
            } else if (MODE == 1 || MODE == 3){
                if (r0 < M)     *(__half2*)&C16[(size_t)r0*ldc + c]     = __floats2half2_rn(x0, x1);
                if (r0 + 8 < M) *(__half2*)&C16[(size_t)(r0+8)*ldc + c] = __floats2half2_rn(x2, x3);
            } else {
                if (r0 < M){ float2 o = make_float2(x0, x1); *(float2*)&C[(size_t)r0*ldc + c] = o; }
                if (r0 + 8 < M){ float2 o = make_float2(x2, x3); *(float2*)&C[(size_t)(r0+8)*ldc + c] = o; }
            }
        }
        if (MODE == 2){
            s0 += __shfl_xor_sync(0xffffffffu, s0, 1);
            s0 += __shfl_xor_sync(0xffffffffu, s0, 2);
            s1 += __shfl_xor_sync(0xffffffffu, s1, 1);
            s1 += __shfl_xor_sync(0xffffffffu, s1, 2);
            if (tig == 0){
                if (r0 < M)     atomicAdd(&score[r0], s0);
                if (r0 + 8 < M) atomicAdd(&score[r0 + 8], s1);
            }
        }
    }
}

template<int MODE>
static void h_gemm(const __half* A, const __half* WT, const float* bias, float* C,
                   __half* C16, const float* w2, float* score,
                   int M, int N, int K, int lda, int ldb, int ldc, cudaStream_t st){
    cudaFuncSetAttribute(h_gemm_kernel<MODE>, cudaFuncAttributeMaxDynamicSharedMemorySize, H_SMEM_B);
    dim3 grid(N/128, (M + 127)/128);
    h_gemm_kernel<MODE><<<grid, 128, H_SMEM_B, st>>>(A, WT, bias, C, C16, w2, score, M, N, K, lda, ldb, ldc);
}

// ---------------- weight transpose+convert (single + batched) ----------------
__device__ __forceinline__ void wt_tile(const float* W, __half* WT, int K, int N,
                                        int n0, int k0, float tile[32][33]){
    for (int i = threadIdx.y; i < 32; i += 8)
        tile[i][threadIdx.x] = W[(size_t)(k0 + i)*N + n0 + threadIdx.x];
    __syncthreads();
    for (int i = threadIdx.y; i < 32; i += 8)
        WT[(size_t)(n0 + i)*K + k0 + threadIdx.x] = __float2half_rn(tile[threadIdx.x][i]);
}

__global__ void transpose_w_kernel(const float* __restrict__ W, __half* __restrict__ WT,
                                   int K, int N){
    __shared__ float tile[32][33];
    wt_tile(W, WT, K, N, blockIdx.x*32, blockIdx.y*32, tile);
}
static void transpose_w(const float* W, __half* WT, int K, int N, cudaStream_t st){
    dim3 g(N/32, K/32); dim3 bl(32, 8);
    transpose_w_kernel<<<g, bl, 0, st>>>(W, WT, K, N);
}

struct WTJobs {
    const float* src[12];
    __half*      dst[12];
    int K[12];
    int N[12];
};
__global__ void transpose_w_all_kernel(WTJobs jobs){
    __shared__ float tile[32][33];
    int j = blockIdx.y;
    int K = jobs.K[j], N = jobs.N[j];
    int tilesX = N >> 5;
    int t = blockIdx.x;
    if (t >= tilesX * (K >> 5)) return;
    int n0 = (t % tilesX)*32, k0 = (t / tilesX)*32;
    wt_tile(jobs.src[j], jobs.dst[j], K, N, n0, k0, tile);
}

// ---------------- flash attention (fp16 mma, online softmax) ----------------
#define FA_KS_STR 136
#define FA_VS_STR 104
#define FA_SMEM_B ((48*136 + 64*104 + 64*136)*4)
#define FA_LOG2E 1.4426950408889634f

__global__ __launch_bounds__(256, 1)
void flash_attn_kernel(const __half* __restrict__ qkv, __half* __restrict__ out16){
    extern __shared__ uint32_t sm32[];
    uint32_t* Ks = sm32;
    uint32_t* Vs = Ks + 48*FA_KS_STR;
    uint32_t* Ps = Vs + 64*FA_VS_STR;

    int qt = blockIdx.x, bh = blockIdx.y, b = bh >> 3, h = bh & 7;
    int tid = threadIdx.x, lane = tid & 31, warp = tid >> 5;
    int gid = lane >> 2, tig = lane & 3;
    int m0 = warp * 16;
    int q0 = qt * 128;
    const float iscale = 0.10206207261596577f;

    uint32_t qf[6][4];
    {
        const __half* Qa = qkv + (size_t)(b*T_ + q0 + m0 + gid)*(3*C_) + h*HD_;
        const __half* Qb = Qa + 8*(3*C_);
        #pragma unroll
        for (int kk = 0; kk < 6; kk++){
            qf[kk][0] = *(const uint32_t*)&Qa[(kk*8 + tig)*2];
            qf[kk][1] = *(const uint32_t*)&Qb[(kk*8 + tig)*2];
            qf[kk][2] = *(const uint32_t*)&Qa[(kk*8 + tig + 4)*2];
            qf[kk][3] = *(const uint32_t*)&Qb[(kk*8 + tig + 4)*2];
        }
    }

    float oacc[12][4];
    #pragma unroll
    for (int i = 0; i < 12; i++)
        #pragma unroll
        for (int j = 0; j < 4; j++) oacc[i][j] = 0.f;
    float mrow0 = -1e30f, mrow1 = -1e30f, lrow0 = 0.f, lrow1 = 0.f;

    for (int kt = 0; kt < 8; kt++){
        __syncthreads();
        {
            const __half* Kb = qkv + (size_t)(b*T_ + kt*128)*(3*C_) + C_ + h*HD_;
            const __half* Vb = Kb + C_;
            for (int idx = tid; idx < 128*48; idx += 256){
                int r = idx / 48, d = idx % 48;
                Ks[d*FA_KS_STR + r] = *(const uint32_t*)&Kb[(size_t)r*(3*C_) + d*2];
            }
            for (int idx = tid; idx < 64*96; idx += 256){
                int p = idx / 96, n = idx % 96;
                __half lo = Vb[(size_t)(2*p)*(3*C_) + n];
                __half hi = Vb[(size_t)(2*p + 1)*(3*C_) + n];
                __half2 hv = __halves2half2(lo, hi);
                Vs[p*FA_VS_STR + n] = *(const uint32_t*)&hv;
            }
        }
        __syncthreads();

        float sacc[16][4];
        #pragma unroll
        for (int nf = 0; nf < 16; nf++)
            #pragma unroll
            for (int j = 0; j < 4; j++) sacc[nf][j] = 0.f;
        #pragma unroll
        for (int kk = 0; kk < 6; kk++){
            int k1 = (kk*8 + tig)*FA_KS_STR, k2 = (kk*8 + tig + 4)*FA_KS_STR;
            #pragma unroll
            for (int nf = 0; nf < 16; nf++){
                uint32_t bfr[2] = { Ks[k1 + nf*8 + gid], Ks[k2 + nf*8 + gid] };
                mma16(sacc[nf], qf[kk], bfr);
            }
        }
        #pragma unroll
        for (int nf = 0; nf < 16; nf++){
            sacc[nf][0] *= iscale; sacc[nf][1] *= iscale;
            sacc[nf][2] *= iscale; sacc[nf][3] *= iscale;
        }

        float rm0 = -1e30f, rm1 = -1e30f;
        #pragma unroll
        for (int nf = 0; nf < 16; nf++){
            rm0 = fmaxf(rm0, fmaxf(sacc[nf][0], sacc[nf][1]));
            rm1 = fmaxf(rm1, fmaxf(sacc[nf][2], sacc[nf][3]));
        }
        rm0 = fmaxf(rm0, __shfl_xor_sync(0xffffffffu, rm0, 1));
        rm0 = fmaxf(rm0, __shfl_xor_sync(0xffffffffu, rm0, 2));
        rm1 = fmaxf(rm1, __shfl_xor_sync(0xffffffffu, rm1, 1));
        rm1 = fmaxf(rm1, __shfl_xor_sync(0xffffffffu, rm1, 2));
        float mn0 = fmaxf(mrow0, rm0), mn1 = fmaxf(mrow1, rm1);
        float al0 = exp2f((mrow0 - mn0)*FA_LOG2E);
        float al1 = exp2f((mrow1 - mn1)*FA_LOG2E);
        mrow0 = mn0; mrow1 = mn1;
        float rs0 = 0.f, rs1 = 0.f;
        #pragma unroll
        for (int nf = 0; nf < 16; nf++){
            float p0 = exp2f((sacc[nf][0] - mn0)*FA_LOG2E);
            float p1 = exp2f((sacc[nf][1] - mn0)*FA_LOG2E);
            float p2 = exp2f((sacc[nf][2] - mn1)*FA_LOG2E);
            float p3 = exp2f((sacc[nf][3] - mn1)*FA_LOG2E);
            sacc[nf][0] = p0; sacc[nf][1] = p1; sacc[nf][2] = p2; sacc[nf][3] = p3;
            rs0 += p0 + p1; rs1 += p2 + p3;
        }
        rs0 += __shfl_xor_sync(0xffffffffu, rs0, 1);
        rs0 += __shfl_xor_sync(0xffffffffu, rs0, 2);
        rs1 += __shfl_xor_sync(0xffffffffu, rs1, 1);
        rs1 += __shfl_xor_sync(0xffffffffu, rs1, 2);
        lrow0 = lrow0*al0 + rs0;
        lrow1 = lrow1*al1 + rs1;
        #pragma unroll
        for (int nf = 0; nf < 12; nf++){
            oacc[nf][0] *= al0; oacc[nf][1] *= al0;
            oacc[nf][2] *= al1; oacc[nf][3] *= al1;
        }

        #pragma unroll
        for (int nf = 0; nf < 16; nf++){
            int cp = nf*4 + tig;
            __half2 h0 = __floats2half2_rn(sacc[nf][0], sacc[nf][1]);
            __half2 h1 = __floats2half2_rn(sacc[nf][2], sacc[nf][3]);
            Ps[cp*FA_KS_STR + m0 + gid]     = *(const uint32_t*)&h0;
            Ps[cp*FA_KS_STR + m0 + gid + 8] = *(const uint32_t*)&h1;
        }
        __syncwarp();

        #pragma unroll
        for (int kk = 0; kk < 8; kk++){
            int k1 = (kk*8 + tig)*FA_KS_STR, k2 = (kk*8 + tig + 4)*FA_KS_STR;
            uint32_t pa[4] = { Ps[k1 + m0 + gid], Ps[k1 + m0 + gid + 8],
                               Ps[k2 + m0 + gid], Ps[k2 + m0 + gid + 8] };
            int v1 = (kk*8 + tig)*FA_VS_STR, v2 = (kk*8 + tig + 4)*FA_VS_STR;
            #pragma unroll
            for (int nf = 0; nf < 12; nf++){
                uint32_t vb2[2] = { Vs[v1 + nf*8 + gid], Vs[v2 + nf*8 + gid] };
                mma16(oacc[nf], pa, vb2);
            }
        }
    }

    float inv0 = 1.f / lrow0, inv1 = 1.f / lrow1;
    size_t r0 = (size_t)(b*T_ + q0 + m0 + gid);
    #pragma unroll
    for (int nf = 0; nf < 12; nf++){
        int col = h*HD_ + nf*8 + 2*tig;
        *(__half2*)&out16[r0*C_ + col]       = __floats2half2_rn(oacc[nf][0]*inv0, oacc[nf][1]*inv0);
        *(__half2*)&out16[(r0 + 8)*C_ + col] = __floats2half2_rn(oacc[nf][2]*inv1, oacc[nf][3]*inv1);
    }
}

// ---------------- transpose x [B,C,T] -> xT [B,T,C] ----------------
__global__ void transpose_in_kernel(const float* __restrict__ x, float* __restrict__ xT){
    __shared__ float tile[32][33];
    int c0 = blockIdx.x*32, t0 = blockIdx.y*32, b = blockIdx.z;
    for (int i = threadIdx.y; i < 32; i += 8)
        tile[i][threadIdx.x] = x[((size_t)b*C_ + c0 + i)*T_ + t0 + threadIdx.x];
    __syncthreads();
    for (int i = threadIdx.y; i < 32; i += 8)
        xT[((size_t)b*T_ + t0 + i)*C_ + c0 + threadIdx.x] = tile[threadIdx.x][i];
}

// ---------------- blockwise sampling (fp32 + fp16 out; zeroes score) ----------------
__global__ void sample_kernel(const float* __restrict__ xT, const float* __restrict__ brand,
                              float* __restrict__ pf, __half* __restrict__ pf16,
                              float* __restrict__ coords, float* __restrict__ score){
    int p0 = blockIdx.x * 16;
    __shared__ int   sidx[16][4];
    __shared__ float swt [16][4];
    int tid = threadIdx.x;
    if (tid < 16){
        int bn = p0 + tid;
        int b  = bn >> 11;
        int n  = bn & 2047;
        int k  = n & 1;
        int pw = (n >> 1) & 31;
        int ph = n >> 6;
        const float bs = 0.0625f;
        const float* br = brand + ((((size_t)b*32 + ph)*32 + pw)*2 + k)*2;
        float gx = br[0]*bs + (-1.0f + ph*bs);
        float gy = br[1]*bs + (-1.0f + pw*bs);
        coords[(size_t)bn*2]     = gx;
        coords[(size_t)bn*2 + 1] = gy;
        score[bn] = 0.f;
        float ix = ((gx + 1.0f)*32.0f - 1.0f)*0.5f;
        float iy = ((gy + 1.0f)*32.0f - 1.0f)*0.5f;
        float x0f = floorf(ix), y0f = floorf(iy);
        int x0 = (int)x0f, y0 = (int)y0f;
        float wx1 = ix - x0f, wy1 = iy - y0f;
        float wxs[2] = {1.f - wx1, wx1};
        float wys[2] = {1.f - wy1, wy1};
        #pragma unroll
        for (int j = 0; j < 4; j++){
            int xi = x0 + (j & 1), yi = y0 + (j >> 1);
            bool v = (xi >= 0) & (xi < 32) & (yi >= 0) & (yi < 32);
            sidx[tid][j] = v ? (yi*32 + xi) : 0;
            swt [tid][j] = v ? (wxs[j & 1]*wys[j >> 1]) : 0.f;
        }
    }
    __syncthreads();
    int b = (p0 >> 11);
    const float* base = xT + (size_t)b*T_*C_;
    for (int pt = 0; pt < 16; pt++){
        const float* r0 = base + (size_t)sidx[pt][0]*C_;
        const float* r1 = base + (size_t)sidx[pt][1]*C_;
        const float* r2 = base + (size_t)sidx[pt][2]*C_;
        const float* r3 = base + (size_t)sidx[pt][3]*C_;
        float w0 = swt[pt][0], w1 = swt[pt][1], w2 = swt[pt][2], w3 = swt[pt][3];
        float* dst = pf + (size_t)(p0 + pt)*C_;
        __half* dst16 = pf16 + (size_t)(p0 + pt)*C_;
        for (int c = tid; c < C_; c += 256){
            float v = r0[c]*w0 + r1[c]*w1 + r2[c]*w2 + r3[c]*w3;
            dst[c] = v;
            dst16[c] = __float2half_rn(v);
        }
    }
}

// ---------------- top-K ----------------
__global__ void topk_kernel(const float* __restrict__ score, int* __restrict__ topidx, int K){
    int b = blockIdx.x;
    __shared__ float sv[2048];
    __shared__ float rv[256];
    __shared__ int   ri[256];
    for (int j = threadIdx.x; j < 2048; j += 256) sv[j] = score[(size_t)b*2048 + j];
    __syncthreads();
    for (int t = 0; t < K; t++){
        float bv = -1e30f; int bi = 0x7fffffff;
        for (int j = threadIdx.x; j < 2048; j += 256){
            float v = sv[j];
            if (v > bv){ bv = v; bi = j; }
        }
        rv[threadIdx.x] = bv; ri[threadIdx.x] = bi;
        __syncthreads();
        for (int s = 128; s; s >>= 1){
            if (threadIdx.x < s){
                float v2 = rv[threadIdx.x + s]; int i2 = ri[threadIdx.x + s];
                if (v2 > rv[threadIdx.x] || (v2 == rv[threadIdx.x] && i2 < ri[threadIdx.x])){
                    rv[threadIdx.x] = v2; ri[threadIdx.x] = i2;
                }
            }
            __syncthreads();
        }
        if (threadIdx.x == 0){
            topidx[b*K + t] = ri[0];
            sv[ri[0]] = -1e30f;
        }
        __syncthreads();
    }
}

// ---------------- exact fp32 rescore ----------------
__global__ __launch_bounds__(256)
void rescore_kernel(const float* __restrict__ pf, const float* __restrict__ W1,
                    const float* __restrict__ b1, const float* __restrict__ w2,
                    const int* __restrict__ cand, float* __restrict__ exsc){
    int b = blockIdx.x >> 4, c = blockIdx.x & 15;
    int idx = cand[b*NCAND + c];
    __shared__ float spf[C_];
    int tid = threadIdx.x;
    for (int i = tid; i < C_; i += 256) spf[i] = pf[((size_t)b*NPTS + idx)*C_ + i];
    __syncthreads();
    float a0 = b1[tid], a1 = b1[tid+256], a2 = b1[tid+512];
    for (int k = 0; k < C_; k++){
        float v = spf[k];
        const float* w = W1 + (size_t)k*C_;
        a0 += v * w[tid];
        a1 += v * w[tid+256];
        a2 += v * w[tid+512];
    }
    float p = fmaxf(a0,0.f)*w2[tid] + fmaxf(a1,0.f)*w2[tid+256] + fmaxf(a2,0.f)*w2[tid+512];
    #pragma unroll
    for (int o = 16; o; o >>= 1) p += __shfl_down_sync(0xffffffffu, p, o);
    __shared__ float red[8];
    if ((tid & 31) == 0) red[tid >> 5] = p;
    __syncthreads();
    if (tid == 0){
        float s = 0.f;
        #pragma unroll
        for (int i = 0; i < 8; i++) s += red[i];
        exsc[b*NCAND + c] = s;
    }
}

// ---------------- final exact top-5 ----------------
__global__ void final_top5_kernel(const float* __restrict__ exsc, const int* __restrict__ cand,
                                  int* __restrict__ topidx){
    int b = blockIdx.x;
    if (threadIdx.x == 0){
        float s[NCAND]; int id[NCAND];
        for (int i = 0; i < NCAND; i++){ s[i] = exsc[b*NCAND + i]; id[i] = cand[b*NCAND + i]; }
        for (int t = 0; t < TOPK_; t++){
            int bi = 0;
            float bv = -1e30f; int bid = 0x7fffffff;
            for (int i = 0; i < NCAND; i++){
                if (s[i] > bv || (s[i] == bv && id[i] < bid)){ bv = s[i]; bid = id[i]; bi = i; }
            }
            topidx[b*TOPK_ + t] = id[bi];
            s[bi] = -1e30f;
        }
    }
}

// ---------------- soft_align (coalesced via mainxT; fp16 mem rows) ----------------
__global__ void soft_align_kernel(const float* __restrict__ mainxT, const float* __restrict__ pe,
                                  const float* __restrict__ arand, const float* __restrict__ mqrow,
                                  const float* __restrict__ pf, const float* __restrict__ coords,
                                  const int* __restrict__ topidx, __half* __restrict__ memo16, int rowBase){
    int b  = blockIdx.x / TOPK_;
    int nk = blockIdx.x % TOPK_;
    int idx = topidx[b*TOPK_ + nk];
    float px = coords[((size_t)b*NPTS + idx)*2 + 0];
    float py = coords[((size_t)b*NPTS + idx)*2 + 1];
    __shared__ float semb[AROUND_*C_];
    __shared__ float red[256];
    __shared__ float res[11];
    __shared__ float sw[AROUND_];

    int   aidx[AROUND_][4];
    float awt [AROUND_][4];
    #pragma unroll
    for (int a = 0; a < AROUND_; a++){
        const float* ar = arand + (((size_t)b*AROUND_ + a)*TOPK_ + nk)*2;
        float g0 = px + (ar[0]*2.f - 0.5f)*0.2f;
        float g1 = py + (ar[1]*2.f - 0.5f)*0.2f;
        g0 = fminf(fmaxf(g0, -1.f), 1.f);
        g1 = fminf(fmaxf(g1, -1.f), 1.f);
        float ix = ((g0 + 1.f)*32.f - 1.f)*0.5f;
        float iy = ((g1 + 1.f)*32.f - 1.f)*0.5f;
        float x0f = floorf(ix), y0f = floorf(iy);
        int x0 = (int)x0f, y0 = (int)y0f;
        float wx1 = ix - x0f, wy1 = iy - y0f;
        float wxs[2] = {1.f - wx1, wx1};
        float wys[2] = {1.f - wy1, wy1};
        #pragma unroll
        for (int j = 0; j < 4; j++){
            int xi = x0 + (j & 1), yi = y0 + (j >> 1);
            bool v = (xi >= 0) & (xi < 32) & (yi >= 0) & (yi < 32);
            aidx[a][j] = v ? (yi*32 + xi) : 0;
            awt [a][j] = v ? (wxs[j & 1]*wys[j >> 1]) : 0.f;
        }
    }
    const float* xbase = mainxT + (size_t)b*T_*C_;
    const float* pfrow = pf + ((size_t)b*NPTS + idx)*C_;
    float rep2 = 0.f, num[AROUND_], af2[AROUND_];
    #pragma unroll
    for (int a = 0; a < AROUND_; a++){ num[a] = 0.f; af2[a] = 0.f; }
    for (int c = threadIdx.x; c < C_; c += 256){
        float r = pfrow[c];
        rep2 += r*r;
        #pragma unroll
        for (int a = 0; a < AROUND_; a++){
            float af = awt[a][0]*xbase[(size_t)aidx[a][0]*C_ + c]
                     + awt[a][1]*xbase[(size_t)aidx[a][1]*C_ + c]
                     + awt[a][2]*xbase[(size_t)aidx[a][2]*C_ + c]
                     + awt[a][3]*xbase[(size_t)aidx[a][3]*C_ + c];
            num[a] += r*af;
            af2[a] += af*af;
            semb[a*C_ + c] = awt[a][0]*pe[(size_t)aidx[a][0]*C_ + c]
                           + awt[a][1]*pe[(size_t)aidx[a][1]*C_ + c]
                           + awt[a][2]*pe[(size_t)aidx[a][2]*C_ + c]
                           + awt[a][3]*pe[(size_t)aidx[a][3]*C_ + c];
        }
    }
    float vals[11];
    vals[0] = rep2;
    #pragma unroll
    for (int a = 0; a < AROUND_; a++){ vals[1+a] = num[a]; vals[6+a] = af2[a]; }
    for (int v = 0; v < 11; v++){
        red[threadIdx.x] = vals[v];
        __syncthreads();
        for (int s = 128; s; s >>= 1){
            if (threadIdx.x < s) red[threadIdx.x] += red[threadIdx.x + s];
            __syncthreads();
        }
        if (threadIdx.x == 0) res[v] = red[0];
        __syncthreads();
    }
    if (threadIdx.x == 0){
        float rn = fmaxf(sqrtf(res[0]), 1e-8f);
        float s[AROUND_]; float mx = -1e30f;
        for (int a = 0; a < AROUND_; a++){
            s[a] = res[1+a] / (rn * fmaxf(sqrtf(res[6+a]), 1e-8f));
            mx = fmaxf(mx, s[a]);
        }
        float ss = 0.f;
        for (int a = 0; a < AROUND_; a++){ s[a] = expf(s[a] - mx); ss += s[a]; }
        for (int a = 0; a < AROUND_; a++) sw[a] = s[a] / ss;
    }
    __syncthreads();
    float w0 = sw[0], w1 = sw[1], w2 = sw[2], w3 = sw[3], w4 = sw[4];
    for (int c = threadIdx.x; c < C_; c += 256){
        float o = pfrow[c] + mqrow[c];
        o += semb[0*C_ + c]*w0 + semb[1*C_ + c]*w1 + semb[2*C_ + c]*w2
           + semb[3*C_ + c]*w3 + semb[4*C_ + c]*w4;
        memo16[((size_t)b*10 + rowBase + nk)*C_ + c] = __float2half_rn(o);
    }
}

// ---------------- tgt init (from mainxT; fp32 + fp16) ----------------
__global__ void tgt_init_kernel(const float* __restrict__ mainxT, const float* __restrict__ mq,
                                const float* __restrict__ pe, float* __restrict__ tgt,
                                __half* __restrict__ tgt16){
    size_t i = (size_t)blockIdx.x*256 + threadIdx.x;
    int c = i % C_;
    size_t tc = i % ((size_t)T_*C_);
    float v = mainxT[i] + mq[c] + pe[tc];
    tgt[i] = v;
    tgt16[i] = __float2half_rn(v);
}

// ---------------- cross-attention (10 keys; half out) ----------------
__global__ void ca_attn_kernel(const float* __restrict__ q, const float* __restrict__ kv,
                               __half* __restrict__ out16){
    int bh = blockIdx.y, b = bh >> 3, h = bh & 7;
    int i = blockIdx.x*256 + threadIdx.x;
    __shared__ float Ks[10][96];
    __shared__ float Vsm[10][96];
    for (int idx = threadIdx.x; idx < 960; idx += 256){
        int j = idx / 96, d = idx % 96;
        Ks[j][d]  = kv[((size_t)b*10 + j)*(2*C_) + h*HD_ + d];
        Vsm[j][d] = kv[((size_t)b*10 + j)*(2*C_) + C_ + h*HD_ + d];
    }
    __syncthreads();
    const float* qr = q + ((size_t)b*T_ + i)*C_ + h*HD_;
    float s[10];
    #pragma unroll
    for (int j = 0; j < 10; j++) s[j] = 0.f;
    for (int d = 0; d < HD_; d++){
        float qd = qr[d];
        #pragma unroll
        for (int j = 0; j < 10; j++) s[j] += qd * Ks[j][d];
    }
    const float scale = 0.10206207261596577f;
    float mx = -1e30f;
    #pragma unroll
    for (int j = 0; j < 10; j++){ s[j] *= scale; mx = fmaxf(mx, s[j]); }
    float sum = 0.f;
    #pragma unroll
    for (int j = 0; j < 10; j++){ s[j] = expf(s[j] - mx); sum += s[j]; }
    float inv = 1.f / sum;
    #pragma unroll
    for (int j = 0; j < 10; j++) s[j] *= inv;
    __half* orow = out16 + ((size_t)b*T_ + i)*C_ + h*HD_;
    for (int d = 0; d < HD_; d++){
        float o = 0.f;
        #pragma unroll
        for (int j = 0; j < 10; j++) o += s[j] * Vsm[j][d];
        orow[d] = __float2half_rn(o);
    }
}

// ---------------- residual add + layernorm: warp per row, shuffle reductions ----------------
__global__ __launch_bounds__(256)
void add_ln_kernel(float* __restrict__ tgt, __half* __restrict__ tgt16,
                   const float* __restrict__ resid,
                   const float* __restrict__ w, const float* __restrict__ bb){
    int warp = threadIdx.x >> 5, lane = threadIdx.x & 31;
    int row = blockIdx.x*8 + warp;
    float* p = tgt + (size_t)row*C_;
    __half* p16 = tgt16 + (size_t)row*C_;
    const float* r = resid + (size_t)row*C_;
    float v[24];
    float sum = 0.f;
    #pragma unroll
    for (int i = 0; i < 24; i++){
        int c = lane + i*32;
        v[i] = p[c] + r[c];
        sum += v[i];
    }
    #pragma unroll
    for (int o = 16; o; o >>= 1) sum += __shfl_xor_sync(0xffffffffu, sum, o);
    float m = sum * (1.f/768.f);
    float s2 = 0.f;
    #pragma unroll
    for (int i = 0; i < 24; i++){ float d = v[i] - m; s2 += d*d; }
    #pragma unroll
    for (int o = 16; o; o >>= 1) s2 += __shfl_xor_sync(0xffffffffu, s2, o);
    float rstd = rsqrtf(s2 * (1.f/768.f) + 1e-5f);
    #pragma unroll
    for (int i = 0; i < 24; i++){
        int c = lane + i*32;
        float o = (v[i] - m)*rstd*w[c] + bb[c];
        p[c] = o;
        p16[c] = __float2half_rn(o);
    }
}

// ---------------- final transpose ----------------
__global__ void transpose_out_kernel(const float* __restrict__ tgt, float* __restrict__ out){
    __shared__ float tile[32][33];
    int c0 = blockIdx.x*32, t0 = blockIdx.y*32, b = blockIdx.z;
    for (int i = threadIdx.y; i < 32; i += 8)
        tile[i][threadIdx.x] = tgt[((size_t)b*T_ + t0 + i)*C_ + c0 + threadIdx.x];
    __syncthreads();
    for (int i = threadIdx.y; i < 32; i += 8)
        out[((size_t)b*C_ + c0 + i)*T_ + t0 + threadIdx.x] = tile[threadIdx.x][i];
}

// ---------------- launch ----------------
extern "C" void kernel_launch(void* const* d_in, const int* in_sizes, int n_in,
                              void* d_out, int out_size){
    const float* mainx      = (const float*)d_in[0];
    const float* others[2]  = {(const float*)d_in[1], (const float*)d_in[2]};
    const float* pe         = (const float*)d_in[3];
    const float* mq         = (const float*)d_in[4];
    const float* s_w1       = (const float*)d_in[5];
    const float* s_b1       = (const float*)d_in[6];
    const float* s_w2       = (const float*)d_in[7];
    const float* s_b2       = (const float*)d_in[8];
    const float* sa_in_w    = (const float*)d_in[9];
    const float* sa_in_b    = (const float*)d_in[10];
    const float* sa_out_w   = (const float*)d_in[11];
    const float* sa_out_b   = (const float*)d_in[12];
    const float* ca_in_w    = (const float*)d_in[13];
    const float* ca_in_b    = (const float*)d_in[14];
    const float* ca_out_w   = (const float*)d_in[15];
    const float* ca_out_b   = (const float*)d_in[16];
    const float* ff1_w      = (const float*)d_in[17];
    const float* ff1_b      = (const float*)d_in[18];
    const float* ff2_w      = (const float*)d_in[19];
    const float* ff2_b      = (const float*)d_in[20];
    const float* ln_w       = (const float*)d_in[21];
    const float* ln_b       = (const float*)d_in[22];
    const float* block_rand = (const float*)d_in[23];
    const float* around_rand= (const float*)d_in[24];
    float* out = (float*)d_out;

    float *pf0, *hid0, *mainxT, *coords, *score, *tgt, *tmp, *ffh, *memkv, *qb, *exsc;
    int *topidx, *top16;
    __half *qkv16, *pf16, *tgt16, *attn16, *memb16, *ffh16, *wt;
    cudaGetSymbolAddress((void**)&pf0,    g_pf);
    cudaGetSymbolAddress((void**)&hid0,   g_hid);
    cudaGetSymbolAddress((void**)&mainxT, g_mainxT);
    cudaGetSymbolAddress((void**)&coords, g_coords);
    cudaGetSymbolAddress((void**)&score,  g_score);
    cudaGetSymbolAddress((void**)&top16,  g_top16);
    cudaGetSymbolAddress((void**)&exsc,   g_exsc);
    cudaGetSymbolAddress((void**)&topidx, g_topidx);
    cudaGetSymbolAddress((void**)&tgt,    g_tgt);
    cudaGetSymbolAddress((void**)&tmp,    g_tmp);
    cudaGetSymbolAddress((void**)&ffh,    g_ffh);
    cudaGetSymbolAddress((void**)&memkv,  g_memkv);
    cudaGetSymbolAddress((void**)&qb,     g_q);
    cudaGetSymbolAddress((void**)&qkv16,  g_qkv16);
    cudaGetSymbolAddress((void**)&pf16,   g_pf16);
    cudaGetSymbolAddress((void**)&tgt16,  g_tgt16);
    cudaGetSymbolAddress((void**)&attn16, g_attn16);
    cudaGetSymbolAddress((void**)&memb16, g_memb16);
    cudaGetSymbolAddress((void**)&ffh16,  g_ffh16);
    cudaGetSymbolAddress((void**)&wt,     g_wt);

    size_t o = 0;
    __half* wtS = wt + o; o += (size_t)768*768;
    __half *wtSAin[L_], *wtSAout[L_], *wtCAin[L_], *wtCAout[L_], *wtFF1[L_], *wtFF2[L_];
    for (int l = 0; l < L_; l++){
        wtSAin[l]  = wt + o; o += (size_t)2304*768;
        wtSAout[l] = wt + o; o += (size_t)768*768;
        wtCAin[l]  = wt + o; o += (size_t)2304*768;
        wtCAout[l] = wt + o; o += (size_t)768*768;
        wtFF1[l]   = wt + o; o += (size_t)3072*768;
        wtFF2[l]   = wt + o; o += (size_t)768*3072;
    }

    float* pf1  = ffh;
    float* hid1 = ffh + (size_t)B_*NPTS*C_;
    float* memkvL[2] = { memkv, memkv + (size_t)B_*10*2*C_ };

    cudaFuncSetAttribute(flash_attn_kernel, cudaFuncAttributeMaxDynamicSharedMemorySize, FA_SMEM_B);

    static cudaStream_t s_m[2] = {nullptr, nullptr};
    static cudaEvent_t  ev_start = nullptr, ev_m[2] = {nullptr, nullptr};
    static cudaEvent_t  ev_w = nullptr, ev_k[2] = {nullptr, nullptr};
    if (s_m[0] == nullptr){
        cudaStreamCreateWithFlags(&s_m[0], cudaStreamNonBlocking);
        cudaStreamCreateWithFlags(&s_m[1], cudaStreamNonBlocking);
        cudaEventCreateWithFlags(&ev_start, cudaEventDisableTiming);
        cudaEventCreateWithFlags(&ev_m[0], cudaEventDisableTiming);
        cudaEventCreateWithFlags(&ev_m[1], cudaEventDisableTiming);
        cudaEventCreateWithFlags(&ev_w, cudaEventDisableTiming);
        cudaEventCreateWithFlags(&ev_k[0], cudaEventDisableTiming);
        cudaEventCreateWithFlags(&ev_k[1], cudaEventDisableTiming);
    }

    // pre-fork work side streams depend on: score weight + mainxT
    transpose_w(s_w1, wtS, 768, 768, 0);
    {
        dim3 g(C_/32, T_/32, B_); dim3 bl(32, 8);
        transpose_in_kernel<<<g, bl>>>(mainx, mainxT);
    }
    cudaEventRecord(ev_start, 0);

    // ---- fork: modality pipelines ----
    float*  pfs[2]   = {pf0, pf1};
    float*  hids[2]  = {hid0, hid1};
    for (int i = 0; i < 2; i++){
        cudaStream_t st = s_m[i];
        cudaStreamWaitEvent(st, ev_start, 0);
        float*  pf_i   = pfs[i];
        __half* pf16_i = pf16 + (size_t)i*B_*NPTS*C_;
        float*  hid_i  = hids[i];
        float* coords_i = coords + (size_t)i*B_*NPTS*2;
        float* score_i  = score  + (size_t)i*B_*NPTS;
        int*   top16_i  = top16  + i*B_*NCAND;
        float* exsc_i   = exsc   + i*B_*NCAND;
        int*   topidx_i = topidx + i*B_*TOPK_;
        {
            dim3 g(C_/32, T_/32, B_); dim3 bl(32, 8);
            transpose_in_kernel<<<g, bl, 0, st>>>(others[i], hid_i);
        }
        sample_kernel<<<B_*NPTS/16, 256, 0, st>>>(hid_i, block_rand + (size_t)i*B_*32*32*2*2,
                                                  pf_i, pf16_i, coords_i, score_i);
        h_gemm<2>(pf16_i, wtS, s_b1, nullptr, nullptr, s_w2, score_i,
                  B_*NPTS, C_, C_, C_, C_, 0, st);
        topk_kernel<<<B_, 256, 0, st>>>(score_i, top16_i, NCAND);
        rescore_kernel<<<B_*NCAND, 256, 0, st>>>(pf_i, s_w1, s_b1, s_w2, top16_i, exsc_i);
        final_top5_kernel<<<B_, 32, 0, st>>>(exsc_i, top16_i, topidx_i);
        soft_align_kernel<<<B_*TOPK_, 256, 0, st>>>(mainxT, pe,
                                                    around_rand + (size_t)i*B_*AROUND_*TOPK_*2,
                                                    mq + (size_t)(i+1)*C_,
                                                    pf_i, coords_i, topidx_i, memb16, i*TOPK_);
        cudaEventRecord(ev_m[i], st);
    }

    // ---- decoder weight transposes (ONE batched launch) + prefix on main stream ----
    {
        WTJobs jobs;
        for (int l = 0; l < L_; l++){
            jobs.src[l*6+0] = sa_in_w  + (size_t)l*C_*3*C_; jobs.dst[l*6+0] = wtSAin[l];  jobs.K[l*6+0] = 768;  jobs.N[l*6+0] = 2304;
            jobs.src[l*6+1] = sa_out_w + (size_t)l*C_*C_;   jobs.dst[l*6+1] = wtSAout[l]; jobs.K[l*6+1] = 768;  jobs.N[l*6+1] = 768;
            jobs.src[l*6+2] = ca_in_w  + (size_t)l*C_*3*C_; jobs.dst[l*6+2] = wtCAin[l];  jobs.K[l*6+2] = 768;  jobs.N[l*6+2] = 2304;
            jobs.src[l*6+3] = ca_out_w + (size_t)l*C_*C_;   jobs.dst[l*6+3] = wtCAout[l]; jobs.K[l*6+3] = 768;  jobs.N[l*6+3] = 768;
            jobs.src[l*6+4] = ff1_w    + (size_t)l*C_*FF_;  jobs.dst[l*6+4] = wtFF1[l];   jobs.K[l*6+4] = 768;  jobs.N[l*6+4] = 3072;
            jobs.src[l*6+5] = ff2_w    + (size_t)l*FF_*C_;  jobs.dst[l*6+5] = wtFF2[l];   jobs.K[l*6+5] = 3072; jobs.N[l*6+5] = 768;
        }
        dim3 g(2304, 12); dim3 bl(32, 8);
        transpose_w_all_kernel<<<g, bl>>>(jobs);
        cudaEventRecord(ev_w, 0);
    }
    tgt_init_kernel<<<(int)(((size_t)B_*T_*C_ + 255)/256), 256>>>(mainxT, mq, pe, tgt, tgt16);

    // memkv GEMMs on side streams (need memb16 from BOTH streams + weights)
    for (int l = 0; l < L_; l++){
        cudaStream_t st = s_m[l];
        cudaStreamWaitEvent(st, ev_m[0], 0);
        cudaStreamWaitEvent(st, ev_m[1], 0);
        cudaStreamWaitEvent(st, ev_w, 0);
        h_gemm<0>(memb16, wtCAin[l] + (size_t)768*C_, ca_in_b + (size_t)l*3*C_ + C_, memkvL[l],
                  nullptr, nullptr, nullptr, B_*10, 2*C_, C_, C_, C_, 2*C_, st);
        cudaEventRecord(ev_k[l], st);
    }

    // layer 0 SA block + CA-q (no memb dependency)
    h_gemm<3>(tgt16, wtSAin[0], sa_in_b, nullptr, qkv16, nullptr, nullptr,
              B_*T_, 3*C_, C_, C_, C_, 3*C_, 0);
    { dim3 g(T_/128, B_*NHEAD_); flash_attn_kernel<<<g, 256, FA_SMEM_B>>>(qkv16, attn16); }
    h_gemm<0>(attn16, wtSAout[0], sa_out_b, tmp, nullptr, nullptr, nullptr,
              B_*T_, C_, C_, C_, C_, C_, 0);
    add_ln_kernel<<<B_*T_/8, 256>>>(tgt, tgt16, tmp, ln_w, ln_b);
    h_gemm<0>(tgt16, wtCAin[0], ca_in_b, qb, nullptr, nullptr, nullptr,
              B_*T_, C_, C_, C_, C_, C_, 0);

    for (int l = 0; l < L_; l++){
        if (l > 0){
            h_gemm<3>(tgt16, wtSAin[l], sa_in_b + (size_t)l*3*C_, nullptr, qkv16, nullptr, nullptr,
                      B_*T_, 3*C_, C_, C_, C_, 3*C_, 0);
            { dim3 g(T_/128, B_*NHEAD_); flash_attn_kernel<<<g, 256, FA_SMEM_B>>>(qkv16, attn16); }
            h_gemm<0>(attn16, wtSAout[l], sa_out_b + (size_t)l*C_, tmp, nullptr, nullptr, nullptr,
                      B_*T_, C_, C_, C_, C_, C_, 0);
            add_ln_kernel<<<B_*T_/8, 256>>>(tgt, tgt16, tmp, ln_w + (size_t)(l*3+0)*C_, ln_b + (size_t)(l*3+0)*C_);
            h_gemm<0>(tgt16, wtCAin[l], ca_in_b + (size_t)l*3*C_, qb, nullptr, nullptr, nullptr,
                      B_*T_, C_, C_, C_, C_, C_, 0);
        }
        cudaStreamWaitEvent(0, ev_k[l], 0);
        { dim3 g(T_/256, B_*NHEAD_); ca_attn_kernel<<<g, 256>>>(qb, memkvL[l], attn16); }
        h_gemm<0>(attn16, wtCAout[l], ca_out_b + (size_t)l*C_, tmp, nullptr, nullptr, nullptr,
                  B_*T_, C_, C_, C_, C_, C_, 0);
        add_ln_kernel<<<B_*T_/8, 256>>>(tgt, tgt16, tmp, ln_w + (size_t)(l*3+1)*C_, ln_b + (size_t)(l*3+1)*C_);

        h_gemm<1>(tgt16, wtFF1[l], ff1_b + (size_t)l*FF_, nullptr, ffh16, nullptr, nullptr,
                  B_*T_, FF_, C_, C_, C_, FF_, 0);
        h_gemm<0>(ffh16, wtFF2[l], ff2_b + (size_t)l*C_, tmp, nullptr, nullptr, nullptr,
                  B_*T_, C_, FF_, FF_, FF_, C_, 0);
        add_ln_kernel<<<B_*T_/8, 256>>>(tgt, tgt16, tmp, ln_w + (size_t)(l*3+2)*C_, ln_b + (size_t)(l*3+2)*C_);
    }

    {
        dim3 g(C_/32, T_/32, B_); dim3 bl(32, 8);
        transpose_out_kernel<<<g, bl>>>(tgt, out);
    }
}